// round 6
// baseline (speedup 1.0000x reference)
#include <cuda_runtime.h>
#include <math.h>

#define B_   256
#define T_   256
#define IN_  256
#define HID_ 512
#define OUT_ 256
#define NBLK 128

typedef unsigned long long u64;

// ---------- packed f32x2 FMA (K packed into the two halves) ----------
__device__ __forceinline__ void f2fma(u64 &d, u64 a, u64 b) {
    asm("fma.rn.f32x2 %0, %1, %2, %0;" : "+l"(d) : "l"(a), "l"(b));
}
__device__ __forceinline__ float f2sum(u64 v) {
    unsigned lo, hi;
    asm("mov.b64 {%0, %1}, %2;" : "=r"(lo), "=r"(hi) : "l"(v));
    return __uint_as_float(lo) + __uint_as_float(hi);
}
__device__ __forceinline__ float sigmoidf_(float x) { return 1.0f / (1.0f + expf(-x)); }

// ---------- device scratch ----------
__device__ float g_pre[(size_t)B_ * T_ * 3 * HID_];   // [m][z|r|h], bias folded
__device__ float g_h[2][B_ * HID_];
__device__ float g_rh[B_ * HID_];
__device__ unsigned g_flags[NBLK * 32];               // 128B-spaced flags, zero-init, monotonic

// =====================================================================================
// Kernel 1: PRE = [x|c] @ [W_x;W_c](gate) + bias.  M=65536, N=1536, K=512.
// Tile 64x128, 512 threads, thread tile 8 rows x 2 cols (f32x2 over K).
// A-loads are warp-broadcast; B stored [col][k] with XOR k-group swizzle.
// =====================================================================================
__global__ __launch_bounds__(512) void pre_gemm_kernel(
    const float* __restrict__ x, const float* __restrict__ c,
    const float* __restrict__ wxz, const float* __restrict__ wcz, const float* __restrict__ bz,
    const float* __restrict__ wxr, const float* __restrict__ wcr, const float* __restrict__ br,
    const float* __restrict__ wxh, const float* __restrict__ wch, const float* __restrict__ bh)
{
    __shared__ __align__(16) float As[64][36];
    __shared__ __align__(16) float Bs[128 * 36];     // [col][k], k-groups XOR-swizzled

    const int tid = threadIdx.x;
    const int m0 = blockIdx.y * 64;
    const int n0 = blockIdx.x * 128;
    const int gate = n0 >> 9;
    const int nl0 = n0 & (HID_ - 1);

    const float* Wx   = (gate == 0) ? wxz : (gate == 1) ? wxr : wxh;
    const float* Wc   = (gate == 0) ? wcz : (gate == 1) ? wcr : wch;
    const float* bias = (gate == 0) ? bz  : (gate == 1) ? br  : bh;

    const int ttr = tid >> 6;        // 0..7  -> rows ttr*8 .. +7
    const int ttc = tid & 63;        // cols ttc, ttc+64

    const int arow = tid >> 3;       // 0..63
    const int akq  = tid & 7;        // k = akq*4
    const int bkr  = tid >> 4;       // 0..31 (k row)
    const int bnq  = tid & 15;       // cols bnq*8..+7

    u64 acc[8][2];
    #pragma unroll
    for (int i = 0; i < 8; i++) { acc[i][0] = 0ull; acc[i][1] = 0ull; }

    // prologue: chunk 0
    float4 av  = *(const float4*)&x[(size_t)(m0 + arow) * IN_ + akq * 4];
    float4 bv0 = *(const float4*)&Wx[(size_t)bkr * HID_ + nl0 + bnq * 8];
    float4 bv1 = *(const float4*)&Wx[(size_t)bkr * HID_ + nl0 + bnq * 8 + 4];

    const int bg = bkr >> 2;                  // k-group 0..7
    const int bw = bkr & 3;
    const int bsw = ((bg ^ (bnq & 7)) << 2) + bw;

    for (int k0 = 0; k0 < 512; k0 += 32) {
        __syncthreads();
        *(float4*)&As[arow][akq * 4] = av;
        {
            float tmp[8] = {bv0.x, bv0.y, bv0.z, bv0.w, bv1.x, bv1.y, bv1.z, bv1.w};
            #pragma unroll
            for (int c2 = 0; c2 < 8; c2++)
                Bs[(bnq * 8 + c2) * 36 + bsw] = tmp[c2];
        }
        __syncthreads();

        if (k0 + 32 < 512) {
            const int kn = k0 + 32;
            const float* Asrc = (kn < 256) ? x  : c;
            const float* Bsrc = (kn < 256) ? Wx : Wc;
            const int kb = kn & 255;
            av  = *(const float4*)&Asrc[(size_t)(m0 + arow) * IN_ + kb + akq * 4];
            bv0 = *(const float4*)&Bsrc[(size_t)(kb + bkr) * HID_ + nl0 + bnq * 8];
            bv1 = *(const float4*)&Bsrc[(size_t)(kb + bkr) * HID_ + nl0 + bnq * 8 + 4];
        }

        #pragma unroll
        for (int q = 0; q < 8; q++) {
            ulonglong2 b0 = *(const ulonglong2*)&Bs[ttc * 36 + ((q ^ ((ttc >> 3) & 7)) << 2)];
            ulonglong2 b1 = *(const ulonglong2*)&Bs[(ttc + 64) * 36 + ((q ^ (((ttc + 64) >> 3) & 7)) << 2)];
            #pragma unroll
            for (int i = 0; i < 8; i++) {
                ulonglong2 a = *(const ulonglong2*)&As[ttr * 8 + i][q * 4];
                f2fma(acc[i][0], a.x, b0.x); f2fma(acc[i][0], a.y, b0.y);
                f2fma(acc[i][1], a.x, b1.x); f2fma(acc[i][1], a.y, b1.y);
            }
        }
    }

    #pragma unroll
    for (int i = 0; i < 8; i++) {
        const int m = m0 + ttr * 8 + i;
        #pragma unroll
        for (int p = 0; p < 2; p++) {
            const int cl = ttc + 64 * p;
            g_pre[(size_t)m * 1536 + n0 + cl] = f2sum(acc[i][p]) + bias[nl0 + cl];
        }
    }
}

// =====================================================================================
// Flag-based grid barrier: one 128B-spaced flag per block, release/acquire, no atomics.
// =====================================================================================
__device__ __forceinline__ void gbar(unsigned want)
{
    __syncthreads();
    if (threadIdx.x == 0) {
        asm volatile("st.release.gpu.global.u32 [%0], %1;"
                     :: "l"(&g_flags[blockIdx.x * 32]), "r"(want) : "memory");
    }
    if (threadIdx.x < NBLK) {
        unsigned v;
        do {
            asm volatile("ld.acquire.gpu.global.u32 %0, [%1];"
                         : "=r"(v) : "l"(&g_flags[threadIdx.x * 32]) : "memory");
        } while ((int)(v - want) < 0);
    }
    __syncthreads();
}

// =====================================================================================
// Persistent scan kernel: 128 blocks = 8 m-tiles (32 rows) x 16 col-tiles (32 cols),
// 512 threads (4 warps/SMSP). Thread tile: 2 rows x 1 col x (2 gates in phase A).
// Weights in smem for all 256 steps; staged h/rh chunks software-pipelined.
// =====================================================================================
#define SC_WZR_F (64 * 516)
#define SC_WH_F  (32 * 516)
#define SC_AS_F  (32 * 132)
#define SCAN_SMEM ((SC_WZR_F + SC_WH_F + SC_AS_F) * sizeof(float))

__global__ __launch_bounds__(512, 1) void scan_kernel(
    const float* __restrict__ w_hz, const float* __restrict__ w_hr,
    const float* __restrict__ w_hh, float* __restrict__ hs_out)
{
    extern __shared__ float sm[];
    float* wZR = sm;                         // [64][516]: cols 0-31 Whz slice, 32-63 Whr slice
    float* wH  = sm + SC_WZR_F;              // [32][516]: Whh slice
    float* As  = sm + SC_WZR_F + SC_WH_F;    // [32][132] staging

    const int tid = threadIdx.x;
    const int bid = blockIdx.x;
    const int bm = bid >> 4;                 // 0..7
    const int bn = bid & 15;                 // 0..15
    const int m0 = bm * 32;
    const int j0 = bn * 32;

    // ---- one-time weight load (transposed to [col][k]) ----
    for (int idx = tid; idx < 512 * 8; idx += 512) {
        const int k  = idx >> 3;
        const int c4 = (idx & 7) * 4;
        float4 vz = *(const float4*)&w_hz[(size_t)k * HID_ + j0 + c4];
        float4 vr = *(const float4*)&w_hr[(size_t)k * HID_ + j0 + c4];
        float4 vh = *(const float4*)&w_hh[(size_t)k * HID_ + j0 + c4];
        wZR[(c4 + 0) * 516 + k] = vz.x; wZR[(c4 + 1) * 516 + k] = vz.y;
        wZR[(c4 + 2) * 516 + k] = vz.z; wZR[(c4 + 3) * 516 + k] = vz.w;
        wZR[(32 + c4 + 0) * 516 + k] = vr.x; wZR[(32 + c4 + 1) * 516 + k] = vr.y;
        wZR[(32 + c4 + 2) * 516 + k] = vr.z; wZR[(32 + c4 + 3) * 516 + k] = vr.w;
        wH[(c4 + 0) * 516 + k] = vh.x; wH[(c4 + 1) * 516 + k] = vh.y;
        wH[(c4 + 2) * 516 + k] = vh.z; wH[(c4 + 3) * 516 + k] = vh.w;
    }

    __shared__ unsigned s_base;
    if (tid == 0) s_base = *(volatile unsigned*)&g_flags[bid * 32];
    __syncthreads();
    const unsigned base = s_base;
    unsigned nbar = 0;

    // compute mapping: warp = 4 rows x 8 cols; thread rows {ttr, ttr+16}
    const int wid  = tid >> 5, lane = tid & 31;
    const int ttr  = (wid >> 2) * 4 + (lane >> 3);   // 0..15
    const int col  = (wid & 3) * 8 + (lane & 7);     // 0..31
    const int j    = j0 + col;

    // staging mapping: 32 rows x 32 float4-slots; xor'd slot for conflict-free STS
    const int srow = tid >> 4;                       // 0..31
    const int sslt = (tid & 15) ^ (srow & 7);        // 0..15
    const int sk0  = sslt * 4;                       // k byte-slot A
    const int sk1  = sk0 + 64;                       // k byte-slot B

    for (int t = 0; t < T_; t++) {
        const float* __restrict__ hprev = g_h[t & 1];
        float* __restrict__ hnext = g_h[(t + 1) & 1];

        // ---- epilogue prefetch ----
        float pz[2], pr[2], ph[2], hv[2];
        #pragma unroll
        for (int u = 0; u < 2; u++) {
            const int m = m0 + ttr + 16 * u;
            const size_t prow = ((size_t)m * T_ + t) * 1536;
            pz[u] = __ldg(&g_pre[prow + j]);
            pr[u] = __ldg(&g_pre[prow + 512 + j]);
            ph[u] = __ldg(&g_pre[prow + 1024 + j]);
            hv[u] = __ldcg(&hprev[m * HID_ + j]);
        }

        // ================= phase A: Sz,Sr = h @ [Whz|Whr] slice =================
        u64 az[2], ar[2];
        az[0] = az[1] = ar[0] = ar[1] = 0ull;

        float4 r4a = __ldcg((const float4*)&hprev[(size_t)(m0 + srow) * HID_ + sk0]);
        float4 r4b = __ldcg((const float4*)&hprev[(size_t)(m0 + srow) * HID_ + sk1]);

        for (int ch = 0; ch < 4; ch++) {
            const int k0 = ch * 128;
            __syncthreads();
            *(float4*)&As[srow * 132 + sk0] = r4a;
            *(float4*)&As[srow * 132 + sk1] = r4b;
            __syncthreads();
            if (ch < 3) {
                r4a = __ldcg((const float4*)&hprev[(size_t)(m0 + srow) * HID_ + k0 + 128 + sk0]);
                r4b = __ldcg((const float4*)&hprev[(size_t)(m0 + srow) * HID_ + k0 + 128 + sk1]);
            }
            #pragma unroll 8
            for (int kg = 0; kg < 32; kg++) {
                ulonglong2 a0 = *(const ulonglong2*)&As[ttr * 132 + kg * 4];
                ulonglong2 a1 = *(const ulonglong2*)&As[(ttr + 16) * 132 + kg * 4];
                ulonglong2 bz2 = *(const ulonglong2*)&wZR[col * 516 + k0 + kg * 4];
                ulonglong2 br2 = *(const ulonglong2*)&wZR[(col + 32) * 516 + k0 + kg * 4];
                f2fma(az[0], a0.x, bz2.x); f2fma(az[0], a0.y, bz2.y);
                f2fma(az[1], a1.x, bz2.x); f2fma(az[1], a1.y, bz2.y);
                f2fma(ar[0], a0.x, br2.x); f2fma(ar[0], a0.y, br2.y);
                f2fma(ar[1], a1.x, br2.x); f2fma(ar[1], a1.y, br2.y);
            }
        }

        float zloc[2];
        #pragma unroll
        for (int u = 0; u < 2; u++) {
            const int m = m0 + ttr + 16 * u;
            zloc[u] = sigmoidf_(pz[u] + f2sum(az[u]));
            const float r = sigmoidf_(pr[u] + f2sum(ar[u]));
            g_rh[m * HID_ + j] = r * hv[u];
        }
        gbar(base + (++nbar));

        // ================= phase B: Sh = rh @ Whh slice =================
        u64 ah[2];
        ah[0] = ah[1] = 0ull;

        r4a = __ldcg((const float4*)&g_rh[(size_t)(m0 + srow) * HID_ + sk0]);
        r4b = __ldcg((const float4*)&g_rh[(size_t)(m0 + srow) * HID_ + sk1]);

        for (int ch = 0; ch < 4; ch++) {
            const int k0 = ch * 128;
            __syncthreads();
            *(float4*)&As[srow * 132 + sk0] = r4a;
            *(float4*)&As[srow * 132 + sk1] = r4b;
            __syncthreads();
            if (ch < 3) {
                r4a = __ldcg((const float4*)&g_rh[(size_t)(m0 + srow) * HID_ + k0 + 128 + sk0]);
                r4b = __ldcg((const float4*)&g_rh[(size_t)(m0 + srow) * HID_ + k0 + 128 + sk1]);
            }
            #pragma unroll 8
            for (int kg = 0; kg < 32; kg++) {
                ulonglong2 a0 = *(const ulonglong2*)&As[ttr * 132 + kg * 4];
                ulonglong2 a1 = *(const ulonglong2*)&As[(ttr + 16) * 132 + kg * 4];
                ulonglong2 bh2 = *(const ulonglong2*)&wH[col * 516 + k0 + kg * 4];
                f2fma(ah[0], a0.x, bh2.x); f2fma(ah[0], a0.y, bh2.y);
                f2fma(ah[1], a1.x, bh2.x); f2fma(ah[1], a1.y, bh2.y);
            }
        }

        #pragma unroll
        for (int u = 0; u < 2; u++) {
            const int m = m0 + ttr + 16 * u;
            const float ht = tanhf(ph[u] + f2sum(ah[u]));
            const float hn = fmaf(zloc[u], ht - hv[u], hv[u]);
            hnext[m * HID_ + j] = hn;
            hs_out[((size_t)m * T_ + t) * HID_ + j] = hn;
        }
        if (t < T_ - 1) gbar(base + (++nbar));
    }
}

// =====================================================================================
// Kernel 4: out = relu(h_last @ w_out + b_out).  M=256, N=256, K=512.
// =====================================================================================
__global__ __launch_bounds__(256) void out_kernel(
    const float* __restrict__ w_out, const float* __restrict__ b_out,
    float* __restrict__ out)
{
    __shared__ __align__(16) float As[32][36];
    __shared__ __align__(16) float Bs[32][36];

    const float* __restrict__ hlast = g_h[0];   // T even -> final state in buffer 0

    const int tid = threadIdx.x;
    const int m0 = blockIdx.y * 32;
    const int n0 = blockIdx.x * 32;

    const int ttr = tid >> 4;
    const int ttc = tid & 15;
    const int arow = tid >> 3;
    const int akq  = tid & 7;
    const int bkr  = tid >> 3;
    const int bnq  = tid & 7;

    u64 acc[2][2];
    #pragma unroll
    for (int i = 0; i < 2; i++)
        #pragma unroll
        for (int p = 0; p < 2; p++) acc[i][p] = 0ull;

    for (int k0 = 0; k0 < HID_; k0 += 32) {
        float4 av = *(const float4*)&hlast[(size_t)(m0 + arow) * HID_ + k0 + akq * 4];
        float4 bv = *(const float4*)&w_out[(size_t)(k0 + bkr) * OUT_ + n0 + bnq * 4];

        __syncthreads();
        *(float4*)&As[arow][akq * 4] = av;
        Bs[bnq * 4 + 0][bkr] = bv.x; Bs[bnq * 4 + 1][bkr] = bv.y;
        Bs[bnq * 4 + 2][bkr] = bv.z; Bs[bnq * 4 + 3][bkr] = bv.w;
        __syncthreads();

        #pragma unroll
        for (int q = 0; q < 8; q++) {
            ulonglong2 a0 = *(const ulonglong2*)&As[ttr * 2 + 0][q * 4];
            ulonglong2 a1 = *(const ulonglong2*)&As[ttr * 2 + 1][q * 4];
            #pragma unroll
            for (int p = 0; p < 2; p++) {
                ulonglong2 bb = *(const ulonglong2*)&Bs[ttc + 16 * p][q * 4];
                f2fma(acc[0][p], a0.x, bb.x); f2fma(acc[0][p], a0.y, bb.y);
                f2fma(acc[1][p], a1.x, bb.x); f2fma(acc[1][p], a1.y, bb.y);
            }
        }
    }

    #pragma unroll
    for (int i = 0; i < 2; i++) {
        const int b = m0 + ttr * 2 + i;
        #pragma unroll
        for (int p = 0; p < 2; p++) {
            const int j = n0 + ttc + 16 * p;
            const float s = f2sum(acc[i][p]) + b_out[j];
            out[(size_t)b * OUT_ + j] = fmaxf(s, 0.0f);
        }
    }
}

// =====================================================================================
extern "C" void kernel_launch(void* const* d_in, const int* in_sizes, int n_in,
                              void* d_out, int out_size)
{
    const float* x     = (const float*)d_in[0];
    const float* c     = (const float*)d_in[1];
    const float* h0    = (const float*)d_in[2];
    const float* w_xr  = (const float*)d_in[3];
    const float* w_hr  = (const float*)d_in[4];
    const float* w_cr  = (const float*)d_in[5];
    const float* w_xz  = (const float*)d_in[6];
    const float* w_hz  = (const float*)d_in[7];
    const float* w_cz  = (const float*)d_in[8];
    const float* w_xh  = (const float*)d_in[9];
    const float* w_hh  = (const float*)d_in[10];
    const float* w_ch  = (const float*)d_in[11];
    const float* b_r   = (const float*)d_in[12];
    const float* b_z   = (const float*)d_in[13];
    const float* b_h   = (const float*)d_in[14];
    const float* w_out = (const float*)d_in[15];
    const float* b_out = (const float*)d_in[16];

    float* out = (float*)d_out;                 // [B, OUT] first
    float* hs  = out + (size_t)B_ * OUT_;       // then [B, T, HID]

    static int smem_set = 0;
    if (!smem_set) {
        cudaFuncSetAttribute(scan_kernel, cudaFuncAttributeMaxDynamicSharedMemorySize,
                             (int)SCAN_SMEM);
        smem_set = 1;
    }

    cudaMemcpyToSymbolAsync(g_h, h0, (size_t)B_ * HID_ * sizeof(float), 0,
                            cudaMemcpyDeviceToDevice, 0);

    pre_gemm_kernel<<<dim3(12, 1024), 512>>>(x, c,
                                             w_xz, w_cz, b_z,
                                             w_xr, w_cr, b_r,
                                             w_xh, w_ch, b_h);

    scan_kernel<<<NBLK, 512, SCAN_SMEM>>>(w_hz, w_hr, w_hh, hs);

    out_kernel<<<dim3(8, 8), 256>>>(w_out, b_out, out);
}

// round 8
// speedup vs baseline: 1.1702x; 1.1702x over previous
#include <cuda_runtime.h>
#include <math.h>

#define B_   256
#define T_   256
#define IN_  256
#define HID_ 512
#define OUT_ 256
#define NBLK 128

typedef unsigned long long u64;

// ---------- packed f32x2 FMA (K packed into the two halves) ----------
__device__ __forceinline__ void f2fma(u64 &d, u64 a, u64 b) {
    asm("fma.rn.f32x2 %0, %1, %2, %0;" : "+l"(d) : "l"(a), "l"(b));
}
__device__ __forceinline__ float f2sum(u64 v) {
    unsigned lo, hi;
    asm("mov.b64 {%0, %1}, %2;" : "=r"(lo), "=r"(hi) : "l"(v));
    return __uint_as_float(lo) + __uint_as_float(hi);
}
__device__ __forceinline__ float sigmoidf_(float x) { return 1.0f / (1.0f + expf(-x)); }

// ---------- device scratch ----------
__device__ float g_pre[(size_t)B_ * T_ * 3 * HID_];   // [m][z|r|h], bias folded
__device__ float g_h[2][B_ * HID_];
__device__ float g_rh[B_ * HID_];
__device__ unsigned g_flags[NBLK * 32];               // 128B-spaced flags, zero-init, monotonic

// =====================================================================================
// Kernel 1: PRE = [x|c] @ [W_x;W_c](gate) + bias.  M=65536, N=1536, K=512.
// Tile 64x64, 256 threads, 4x4 f32x2 thread tile, XOR-swizzled B.
// DOUBLE-BUFFERED smem: one sync per chunk, global prefetch two chunks deep.
// =====================================================================================
__global__ __launch_bounds__(256) void pre_gemm_kernel(
    const float* __restrict__ x, const float* __restrict__ c,
    const float* __restrict__ wxz, const float* __restrict__ wcz, const float* __restrict__ bz,
    const float* __restrict__ wxr, const float* __restrict__ wcr, const float* __restrict__ br,
    const float* __restrict__ wxh, const float* __restrict__ wch, const float* __restrict__ bh)
{
    __shared__ __align__(16) float As[2][64][36];
    __shared__ __align__(16) float Bs[2][64 * 36];   // [col][k], k-groups XOR-swizzled

    const int tid = threadIdx.x;
    const int m0 = blockIdx.y * 64;
    const int n0 = blockIdx.x * 64;
    const int gate = n0 >> 9;
    const int nl0 = n0 & (HID_ - 1);

    const float* Wx   = (gate == 0) ? wxz : (gate == 1) ? wxr : wxh;
    const float* Wc   = (gate == 0) ? wcz : (gate == 1) ? wcr : wch;
    const float* bias = (gate == 0) ? bz  : (gate == 1) ? br  : bh;

    const int ttr = tid >> 4;        // 0..15
    const int ttc = tid & 15;        // 0..15
    const int arow = tid >> 2;       // 0..63
    const int akq  = tid & 3;        // 0..3
    const int bkr  = tid >> 3;       // 0..31 (k row within chunk)
    const int bnq  = tid & 7;        // 0..7  (8-col group)

    const int bg = bkr >> 2;
    const int bw = bkr & 3;
    const int bsw = ((bg ^ bnq) << 2) + bw;   // swizzled k-offset within B row

    u64 acc[4][4];
    #pragma unroll
    for (int i = 0; i < 4; i++)
        #pragma unroll
        for (int p = 0; p < 4; p++) acc[i][p] = 0ull;

    // ---- prologue: load chunk 0, store to buf0, prefetch chunk 1 ----
    float4 av0 = *(const float4*)&x[(size_t)(m0 + arow) * IN_ + akq * 4];
    float4 av1 = *(const float4*)&x[(size_t)(m0 + arow) * IN_ + 16 + akq * 4];
    float4 bv0 = *(const float4*)&Wx[(size_t)bkr * HID_ + nl0 + bnq * 8];
    float4 bv1 = *(const float4*)&Wx[(size_t)bkr * HID_ + nl0 + bnq * 8 + 4];

    *(float4*)&As[0][arow][akq * 4]      = av0;
    *(float4*)&As[0][arow][16 + akq * 4] = av1;
    {
        float tmp[8] = {bv0.x, bv0.y, bv0.z, bv0.w, bv1.x, bv1.y, bv1.z, bv1.w};
        #pragma unroll
        for (int c2 = 0; c2 < 8; c2++)
            Bs[0][(bnq * 8 + c2) * 36 + bsw] = tmp[c2];
    }
    av0 = *(const float4*)&x[(size_t)(m0 + arow) * IN_ + 32 + akq * 4];
    av1 = *(const float4*)&x[(size_t)(m0 + arow) * IN_ + 48 + akq * 4];
    bv0 = *(const float4*)&Wx[(size_t)(32 + bkr) * HID_ + nl0 + bnq * 8];
    bv1 = *(const float4*)&Wx[(size_t)(32 + bkr) * HID_ + nl0 + bnq * 8 + 4];
    __syncthreads();

    for (int ch = 0; ch < 16; ch++) {
        const int buf = ch & 1;

        // compute on current buffer
        #pragma unroll
        for (int q = 0; q < 8; q++) {
            ulonglong2 a[4];
            #pragma unroll
            for (int i = 0; i < 4; i++)
                a[i] = *(const ulonglong2*)&As[buf][ttr * 4 + i][q * 4];
            #pragma unroll
            for (int p = 0; p < 4; p++) {
                const int colp = ttc + 16 * p;
                ulonglong2 b = *(const ulonglong2*)&Bs[buf][colp * 36 + ((q ^ (colp >> 3)) << 2)];
                #pragma unroll
                for (int i = 0; i < 4; i++) {
                    f2fma(acc[i][p], a[i].x, b.x);
                    f2fma(acc[i][p], a[i].y, b.y);
                }
            }
        }

        if (ch < 15) {
            const int nb = buf ^ 1;
            *(float4*)&As[nb][arow][akq * 4]      = av0;
            *(float4*)&As[nb][arow][16 + akq * 4] = av1;
            {
                float tmp[8] = {bv0.x, bv0.y, bv0.z, bv0.w, bv1.x, bv1.y, bv1.z, bv1.w};
                #pragma unroll
                for (int c2 = 0; c2 < 8; c2++)
                    Bs[nb][(bnq * 8 + c2) * 36 + bsw] = tmp[c2];
            }
            if (ch < 14) {
                const int kn = (ch + 2) * 32;
                const float* Asrc = (kn < 256) ? x  : c;
                const float* Bsrc = (kn < 256) ? Wx : Wc;
                const int kb = kn & 255;
                av0 = *(const float4*)&Asrc[(size_t)(m0 + arow) * IN_ + kb + akq * 4];
                av1 = *(const float4*)&Asrc[(size_t)(m0 + arow) * IN_ + kb + 16 + akq * 4];
                bv0 = *(const float4*)&Bsrc[(size_t)(kb + bkr) * HID_ + nl0 + bnq * 8];
                bv1 = *(const float4*)&Bsrc[(size_t)(kb + bkr) * HID_ + nl0 + bnq * 8 + 4];
            }
            __syncthreads();
        }
    }

    #pragma unroll
    for (int i = 0; i < 4; i++) {
        const int m = m0 + ttr * 4 + i;
        #pragma unroll
        for (int p = 0; p < 4; p++) {
            const int cl = ttc + 16 * p;
            g_pre[(size_t)m * 1536 + n0 + cl] = f2sum(acc[i][p]) + bias[nl0 + cl];
        }
    }
}

// =====================================================================================
// Flag-based grid barrier: one 128B-spaced flag per block, release/acquire, no atomics.
// =====================================================================================
__device__ __forceinline__ void gbar(unsigned want)
{
    __syncthreads();
    if (threadIdx.x == 0) {
        asm volatile("st.release.gpu.global.u32 [%0], %1;"
                     :: "l"(&g_flags[blockIdx.x * 32]), "r"(want) : "memory");
    }
    if (threadIdx.x < NBLK) {
        unsigned v;
        do {
            asm volatile("ld.acquire.gpu.global.u32 %0, [%1];"
                         : "=r"(v) : "l"(&g_flags[threadIdx.x * 32]) : "memory");
        } while ((int)(v - want) < 0);
    }
    __syncthreads();
}

// =====================================================================================
// Persistent scan kernel: 128 blocks = 8 m-tiles (32 rows) x 16 col-tiles (32 cols),
// 256 threads. Thread tile: 4 rows x 1 col x (2 gates in phase A).
// Weights in smem all 256 steps; staging DOUBLE-BUFFERED in 64k sub-chunks.
// =====================================================================================
#define SC_WZR_F (64 * 516)
#define SC_WH_F  (32 * 516)
#define SC_AS_F  (2 * 32 * 68)
#define SCAN_SMEM ((SC_WZR_F + SC_WH_F + SC_AS_F) * sizeof(float))

__global__ __launch_bounds__(256, 1) void scan_kernel(
    const float* __restrict__ w_hz, const float* __restrict__ w_hr,
    const float* __restrict__ w_hh, float* __restrict__ hs_out)
{
    extern __shared__ float sm[];
    float* wZR = sm;                         // [64][516]: cols 0-31 Whz slice, 32-63 Whr slice
    float* wH  = sm + SC_WZR_F;              // [32][516]: Whh slice
    float* As  = sm + SC_WZR_F + SC_WH_F;    // [2][32][68] staging

    const int tid = threadIdx.x;
    const int bid = blockIdx.x;
    const int bm = bid >> 4;                 // 0..7
    const int bn = bid & 15;                 // 0..15
    const int m0 = bm * 32;
    const int j0 = bn * 32;

    // ---- one-time weight load (transposed to [col][k]) ----
    for (int idx = tid; idx < 512 * 8; idx += 256) {
        const int k  = idx >> 3;
        const int c4 = (idx & 7) * 4;
        float4 vz = *(const float4*)&w_hz[(size_t)k * HID_ + j0 + c4];
        float4 vr = *(const float4*)&w_hr[(size_t)k * HID_ + j0 + c4];
        float4 vh = *(const float4*)&w_hh[(size_t)k * HID_ + j0 + c4];
        wZR[(c4 + 0) * 516 + k] = vz.x; wZR[(c4 + 1) * 516 + k] = vz.y;
        wZR[(c4 + 2) * 516 + k] = vz.z; wZR[(c4 + 3) * 516 + k] = vz.w;
        wZR[(32 + c4 + 0) * 516 + k] = vr.x; wZR[(32 + c4 + 1) * 516 + k] = vr.y;
        wZR[(32 + c4 + 2) * 516 + k] = vr.z; wZR[(32 + c4 + 3) * 516 + k] = vr.w;
        wH[(c4 + 0) * 516 + k] = vh.x; wH[(c4 + 1) * 516 + k] = vh.y;
        wH[(c4 + 2) * 516 + k] = vh.z; wH[(c4 + 3) * 516 + k] = vh.w;
    }

    __shared__ unsigned s_base;
    if (tid == 0) s_base = *(volatile unsigned*)&g_flags[bid * 32];
    __syncthreads();
    const unsigned base = s_base;
    unsigned nbar = 0;

    // compute mapping: warp = 4 rows x 8 cols; block rows = ttr + 8u (u=0..3)
    const int wid  = tid >> 5, lane = tid & 31;
    const int ttr  = (wid >> 2) * 4 + (lane >> 3);   // 0..7
    const int col  = (wid & 3) * 8 + (lane & 7);     // 0..31
    const int j    = j0 + col;

    // staging: sub-chunk = 32 rows x 64 k; thread stores 2 float4 (xor'd slots)
    const int srow = tid >> 3;                       // 0..31
    const int sl   = (tid & 7) ^ (srow & 7);         // slot 0..7
    const int sk0  = sl * 4;
    const int sk1  = sk0 + 32;

    for (int t = 0; t < T_; t++) {
        const float* __restrict__ hprev = g_h[t & 1];
        float* __restrict__ hnext = g_h[(t + 1) & 1];

        // ---- epilogue prefetch ----
        float pz[4], pr[4], ph[4], hv[4];
        #pragma unroll
        for (int u = 0; u < 4; u++) {
            const int m = m0 + ttr + 8 * u;
            const size_t prow = ((size_t)m * T_ + t) * 1536;
            pz[u] = __ldg(&g_pre[prow + j]);
            pr[u] = __ldg(&g_pre[prow + 512 + j]);
            ph[u] = __ldg(&g_pre[prow + 1024 + j]);
            hv[u] = __ldcg(&hprev[m * HID_ + j]);
        }

        // ================= phase A: Sz,Sr = h @ [Whz|Whr] slice =================
        u64 az[4], ar[4];
        #pragma unroll
        for (int u = 0; u < 4; u++) { az[u] = 0ull; ar[u] = 0ull; }

        {
            const float* __restrict__ src = hprev;
            float4 r4a = __ldcg((const float4*)&src[(size_t)(m0 + srow) * HID_ + sk0]);
            float4 r4b = __ldcg((const float4*)&src[(size_t)(m0 + srow) * HID_ + sk1]);
            __syncthreads();
            *(float4*)&As[srow * 68 + sk0] = r4a;
            *(float4*)&As[srow * 68 + sk1] = r4b;
            r4a = __ldcg((const float4*)&src[(size_t)(m0 + srow) * HID_ + 64 + sk0]);
            r4b = __ldcg((const float4*)&src[(size_t)(m0 + srow) * HID_ + 64 + sk1]);
            __syncthreads();

            for (int s = 0; s < 8; s++) {
                const float* bufc = As + (s & 1) * (32 * 68);
                const int k0 = s * 64;
                #pragma unroll 8
                for (int kg = 0; kg < 16; kg++) {
                    ulonglong2 a0 = *(const ulonglong2*)&bufc[ttr * 68 + kg * 4];
                    ulonglong2 a1 = *(const ulonglong2*)&bufc[(ttr + 8) * 68 + kg * 4];
                    ulonglong2 a2 = *(const ulonglong2*)&bufc[(ttr + 16) * 68 + kg * 4];
                    ulonglong2 a3 = *(const ulonglong2*)&bufc[(ttr + 24) * 68 + kg * 4];
                    ulonglong2 bz2 = *(const ulonglong2*)&wZR[col * 516 + k0 + kg * 4];
                    ulonglong2 br2 = *(const ulonglong2*)&wZR[(col + 32) * 516 + k0 + kg * 4];
                    f2fma(az[0], a0.x, bz2.x); f2fma(az[0], a0.y, bz2.y);
                    f2fma(az[1], a1.x, bz2.x); f2fma(az[1], a1.y, bz2.y);
                    f2fma(az[2], a2.x, bz2.x); f2fma(az[2], a2.y, bz2.y);
                    f2fma(az[3], a3.x, bz2.x); f2fma(az[3], a3.y, bz2.y);
                    f2fma(ar[0], a0.x, br2.x); f2fma(ar[0], a0.y, br2.y);
                    f2fma(ar[1], a1.x, br2.x); f2fma(ar[1], a1.y, br2.y);
                    f2fma(ar[2], a2.x, br2.x); f2fma(ar[2], a2.y, br2.y);
                    f2fma(ar[3], a3.x, br2.x); f2fma(ar[3], a3.y, br2.y);
                }
                if (s < 7) {
                    float* bufn = As + ((s + 1) & 1) * (32 * 68);
                    *(float4*)&bufn[srow * 68 + sk0] = r4a;
                    *(float4*)&bufn[srow * 68 + sk1] = r4b;
                    if (s < 6) {
                        r4a = __ldcg((const float4*)&src[(size_t)(m0 + srow) * HID_ + (s + 2) * 64 + sk0]);
                        r4b = __ldcg((const float4*)&src[(size_t)(m0 + srow) * HID_ + (s + 2) * 64 + sk1]);
                    }
                    __syncthreads();
                }
            }
        }

        float zloc[4];
        #pragma unroll
        for (int u = 0; u < 4; u++) {
            const int m = m0 + ttr + 8 * u;
            zloc[u] = sigmoidf_(pz[u] + f2sum(az[u]));
            const float r = sigmoidf_(pr[u] + f2sum(ar[u]));
            g_rh[m * HID_ + j] = r * hv[u];
        }
        gbar(base + (++nbar));

        // ================= phase B: Sh = rh @ Whh slice =================
        u64 ah[4];
        #pragma unroll
        for (int u = 0; u < 4; u++) ah[u] = 0ull;

        {
            const float* __restrict__ src = g_rh;
            float4 r4a = __ldcg((const float4*)&src[(size_t)(m0 + srow) * HID_ + sk0]);
            float4 r4b = __ldcg((const float4*)&src[(size_t)(m0 + srow) * HID_ + sk1]);
            __syncthreads();
            *(float4*)&As[srow * 68 + sk0] = r4a;
            *(float4*)&As[srow * 68 + sk1] = r4b;
            r4a = __ldcg((const float4*)&src[(size_t)(m0 + srow) * HID_ + 64 + sk0]);
            r4b = __ldcg((const float4*)&src[(size_t)(m0 + srow) * HID_ + 64 + sk1]);
            __syncthreads();

            for (int s = 0; s < 8; s++) {
                const float* bufc = As + (s & 1) * (32 * 68);
                const int k0 = s * 64;
                #pragma unroll 8
                for (int kg = 0; kg < 16; kg++) {
                    ulonglong2 a0 = *(const ulonglong2*)&bufc[ttr * 68 + kg * 4];
                    ulonglong2 a1 = *(const ulonglong2*)&bufc[(ttr + 8) * 68 + kg * 4];
                    ulonglong2 a2 = *(const ulonglong2*)&bufc[(ttr + 16) * 68 + kg * 4];
                    ulonglong2 a3 = *(const ulonglong2*)&bufc[(ttr + 24) * 68 + kg * 4];
                    ulonglong2 bh2 = *(const ulonglong2*)&wH[col * 516 + k0 + kg * 4];
                    f2fma(ah[0], a0.x, bh2.x); f2fma(ah[0], a0.y, bh2.y);
                    f2fma(ah[1], a1.x, bh2.x); f2fma(ah[1], a1.y, bh2.y);
                    f2fma(ah[2], a2.x, bh2.x); f2fma(ah[2], a2.y, bh2.y);
                    f2fma(ah[3], a3.x, bh2.x); f2fma(ah[3], a3.y, bh2.y);
                }
                if (s < 7) {
                    float* bufn = As + ((s + 1) & 1) * (32 * 68);
                    *(float4*)&bufn[srow * 68 + sk0] = r4a;
                    *(float4*)&bufn[srow * 68 + sk1] = r4b;
                    if (s < 6) {
                        r4a = __ldcg((const float4*)&src[(size_t)(m0 + srow) * HID_ + (s + 2) * 64 + sk0]);
                        r4b = __ldcg((const float4*)&src[(size_t)(m0 + srow) * HID_ + (s + 2) * 64 + sk1]);
                    }
                    __syncthreads();
                }
            }
        }

        #pragma unroll
        for (int u = 0; u < 4; u++) {
            const int m = m0 + ttr + 8 * u;
            const float ht = tanhf(ph[u] + f2sum(ah[u]));
            const float hn = fmaf(zloc[u], ht - hv[u], hv[u]);
            hnext[m * HID_ + j] = hn;
            hs_out[((size_t)m * T_ + t) * HID_ + j] = hn;
        }
        if (t < T_ - 1) gbar(base + (++nbar));
    }
}

// =====================================================================================
// Kernel 4: out = relu(h_last @ w_out + b_out).  M=256, N=256, K=512.
// =====================================================================================
__global__ __launch_bounds__(256) void out_kernel(
    const float* __restrict__ w_out, const float* __restrict__ b_out,
    float* __restrict__ out)
{
    __shared__ __align__(16) float As[32][36];
    __shared__ __align__(16) float Bs[32][36];

    const float* __restrict__ hlast = g_h[0];   // T even -> final state in buffer 0

    const int tid = threadIdx.x;
    const int m0 = blockIdx.y * 32;
    const int n0 = blockIdx.x * 32;

    const int ttr = tid >> 4;
    const int ttc = tid & 15;
    const int arow = tid >> 3;
    const int akq  = tid & 7;
    const int bkr  = tid >> 3;
    const int bnq  = tid & 7;

    u64 acc[2][2];
    #pragma unroll
    for (int i = 0; i < 2; i++)
        #pragma unroll
        for (int p = 0; p < 2; p++) acc[i][p] = 0ull;

    for (int k0 = 0; k0 < HID_; k0 += 32) {
        float4 av = *(const float4*)&hlast[(size_t)(m0 + arow) * HID_ + k0 + akq * 4];
        float4 bv = *(const float4*)&w_out[(size_t)(k0 + bkr) * OUT_ + n0 + bnq * 4];

        __syncthreads();
        *(float4*)&As[arow][akq * 4] = av;
        Bs[bnq * 4 + 0][bkr] = bv.x; Bs[bnq * 4 + 1][bkr] = bv.y;
        Bs[bnq * 4 + 2][bkr] = bv.z; Bs[bnq * 4 + 3][bkr] = bv.w;
        __syncthreads();

        #pragma unroll
        for (int q = 0; q < 8; q++) {
            ulonglong2 a0 = *(const ulonglong2*)&As[ttr * 2 + 0][q * 4];
            ulonglong2 a1 = *(const ulonglong2*)&As[ttr * 2 + 1][q * 4];
            #pragma unroll
            for (int p = 0; p < 2; p++) {
                ulonglong2 bb = *(const ulonglong2*)&Bs[ttc + 16 * p][q * 4];
                f2fma(acc[0][p], a0.x, bb.x); f2fma(acc[0][p], a0.y, bb.y);
                f2fma(acc[1][p], a1.x, bb.x); f2fma(acc[1][p], a1.y, bb.y);
            }
        }
    }

    #pragma unroll
    for (int i = 0; i < 2; i++) {
        const int b = m0 + ttr * 2 + i;
        #pragma unroll
        for (int p = 0; p < 2; p++) {
            const int j = n0 + ttc + 16 * p;
            const float s = f2sum(acc[i][p]) + b_out[j];
            out[(size_t)b * OUT_ + j] = fmaxf(s, 0.0f);
        }
    }
}

// =====================================================================================
extern "C" void kernel_launch(void* const* d_in, const int* in_sizes, int n_in,
                              void* d_out, int out_size)
{
    const float* x     = (const float*)d_in[0];
    const float* c     = (const float*)d_in[1];
    const float* h0    = (const float*)d_in[2];
    const float* w_xr  = (const float*)d_in[3];
    const float* w_hr  = (const float*)d_in[4];
    const float* w_cr  = (const float*)d_in[5];
    const float* w_xz  = (const float*)d_in[6];
    const float* w_hz  = (const float*)d_in[7];
    const float* w_cz  = (const float*)d_in[8];
    const float* w_xh  = (const float*)d_in[9];
    const float* w_hh  = (const float*)d_in[10];
    const float* w_ch  = (const float*)d_in[11];
    const float* b_r   = (const float*)d_in[12];
    const float* b_z   = (const float*)d_in[13];
    const float* b_h   = (const float*)d_in[14];
    const float* w_out = (const float*)d_in[15];
    const float* b_out = (const float*)d_in[16];

    float* out = (float*)d_out;                 // [B, OUT] first
    float* hs  = out + (size_t)B_ * OUT_;       // then [B, T, HID]

    static int smem_set = 0;
    if (!smem_set) {
        cudaFuncSetAttribute(scan_kernel, cudaFuncAttributeMaxDynamicSharedMemorySize,
                             (int)SCAN_SMEM);
        smem_set = 1;
    }

    cudaMemcpyToSymbolAsync(g_h, h0, (size_t)B_ * HID_ * sizeof(float), 0,
                            cudaMemcpyDeviceToDevice, 0);

    pre_gemm_kernel<<<dim3(24, 1024), 256>>>(x, c,
                                             w_xz, w_cz, b_z,
                                             w_xr, w_cr, b_r,
                                             w_xh, w_ch, b_h);

    scan_kernel<<<NBLK, 256, SCAN_SMEM>>>(w_hz, w_hr, w_hh, hs);

    out_kernel<<<dim3(8, 8), 256>>>(w_out, b_out, out);
}

// round 10
// speedup vs baseline: 1.5313x; 1.3086x over previous
#include <cuda_runtime.h>
#include <cuda_bf16.h>
#include <math.h>

#define B_   256
#define T_   256
#define IN_  256
#define HID_ 512
#define OUT_ 256
#define NBLK 128

typedef unsigned long long u64;
typedef unsigned int u32;

// ---------- packed f32x2 FMA (scan/out kernels) ----------
__device__ __forceinline__ void f2fma(u64 &d, u64 a, u64 b) {
    asm("fma.rn.f32x2 %0, %1, %2, %0;" : "+l"(d) : "l"(a), "l"(b));
}
__device__ __forceinline__ float f2sum(u64 v) {
    unsigned lo, hi;
    asm("mov.b64 {%0, %1}, %2;" : "=r"(lo), "=r"(hi) : "l"(v));
    return __uint_as_float(lo) + __uint_as_float(hi);
}
__device__ __forceinline__ float sigmoidf_(float x) { return 1.0f / (1.0f + expf(-x)); }

// ---------- warp mma.sync m16n8k16 bf16 (sm_80+ baseline PTX; no arch-suffix needed) ----------
#define MMA16816(d, a, b) \
    asm volatile("mma.sync.aligned.m16n8k16.row.col.f32.bf16.bf16.f32 " \
        "{%0,%1,%2,%3}, {%4,%5,%6,%7}, {%8,%9}, {%0,%1,%2,%3};" \
        : "+f"((d)[0]), "+f"((d)[1]), "+f"((d)[2]), "+f"((d)[3]) \
        : "r"((a)[0]), "r"((a)[1]), "r"((a)[2]), "r"((a)[3]), \
          "r"((b)[0]), "r"((b)[1]))

// ---------- device scratch ----------
__device__ float g_pre[(size_t)B_ * T_ * 3 * HID_];
__device__ float g_h[2][B_ * HID_];
__device__ float g_rh[B_ * HID_];
__device__ unsigned g_flags[NBLK * 32];
// bf16 hi/lo images: A row-major [65536][512]; B n-major [3][512][512]
__device__ __align__(16) unsigned short g_Ahi[(size_t)65536 * 512];
__device__ __align__(16) unsigned short g_Alo[(size_t)65536 * 512];
__device__ __align__(16) unsigned short g_Bhi[3 * 512 * 512];
__device__ __align__(16) unsigned short g_Blo[3 * 512 * 512];

// =====================================================================================
// Convert A: [x|c] fp32 -> bf16 hi/lo row-major [m][512]
// =====================================================================================
__global__ __launch_bounds__(256) void convertA_kernel(
    const float* __restrict__ x, const float* __restrict__ c)
{
    const size_t idx = (size_t)blockIdx.x * 256 + threadIdx.x;   // 8388608 total
    const int m  = (int)(idx >> 7);
    const int kq = ((int)idx & 127) << 2;
    const float* src = (kq < 256) ? &x[(size_t)m * 256 + kq]
                                  : &c[(size_t)m * 256 + (kq - 256)];
    float4 v = *(const float4*)src;
    float vv[4] = {v.x, v.y, v.z, v.w};
    unsigned h[4], l[4];
    #pragma unroll
    for (int i = 0; i < 4; i++) {
        __nv_bfloat16 bh = __float2bfloat16(vv[i]);
        __nv_bfloat16 bl = __float2bfloat16(vv[i] - __bfloat162float(bh));
        h[i] = (unsigned)__bfloat16_as_ushort(bh);
        l[i] = (unsigned)__bfloat16_as_ushort(bl);
    }
    const size_t base = (size_t)m * 512 + kq;
    *(uint2*)&g_Ahi[base] = make_uint2(h[0] | (h[1] << 16), h[2] | (h[3] << 16));
    *(uint2*)&g_Alo[base] = make_uint2(l[0] | (l[1] << 16), l[2] | (l[3] << 16));
}

// =====================================================================================
// Convert B: [Wx;Wc] (k-major [512][512]) -> bf16 hi/lo n-major [gate][n][k]
// =====================================================================================
__global__ __launch_bounds__(256) void convertB_kernel(
    const float* __restrict__ wxz, const float* __restrict__ wxr, const float* __restrict__ wxh,
    const float* __restrict__ wcz, const float* __restrict__ wcr, const float* __restrict__ wch)
{
    const int idx = blockIdx.x * 256 + threadIdx.x;   // 196608 total
    const int gate = idx >> 16;
    const int rem  = idx & 65535;
    const int k  = rem >> 7;
    const int nq = (rem & 127) << 2;
    const float* wx = (gate == 0) ? wxz : (gate == 1) ? wxr : wxh;
    const float* wc = (gate == 0) ? wcz : (gate == 1) ? wcr : wch;
    const float* src = (k < 256) ? &wx[(size_t)k * 512 + nq]
                                 : &wc[(size_t)(k - 256) * 512 + nq];
    float4 v = *(const float4*)src;
    float vv[4] = {v.x, v.y, v.z, v.w};
    #pragma unroll
    for (int i = 0; i < 4; i++) {
        __nv_bfloat16 bh = __float2bfloat16(vv[i]);
        __nv_bfloat16 bl = __float2bfloat16(vv[i] - __bfloat162float(bh));
        const size_t dst = ((size_t)(gate * 512 + nq + i)) * 512 + k;
        g_Bhi[dst] = __bfloat16_as_ushort(bh);
        g_Blo[dst] = __bfloat16_as_ushort(bl);
    }
}

// =====================================================================================
// PRE via mma.sync: block = 128 rows x 128 cols, grid (12 ntiles, 512 mtiles).
// 8 warps (2 row-groups x 4 col-groups), warp tile 64x32, K-chunks of 64.
// smem pitch 144B -> fragment LDS conflict-free. hi/lo split: 3 products.
// =====================================================================================
#define PMA_PITCH 144                       // bytes per 64-k row (128 data + 16 pad)
#define PMA_IMG   (128 * PMA_PITCH)         // 18432 B per image
#define PM_SMEM   (4 * PMA_IMG)             // Ahi, Alo, Bhi, Blo = 73728 B

__global__ __launch_bounds__(256) void pre_mma_kernel(
    const float* __restrict__ bz, const float* __restrict__ br, const float* __restrict__ bh)
{
    extern __shared__ __align__(16) char psm[];
    char* sAhi = psm;
    char* sAlo = psm + PMA_IMG;
    char* sBhi = psm + 2 * PMA_IMG;
    char* sBlo = psm + 3 * PMA_IMG;

    const int tid = threadIdx.x;
    const int wid = tid >> 5, lane = tid & 31;
    const int g   = lane >> 2;          // groupID 0..7
    const int tig = lane & 3;           // thread-in-group

    const int ntg   = blockIdx.x;       // 0..11
    const int mtile = blockIdx.y;       // 0..511
    const int gate  = ntg >> 2;
    const int n0    = (ntg & 3) * 128;  // col base within gate

    const int wm = wid >> 2;            // 0..1  (row group: 64 rows)
    const int wn = wid & 3;             // 0..3  (col group: 32 cols)

    float acc[4][4][4];
    #pragma unroll
    for (int mi = 0; mi < 4; mi++)
        #pragma unroll
        for (int ni = 0; ni < 4; ni++)
            #pragma unroll
            for (int e = 0; e < 4; e++) acc[mi][ni][e] = 0.0f;

    for (int kc = 0; kc < 8; kc++) {
        __syncthreads();
        // load 64-k chunk of all four images into smem (uint4 = 8 bf16)
        #pragma unroll
        for (int i = 0; i < 4; i++) {
            const int lin = tid + 256 * i;      // 0..1023
            const int row = lin >> 3, q = lin & 7;
            const size_t asrc = ((size_t)(mtile * 128 + row)) * 512 + kc * 64 + q * 8;
            const size_t bsrc = ((size_t)(gate * 512 + n0 + row)) * 512 + kc * 64 + q * 8;
            *(uint4*)(sAhi + row * PMA_PITCH + q * 16) = *(const uint4*)&g_Ahi[asrc];
            *(uint4*)(sAlo + row * PMA_PITCH + q * 16) = *(const uint4*)&g_Alo[asrc];
            *(uint4*)(sBhi + row * PMA_PITCH + q * 16) = *(const uint4*)&g_Bhi[bsrc];
            *(uint4*)(sBlo + row * PMA_PITCH + q * 16) = *(const uint4*)&g_Blo[bsrc];
        }
        __syncthreads();

        #pragma unroll
        for (int kk = 0; kk < 4; kk++) {
            const int kb = kk * 32 + tig * 4;   // byte offset of (k, k+1) pair
            u32 ah[4][4], al[4][4], bhf[4][2], blf[4][2];
            #pragma unroll
            for (int mi = 0; mi < 4; mi++) {
                const int rbase = (wm * 64 + mi * 16 + g) * PMA_PITCH + kb;
                ah[mi][0] = *(const u32*)(sAhi + rbase);
                ah[mi][1] = *(const u32*)(sAhi + rbase + 8 * PMA_PITCH);
                ah[mi][2] = *(const u32*)(sAhi + rbase + 16);
                ah[mi][3] = *(const u32*)(sAhi + rbase + 8 * PMA_PITCH + 16);
                al[mi][0] = *(const u32*)(sAlo + rbase);
                al[mi][1] = *(const u32*)(sAlo + rbase + 8 * PMA_PITCH);
                al[mi][2] = *(const u32*)(sAlo + rbase + 16);
                al[mi][3] = *(const u32*)(sAlo + rbase + 8 * PMA_PITCH + 16);
            }
            #pragma unroll
            for (int ni = 0; ni < 4; ni++) {
                const int nbase = (wn * 32 + ni * 8 + g) * PMA_PITCH + kb;
                bhf[ni][0] = *(const u32*)(sBhi + nbase);
                bhf[ni][1] = *(const u32*)(sBhi + nbase + 16);
                blf[ni][0] = *(const u32*)(sBlo + nbase);
                blf[ni][1] = *(const u32*)(sBlo + nbase + 16);
            }
            #pragma unroll
            for (int mi = 0; mi < 4; mi++)
                #pragma unroll
                for (int ni = 0; ni < 4; ni++) {
                    MMA16816(acc[mi][ni], ah[mi], bhf[ni]);
                    MMA16816(acc[mi][ni], ah[mi], blf[ni]);
                    MMA16816(acc[mi][ni], al[mi], bhf[ni]);
                }
        }
    }

    // epilogue: bias + store
    const float* bias = (gate == 0) ? bz : (gate == 1) ? br : bh;
    #pragma unroll
    for (int mi = 0; mi < 4; mi++) {
        const int r0 = mtile * 128 + wm * 64 + mi * 16 + g;
        #pragma unroll
        for (int ni = 0; ni < 4; ni++) {
            const int cl = n0 + wn * 32 + ni * 8 + tig * 2;   // col within gate, 0..511
            const float b0 = bias[cl], b1 = bias[cl + 1];
            float* d0 = &g_pre[(size_t)r0 * 1536 + gate * 512 + cl];
            float* d1 = &g_pre[(size_t)(r0 + 8) * 1536 + gate * 512 + cl];
            *(float2*)d0 = make_float2(acc[mi][ni][0] + b0, acc[mi][ni][1] + b1);
            *(float2*)d1 = make_float2(acc[mi][ni][2] + b0, acc[mi][ni][3] + b1);
        }
    }
}

// =====================================================================================
// Flag-based grid barrier (unchanged)
// =====================================================================================
__device__ __forceinline__ void gbar(unsigned want)
{
    __syncthreads();
    if (threadIdx.x == 0) {
        asm volatile("st.release.gpu.global.u32 [%0], %1;"
                     :: "l"(&g_flags[blockIdx.x * 32]), "r"(want) : "memory");
    }
    if (threadIdx.x < NBLK) {
        unsigned v;
        do {
            asm volatile("ld.acquire.gpu.global.u32 %0, [%1];"
                         : "=r"(v) : "l"(&g_flags[threadIdx.x * 32]) : "memory");
        } while ((int)(v - want) < 0);
    }
    __syncthreads();
}

// =====================================================================================
// Persistent scan kernel (unchanged 8208us version)
// =====================================================================================
#define SC_WZR_F (64 * 516)
#define SC_WH_F  (32 * 516)
#define SC_AS_F  (32 * 132)
#define SCAN_SMEM ((SC_WZR_F + SC_WH_F + SC_AS_F) * sizeof(float))

__global__ __launch_bounds__(256, 1) void scan_kernel(
    const float* __restrict__ w_hz, const float* __restrict__ w_hr,
    const float* __restrict__ w_hh, float* __restrict__ hs_out)
{
    extern __shared__ float sm[];
    float* wZR = sm;
    float* wH  = sm + SC_WZR_F;
    float* As  = sm + SC_WZR_F + SC_WH_F;

    const int tid = threadIdx.x;
    const int bid = blockIdx.x;
    const int bm = bid >> 4;
    const int bn = bid & 15;
    const int m0 = bm * 32;
    const int j0 = bn * 32;

    for (int idx = tid; idx < 512 * 8; idx += 256) {
        const int k  = idx >> 3;
        const int c4 = (idx & 7) * 4;
        float4 vz = *(const float4*)&w_hz[(size_t)k * HID_ + j0 + c4];
        float4 vr = *(const float4*)&w_hr[(size_t)k * HID_ + j0 + c4];
        float4 vh = *(const float4*)&w_hh[(size_t)k * HID_ + j0 + c4];
        wZR[(c4 + 0) * 516 + k] = vz.x; wZR[(c4 + 1) * 516 + k] = vz.y;
        wZR[(c4 + 2) * 516 + k] = vz.z; wZR[(c4 + 3) * 516 + k] = vz.w;
        wZR[(32 + c4 + 0) * 516 + k] = vr.x; wZR[(32 + c4 + 1) * 516 + k] = vr.y;
        wZR[(32 + c4 + 2) * 516 + k] = vr.z; wZR[(32 + c4 + 3) * 516 + k] = vr.w;
        wH[(c4 + 0) * 516 + k] = vh.x; wH[(c4 + 1) * 516 + k] = vh.y;
        wH[(c4 + 2) * 516 + k] = vh.z; wH[(c4 + 3) * 516 + k] = vh.w;
    }

    __shared__ unsigned s_base;
    if (tid == 0) s_base = *(volatile unsigned*)&g_flags[bid * 32];
    __syncthreads();
    const unsigned base = s_base;
    unsigned nbar = 0;

    const int wid  = tid >> 5, lane = tid & 31;
    const int ttr  = (wid >> 2) * 4 + (lane >> 3);
    const int col  = (wid & 3) * 8 + (lane & 7);
    const int j    = j0 + col;

    const int srow = tid >> 3;
    const int sk   = (((tid & 7) ^ (srow & 7)) * 4);

    for (int t = 0; t < T_; t++) {
        const float* __restrict__ hprev = g_h[t & 1];
        float* __restrict__ hnext = g_h[(t + 1) & 1];

        float pz[4], pr[4], ph2[4], hv[4];
        #pragma unroll
        for (int u = 0; u < 4; u++) {
            const int m = m0 + ttr + 8 * u;
            const size_t prow = ((size_t)m * T_ + t) * 1536;
            pz[u]  = __ldg(&g_pre[prow + j]);
            pr[u]  = __ldg(&g_pre[prow + 512 + j]);
            ph2[u] = __ldg(&g_pre[prow + 1024 + j]);
            hv[u]  = __ldcg(&hprev[m * HID_ + j]);
        }

        u64 az[4], ar[4];
        #pragma unroll
        for (int u = 0; u < 4; u++) { az[u] = 0ull; ar[u] = 0ull; }

        float4 r4[4];
        #pragma unroll
        for (int ps = 0; ps < 4; ps++)
            r4[ps] = __ldcg((const float4*)&hprev[(size_t)(m0 + srow) * HID_ + ps * 32 + sk]);

        for (int ch = 0; ch < 4; ch++) {
            const int k0 = ch * 128;
            __syncthreads();
            #pragma unroll
            for (int ps = 0; ps < 4; ps++)
                *(float4*)&As[srow * 132 + ps * 32 + sk] = r4[ps];
            __syncthreads();
            if (ch < 3) {
                #pragma unroll
                for (int ps = 0; ps < 4; ps++)
                    r4[ps] = __ldcg((const float4*)&hprev[(size_t)(m0 + srow) * HID_ + k0 + 128 + ps * 32 + sk]);
            }
            #pragma unroll 8
            for (int kg = 0; kg < 32; kg++) {
                ulonglong2 bz2 = *(const ulonglong2*)&wZR[col * 516 + k0 + kg * 4];
                ulonglong2 br2 = *(const ulonglong2*)&wZR[(col + 32) * 516 + k0 + kg * 4];
                #pragma unroll
                for (int u = 0; u < 4; u++) {
                    ulonglong2 a = *(const ulonglong2*)&As[(ttr + 8 * u) * 132 + kg * 4];
                    f2fma(az[u], a.x, bz2.x); f2fma(az[u], a.y, bz2.y);
                    f2fma(ar[u], a.x, br2.x); f2fma(ar[u], a.y, br2.y);
                }
            }
        }

        float zloc[4];
        #pragma unroll
        for (int u = 0; u < 4; u++) {
            const int m = m0 + ttr + 8 * u;
            zloc[u] = sigmoidf_(pz[u] + f2sum(az[u]));
            const float r = sigmoidf_(pr[u] + f2sum(ar[u]));
            g_rh[m * HID_ + j] = r * hv[u];
        }
        gbar(base + (++nbar));

        u64 ah2[4];
        #pragma unroll
        for (int u = 0; u < 4; u++) ah2[u] = 0ull;

        #pragma unroll
        for (int ps = 0; ps < 4; ps++)
            r4[ps] = __ldcg((const float4*)&g_rh[(size_t)(m0 + srow) * HID_ + ps * 32 + sk]);

        for (int ch = 0; ch < 4; ch++) {
            const int k0 = ch * 128;
            __syncthreads();
            #pragma unroll
            for (int ps = 0; ps < 4; ps++)
                *(float4*)&As[srow * 132 + ps * 32 + sk] = r4[ps];
            __syncthreads();
            if (ch < 3) {
                #pragma unroll
                for (int ps = 0; ps < 4; ps++)
                    r4[ps] = __ldcg((const float4*)&g_rh[(size_t)(m0 + srow) * HID_ + k0 + 128 + ps * 32 + sk]);
            }
            #pragma unroll 8
            for (int kg = 0; kg < 32; kg++) {
                ulonglong2 bh2 = *(const ulonglong2*)&wH[col * 516 + k0 + kg * 4];
                #pragma unroll
                for (int u = 0; u < 4; u++) {
                    ulonglong2 a = *(const ulonglong2*)&As[(ttr + 8 * u) * 132 + kg * 4];
                    f2fma(ah2[u], a.x, bh2.x); f2fma(ah2[u], a.y, bh2.y);
                }
            }
        }

        #pragma unroll
        for (int u = 0; u < 4; u++) {
            const int m = m0 + ttr + 8 * u;
            const float ht = tanhf(ph2[u] + f2sum(ah2[u]));
            const float hn = fmaf(zloc[u], ht - hv[u], hv[u]);
            hnext[m * HID_ + j] = hn;
            hs_out[((size_t)m * T_ + t) * HID_ + j] = hn;
        }
        if (t < T_ - 1) gbar(base + (++nbar));
    }
}

// =====================================================================================
// out = relu(h_last @ w_out + b_out)  (unchanged)
// =====================================================================================
__global__ __launch_bounds__(256) void out_kernel(
    const float* __restrict__ w_out, const float* __restrict__ b_out,
    float* __restrict__ out)
{
    __shared__ __align__(16) float As[32][36];
    __shared__ __align__(16) float Bs[32][36];

    const float* __restrict__ hlast = g_h[0];

    const int tid = threadIdx.x;
    const int m0 = blockIdx.y * 32;
    const int n0 = blockIdx.x * 32;

    const int ttr = tid >> 4;
    const int ttc = tid & 15;
    const int arow = tid >> 3;
    const int akq  = tid & 7;
    const int bkr  = tid >> 3;
    const int bnq  = tid & 7;

    u64 acc[2][2];
    #pragma unroll
    for (int i = 0; i < 2; i++)
        #pragma unroll
        for (int p = 0; p < 2; p++) acc[i][p] = 0ull;

    for (int k0 = 0; k0 < HID_; k0 += 32) {
        float4 av = *(const float4*)&hlast[(size_t)(m0 + arow) * HID_ + k0 + akq * 4];
        float4 bv = *(const float4*)&w_out[(size_t)(k0 + bkr) * OUT_ + n0 + bnq * 4];

        __syncthreads();
        *(float4*)&As[arow][akq * 4] = av;
        Bs[bnq * 4 + 0][bkr] = bv.x; Bs[bnq * 4 + 1][bkr] = bv.y;
        Bs[bnq * 4 + 2][bkr] = bv.z; Bs[bnq * 4 + 3][bkr] = bv.w;
        __syncthreads();

        #pragma unroll
        for (int q = 0; q < 8; q++) {
            ulonglong2 a0 = *(const ulonglong2*)&As[ttr * 2 + 0][q * 4];
            ulonglong2 a1 = *(const ulonglong2*)&As[ttr * 2 + 1][q * 4];
            #pragma unroll
            for (int p = 0; p < 2; p++) {
                ulonglong2 bb = *(const ulonglong2*)&Bs[ttc + 16 * p][q * 4];
                f2fma(acc[0][p], a0.x, bb.x); f2fma(acc[0][p], a0.y, bb.y);
                f2fma(acc[1][p], a1.x, bb.x); f2fma(acc[1][p], a1.y, bb.y);
            }
        }
    }

    #pragma unroll
    for (int i = 0; i < 2; i++) {
        const int b = m0 + ttr * 2 + i;
        #pragma unroll
        for (int p = 0; p < 2; p++) {
            const int j = n0 + ttc + 16 * p;
            const float s = f2sum(acc[i][p]) + b_out[j];
            out[(size_t)b * OUT_ + j] = fmaxf(s, 0.0f);
        }
    }
}

// =====================================================================================
extern "C" void kernel_launch(void* const* d_in, const int* in_sizes, int n_in,
                              void* d_out, int out_size)
{
    const float* x     = (const float*)d_in[0];
    const float* c     = (const float*)d_in[1];
    const float* h0    = (const float*)d_in[2];
    const float* w_xr  = (const float*)d_in[3];
    const float* w_hr  = (const float*)d_in[4];
    const float* w_cr  = (const float*)d_in[5];
    const float* w_xz  = (const float*)d_in[6];
    const float* w_hz  = (const float*)d_in[7];
    const float* w_cz  = (const float*)d_in[8];
    const float* w_xh  = (const float*)d_in[9];
    const float* w_hh  = (const float*)d_in[10];
    const float* w_ch  = (const float*)d_in[11];
    const float* b_r   = (const float*)d_in[12];
    const float* b_z   = (const float*)d_in[13];
    const float* b_h   = (const float*)d_in[14];
    const float* w_out = (const float*)d_in[15];
    const float* b_out = (const float*)d_in[16];

    float* out = (float*)d_out;
    float* hs  = out + (size_t)B_ * OUT_;

    static int attr_set = 0;
    if (!attr_set) {
        cudaFuncSetAttribute(scan_kernel, cudaFuncAttributeMaxDynamicSharedMemorySize,
                             (int)SCAN_SMEM);
        cudaFuncSetAttribute(pre_mma_kernel, cudaFuncAttributeMaxDynamicSharedMemorySize,
                             PM_SMEM);
        attr_set = 1;
    }

    cudaMemcpyToSymbolAsync(g_h, h0, (size_t)B_ * HID_ * sizeof(float), 0,
                            cudaMemcpyDeviceToDevice, 0);

    convertA_kernel<<<32768, 256>>>(x, c);
    convertB_kernel<<<768, 256>>>(w_xz, w_xr, w_xh, w_cz, w_cr, w_ch);
    pre_mma_kernel<<<dim3(12, 512), 256, PM_SMEM>>>(b_z, b_r, b_h);

    scan_kernel<<<NBLK, 256, SCAN_SMEM>>>(w_hz, w_hr, w_hh, hs);

    out_kernel<<<dim3(8, 8), 256>>>(w_out, b_out, out);
}

// round 11
// speedup vs baseline: 2.3800x; 1.5542x over previous
#include <cuda_runtime.h>
#include <cuda_bf16.h>
#include <math.h>

#define B_   256
#define T_   256
#define IN_  256
#define HID_ 512
#define OUT_ 256
#define NBLK 128

typedef unsigned long long u64;
typedef unsigned int u32;
typedef unsigned short u16;

// ---------- packed f32x2 FMA (out kernel) ----------
__device__ __forceinline__ void f2fma(u64 &d, u64 a, u64 b) {
    asm("fma.rn.f32x2 %0, %1, %2, %0;" : "+l"(d) : "l"(a), "l"(b));
}
__device__ __forceinline__ float f2sum(u64 v) {
    unsigned lo, hi;
    asm("mov.b64 {%0, %1}, %2;" : "=r"(lo), "=r"(hi) : "l"(v));
    return __uint_as_float(lo) + __uint_as_float(hi);
}
__device__ __forceinline__ float sigmoidf_(float x) { return 1.0f / (1.0f + expf(-x)); }

// ---------- warp mma.sync m16n8k16 bf16 ----------
#define MMA16816(d, a, b) \
    asm volatile("mma.sync.aligned.m16n8k16.row.col.f32.bf16.bf16.f32 " \
        "{%0,%1,%2,%3}, {%4,%5,%6,%7}, {%8,%9}, {%0,%1,%2,%3};" \
        : "+f"((d)[0]), "+f"((d)[1]), "+f"((d)[2]), "+f"((d)[3]) \
        : "r"((a)[0]), "r"((a)[1]), "r"((a)[2]), "r"((a)[3]), \
          "r"((b)[0]), "r"((b)[1]))

__device__ __forceinline__ void bsplit(float v, u16 &hi, u16 &lo) {
    __nv_bfloat16 h = __float2bfloat16(v);
    __nv_bfloat16 l = __float2bfloat16(v - __bfloat162float(h));
    hi = __bfloat16_as_ushort(h);
    lo = __bfloat16_as_ushort(l);
}

// ---------- device scratch ----------
__device__ float g_pre[(size_t)B_ * T_ * 3 * HID_];
__device__ float g_h[2][B_ * HID_];
__device__ unsigned g_flags[NBLK * 32];
// bf16 hi/lo state images for scan GEMMs
__device__ __align__(16) u16 g_hbf_hi[2][B_ * HID_];
__device__ __align__(16) u16 g_hbf_lo[2][B_ * HID_];
__device__ __align__(16) u16 g_rhbf_hi[B_ * HID_];
__device__ __align__(16) u16 g_rhbf_lo[B_ * HID_];
// pre-GEMM bf16 images
__device__ __align__(16) u16 g_Ahi[(size_t)65536 * 512];
__device__ __align__(16) u16 g_Alo[(size_t)65536 * 512];
__device__ __align__(16) u16 g_Bhi[3 * 512 * 512];
__device__ __align__(16) u16 g_Blo[3 * 512 * 512];

// =====================================================================================
// Convert A: [x|c] fp32 -> bf16 hi/lo row-major [m][512]   (unchanged, passed R10)
// =====================================================================================
__global__ __launch_bounds__(256) void convertA_kernel(
    const float* __restrict__ x, const float* __restrict__ c)
{
    const size_t idx = (size_t)blockIdx.x * 256 + threadIdx.x;
    const int m  = (int)(idx >> 7);
    const int kq = ((int)idx & 127) << 2;
    const float* src = (kq < 256) ? &x[(size_t)m * 256 + kq]
                                  : &c[(size_t)m * 256 + (kq - 256)];
    float4 v = *(const float4*)src;
    float vv[4] = {v.x, v.y, v.z, v.w};
    unsigned h[4], l[4];
    #pragma unroll
    for (int i = 0; i < 4; i++) {
        u16 hh, ll; bsplit(vv[i], hh, ll);
        h[i] = hh; l[i] = ll;
    }
    const size_t base = (size_t)m * 512 + kq;
    *(uint2*)&g_Ahi[base] = make_uint2(h[0] | (h[1] << 16), h[2] | (h[3] << 16));
    *(uint2*)&g_Alo[base] = make_uint2(l[0] | (l[1] << 16), l[2] | (l[3] << 16));
}

// =====================================================================================
// Convert B (pre weights)  (unchanged, passed R10)
// =====================================================================================
__global__ __launch_bounds__(256) void convertB_kernel(
    const float* __restrict__ wxz, const float* __restrict__ wxr, const float* __restrict__ wxh,
    const float* __restrict__ wcz, const float* __restrict__ wcr, const float* __restrict__ wch)
{
    const int idx = blockIdx.x * 256 + threadIdx.x;
    const int gate = idx >> 16;
    const int rem  = idx & 65535;
    const int k  = rem >> 7;
    const int nq = (rem & 127) << 2;
    const float* wx = (gate == 0) ? wxz : (gate == 1) ? wxr : wxh;
    const float* wc = (gate == 0) ? wcz : (gate == 1) ? wcr : wch;
    const float* src = (k < 256) ? &wx[(size_t)k * 512 + nq]
                                 : &wc[(size_t)(k - 256) * 512 + nq];
    float4 v = *(const float4*)src;
    float vv[4] = {v.x, v.y, v.z, v.w};
    #pragma unroll
    for (int i = 0; i < 4; i++) {
        u16 hh, ll; bsplit(vv[i], hh, ll);
        const size_t dst = ((size_t)(gate * 512 + nq + i)) * 512 + k;
        g_Bhi[dst] = hh;
        g_Blo[dst] = ll;
    }
}

// =====================================================================================
// init h0: fp32 copy + bf16 hi/lo images
// =====================================================================================
__global__ __launch_bounds__(256) void init_h_kernel(const float* __restrict__ h0)
{
    const int idx = blockIdx.x * 256 + threadIdx.x;   // 131072
    float v = h0[idx];
    g_h[0][idx] = v;
    u16 hh, ll; bsplit(v, hh, ll);
    g_hbf_hi[0][idx] = hh;
    g_hbf_lo[0][idx] = ll;
}

// =====================================================================================
// PRE via mma.sync  (unchanged, passed R10)
// =====================================================================================
#define PMA_PITCH 144
#define PMA_IMG   (128 * PMA_PITCH)
#define PM_SMEM   (4 * PMA_IMG)

__global__ __launch_bounds__(256) void pre_mma_kernel(
    const float* __restrict__ bz, const float* __restrict__ br, const float* __restrict__ bh)
{
    extern __shared__ __align__(16) char psm[];
    char* sAhi = psm;
    char* sAlo = psm + PMA_IMG;
    char* sBhi = psm + 2 * PMA_IMG;
    char* sBlo = psm + 3 * PMA_IMG;

    const int tid = threadIdx.x;
    const int wid = tid >> 5, lane = tid & 31;
    const int g   = lane >> 2;
    const int tig = lane & 3;

    const int ntg   = blockIdx.x;
    const int mtile = blockIdx.y;
    const int gate  = ntg >> 2;
    const int n0    = (ntg & 3) * 128;

    const int wm = wid >> 2;
    const int wn = wid & 3;

    float acc[4][4][4];
    #pragma unroll
    for (int mi = 0; mi < 4; mi++)
        #pragma unroll
        for (int ni = 0; ni < 4; ni++)
            #pragma unroll
            for (int e = 0; e < 4; e++) acc[mi][ni][e] = 0.0f;

    for (int kc = 0; kc < 8; kc++) {
        __syncthreads();
        #pragma unroll
        for (int i = 0; i < 4; i++) {
            const int lin = tid + 256 * i;
            const int row = lin >> 3, q = lin & 7;
            const size_t asrc = ((size_t)(mtile * 128 + row)) * 512 + kc * 64 + q * 8;
            const size_t bsrc = ((size_t)(gate * 512 + n0 + row)) * 512 + kc * 64 + q * 8;
            *(uint4*)(sAhi + row * PMA_PITCH + q * 16) = *(const uint4*)&g_Ahi[asrc];
            *(uint4*)(sAlo + row * PMA_PITCH + q * 16) = *(const uint4*)&g_Alo[asrc];
            *(uint4*)(sBhi + row * PMA_PITCH + q * 16) = *(const uint4*)&g_Bhi[bsrc];
            *(uint4*)(sBlo + row * PMA_PITCH + q * 16) = *(const uint4*)&g_Blo[bsrc];
        }
        __syncthreads();

        #pragma unroll
        for (int kk = 0; kk < 4; kk++) {
            const int kb = kk * 32 + tig * 4;
            u32 ah[4][4], al[4][4], bhf[4][2], blf[4][2];
            #pragma unroll
            for (int mi = 0; mi < 4; mi++) {
                const int rbase = (wm * 64 + mi * 16 + g) * PMA_PITCH + kb;
                ah[mi][0] = *(const u32*)(sAhi + rbase);
                ah[mi][1] = *(const u32*)(sAhi + rbase + 8 * PMA_PITCH);
                ah[mi][2] = *(const u32*)(sAhi + rbase + 16);
                ah[mi][3] = *(const u32*)(sAhi + rbase + 8 * PMA_PITCH + 16);
                al[mi][0] = *(const u32*)(sAlo + rbase);
                al[mi][1] = *(const u32*)(sAlo + rbase + 8 * PMA_PITCH);
                al[mi][2] = *(const u32*)(sAlo + rbase + 16);
                al[mi][3] = *(const u32*)(sAlo + rbase + 8 * PMA_PITCH + 16);
            }
            #pragma unroll
            for (int ni = 0; ni < 4; ni++) {
                const int nbase = (wn * 32 + ni * 8 + g) * PMA_PITCH + kb;
                bhf[ni][0] = *(const u32*)(sBhi + nbase);
                bhf[ni][1] = *(const u32*)(sBhi + nbase + 16);
                blf[ni][0] = *(const u32*)(sBlo + nbase);
                blf[ni][1] = *(const u32*)(sBlo + nbase + 16);
            }
            #pragma unroll
            for (int mi = 0; mi < 4; mi++)
                #pragma unroll
                for (int ni = 0; ni < 4; ni++) {
                    MMA16816(acc[mi][ni], ah[mi], bhf[ni]);
                    MMA16816(acc[mi][ni], ah[mi], blf[ni]);
                    MMA16816(acc[mi][ni], al[mi], bhf[ni]);
                }
        }
    }

    const float* bias = (gate == 0) ? bz : (gate == 1) ? br : bh;
    #pragma unroll
    for (int mi = 0; mi < 4; mi++) {
        const int r0 = mtile * 128 + wm * 64 + mi * 16 + g;
        #pragma unroll
        for (int ni = 0; ni < 4; ni++) {
            const int cl = n0 + wn * 32 + ni * 8 + tig * 2;
            const float b0 = bias[cl], b1 = bias[cl + 1];
            float* d0 = &g_pre[(size_t)r0 * 1536 + gate * 512 + cl];
            float* d1 = &g_pre[(size_t)(r0 + 8) * 1536 + gate * 512 + cl];
            *(float2*)d0 = make_float2(acc[mi][ni][0] + b0, acc[mi][ni][1] + b1);
            *(float2*)d1 = make_float2(acc[mi][ni][2] + b0, acc[mi][ni][3] + b1);
        }
    }
}

// =====================================================================================
// Flag-based grid barrier (unchanged)
// =====================================================================================
__device__ __forceinline__ void gbar(unsigned want)
{
    __syncthreads();
    if (threadIdx.x == 0) {
        asm volatile("st.release.gpu.global.u32 [%0], %1;"
                     :: "l"(&g_flags[blockIdx.x * 32]), "r"(want) : "memory");
    }
    if (threadIdx.x < NBLK) {
        unsigned v;
        do {
            asm volatile("ld.acquire.gpu.global.u32 %0, [%1];"
                         : "=r"(v) : "l"(&g_flags[threadIdx.x * 32]) : "memory");
        } while ((int)(v - want) < 0);
    }
    __syncthreads();
}

// =====================================================================================
// Tensor-core persistent scan: 128 blocks = 8 m-tiles(32) x 16 n-tiles(32), 256 thr.
// Phase A: [32x512] @ [512x64] (z|r), phase B: [32x512] @ [512x32], bf16 hi/lo split.
// Weights in smem bf16 hi/lo (n-major, 520-elem pitch). State staged per 128-k chunk.
// =====================================================================================
#define WPITCH 520                        // bf16 elements per weight row (1040 B)
#define APITCH 272                        // bytes per staged A row (128 bf16 + pad)
#define SOFF_WZR_HI 0
#define SOFF_WZR_LO (SOFF_WZR_HI + 64 * WPITCH * 2)       // 66560
#define SOFF_WH_HI  (SOFF_WZR_LO + 64 * WPITCH * 2)       // 133120
#define SOFF_WH_LO  (SOFF_WH_HI + 32 * WPITCH * 2)        // 166400
#define SOFF_SA_HI  (SOFF_WH_LO + 32 * WPITCH * 2)        // 199680
#define SOFF_SA_LO  (SOFF_SA_HI + 32 * APITCH)            // 208384
#define SOFF_ZBUF   (SOFF_SA_LO + 32 * APITCH)            // 217088
#define SC2_SMEM    (SOFF_ZBUF + 32 * 33 * 4)             // 221312

__global__ __launch_bounds__(256, 1) void scan_mma_kernel(
    const float* __restrict__ w_hz, const float* __restrict__ w_hr,
    const float* __restrict__ w_hh, float* __restrict__ hs_out)
{
    extern __shared__ __align__(16) char sm2[];
    u16* wZRhi = (u16*)(sm2 + SOFF_WZR_HI);
    u16* wZRlo = (u16*)(sm2 + SOFF_WZR_LO);
    u16* wHhi  = (u16*)(sm2 + SOFF_WH_HI);
    u16* wHlo  = (u16*)(sm2 + SOFF_WH_LO);
    char* sAhi = sm2 + SOFF_SA_HI;
    char* sAlo = sm2 + SOFF_SA_LO;
    float* zbuf = (float*)(sm2 + SOFF_ZBUF);

    const int tid = threadIdx.x;
    const int bid = blockIdx.x;
    const int bm = bid >> 4;
    const int bn = bid & 15;
    const int m0 = bm * 32;
    const int j0 = bn * 32;

    // ---- one-time weight conversion to smem bf16 hi/lo, n-major ----
    for (int idx = tid; idx < 4096; idx += 256) {
        const int k  = idx >> 3;
        const int c4 = (idx & 7) * 4;
        float4 vz = *(const float4*)&w_hz[(size_t)k * HID_ + j0 + c4];
        float4 vr = *(const float4*)&w_hr[(size_t)k * HID_ + j0 + c4];
        float4 vh = *(const float4*)&w_hh[(size_t)k * HID_ + j0 + c4];
        float az[4] = {vz.x, vz.y, vz.z, vz.w};
        float ar[4] = {vr.x, vr.y, vr.z, vr.w};
        float ah[4] = {vh.x, vh.y, vh.z, vh.w};
        #pragma unroll
        for (int i = 0; i < 4; i++) {
            u16 hh, ll;
            bsplit(az[i], hh, ll);
            wZRhi[(c4 + i) * WPITCH + k] = hh; wZRlo[(c4 + i) * WPITCH + k] = ll;
            bsplit(ar[i], hh, ll);
            wZRhi[(32 + c4 + i) * WPITCH + k] = hh; wZRlo[(32 + c4 + i) * WPITCH + k] = ll;
            bsplit(ah[i], hh, ll);
            wHhi[(c4 + i) * WPITCH + k] = hh; wHlo[(c4 + i) * WPITCH + k] = ll;
        }
    }

    __shared__ unsigned s_base;
    if (tid == 0) s_base = *(volatile unsigned*)&g_flags[bid * 32];
    __syncthreads();
    const unsigned base = s_base;
    unsigned nbar = 0;

    const int wid = tid >> 5, lane = tid & 31;
    const int g   = lane >> 2;
    const int tig = lane & 3;
    const int wm  = wid >> 2;          // 0..1
    const int wn  = wid & 3;           // 0..3
    const int rA  = wm * 16 + g;       // A-frag base row (local)
    const bool is_z = (wn < 2);
    const int c32b = (wn & 1) * 16;    // phase A col base within 32 (mod gate)

    // staging slots: per image, thread handles slots tid and tid+256
    const int srow0 = tid >> 4, sq0 = tid & 15;
    const int srow1 = (tid + 256) >> 4, sq1 = (tid + 256) & 15;

    for (int t = 0; t < T_; t++) {
        const int pp = t & 1;
        const float* __restrict__ hprev = g_h[pp];
        float* __restrict__ hnext = g_h[pp ^ 1];
        const u16* __restrict__ hbh = g_hbf_hi[pp];
        const u16* __restrict__ hbl = g_hbf_lo[pp];

        // ---- phase A epilogue prefetch ----
        const int goff = is_z ? 0 : 512;
        float2 pvA[2][2], hvA[2][2];
        #pragma unroll
        for (int i = 0; i < 2; i++) {
            const int rl = rA + 8 * i;
            const size_t prow = ((size_t)(m0 + rl) * T_ + t) * 1536;
            #pragma unroll
            for (int s = 0; s < 2; s++) {
                const int c = c32b + s * 8 + tig * 2;
                pvA[i][s] = *(const float2*)&g_pre[prow + goff + j0 + c];
                if (!is_z)
                    hvA[i][s] = *(const float2*)&hprev[(size_t)(m0 + rl) * HID_ + j0 + c];
            }
        }

        // ================= phase A GEMM =================
        float accA[2][4];
        #pragma unroll
        for (int s = 0; s < 2; s++)
            #pragma unroll
            for (int e = 0; e < 4; e++) accA[s][e] = 0.0f;

        uint4 pfh0 = *(const uint4*)&hbh[(size_t)(m0 + srow0) * HID_ + sq0 * 8];
        uint4 pfh1 = *(const uint4*)&hbh[(size_t)(m0 + srow1) * HID_ + sq1 * 8];
        uint4 pfl0 = *(const uint4*)&hbl[(size_t)(m0 + srow0) * HID_ + sq0 * 8];
        uint4 pfl1 = *(const uint4*)&hbl[(size_t)(m0 + srow1) * HID_ + sq1 * 8];

        for (int kc = 0; kc < 4; kc++) {
            __syncthreads();
            *(uint4*)(sAhi + srow0 * APITCH + sq0 * 16) = pfh0;
            *(uint4*)(sAhi + srow1 * APITCH + sq1 * 16) = pfh1;
            *(uint4*)(sAlo + srow0 * APITCH + sq0 * 16) = pfl0;
            *(uint4*)(sAlo + srow1 * APITCH + sq1 * 16) = pfl1;
            __syncthreads();
            if (kc < 3) {
                const int kb = (kc + 1) * 128;
                pfh0 = *(const uint4*)&hbh[(size_t)(m0 + srow0) * HID_ + kb + sq0 * 8];
                pfh1 = *(const uint4*)&hbh[(size_t)(m0 + srow1) * HID_ + kb + sq1 * 8];
                pfl0 = *(const uint4*)&hbl[(size_t)(m0 + srow0) * HID_ + kb + sq0 * 8];
                pfl1 = *(const uint4*)&hbl[(size_t)(m0 + srow1) * HID_ + kb + sq1 * 8];
            }
            #pragma unroll
            for (int kk = 0; kk < 8; kk++) {
                const int ab = rA * APITCH + kk * 32 + tig * 4;
                u32 ah[4], al[4];
                ah[0] = *(const u32*)(sAhi + ab);
                ah[1] = *(const u32*)(sAhi + ab + 8 * APITCH);
                ah[2] = *(const u32*)(sAhi + ab + 16);
                ah[3] = *(const u32*)(sAhi + ab + 8 * APITCH + 16);
                al[0] = *(const u32*)(sAlo + ab);
                al[1] = *(const u32*)(sAlo + ab + 8 * APITCH);
                al[2] = *(const u32*)(sAlo + ab + 16);
                al[3] = *(const u32*)(sAlo + ab + 8 * APITCH + 16);
                #pragma unroll
                for (int s = 0; s < 2; s++) {
                    const int col = wn * 16 + s * 8 + g;
                    const int bb = col * WPITCH + kc * 128 + kk * 16 + tig * 2;
                    u32 bh2[2], bl2[2];
                    bh2[0] = *(const u32*)&wZRhi[bb];
                    bh2[1] = *(const u32*)&wZRhi[bb + 8];
                    bl2[0] = *(const u32*)&wZRlo[bb];
                    bl2[1] = *(const u32*)&wZRlo[bb + 8];
                    MMA16816(accA[s], ah, bh2);
                    MMA16816(accA[s], ah, bl2);
                    MMA16816(accA[s], al, bh2);
                }
            }
        }

        // ---- phase A epilogue ----
        if (is_z) {
            #pragma unroll
            for (int i = 0; i < 2; i++) {
                const int rl = rA + 8 * i;
                #pragma unroll
                for (int s = 0; s < 2; s++) {
                    const int c = c32b + s * 8 + tig * 2;
                    zbuf[rl * 33 + c]     = sigmoidf_(pvA[i][s].x + accA[s][2 * i]);
                    zbuf[rl * 33 + c + 1] = sigmoidf_(pvA[i][s].y + accA[s][2 * i + 1]);
                }
            }
        } else {
            #pragma unroll
            for (int i = 0; i < 2; i++) {
                const int rl = rA + 8 * i;
                #pragma unroll
                for (int s = 0; s < 2; s++) {
                    const int c = c32b + s * 8 + tig * 2;
                    const float r0 = sigmoidf_(pvA[i][s].x + accA[s][2 * i]);
                    const float r1 = sigmoidf_(pvA[i][s].y + accA[s][2 * i + 1]);
                    const float rh0 = r0 * hvA[i][s].x;
                    const float rh1 = r1 * hvA[i][s].y;
                    u16 h0b, l0b, h1b, l1b;
                    bsplit(rh0, h0b, l0b);
                    bsplit(rh1, h1b, l1b);
                    const size_t gi = (size_t)(m0 + rl) * HID_ + j0 + c;
                    *(u32*)&g_rhbf_hi[gi] = (u32)h0b | ((u32)h1b << 16);
                    *(u32*)&g_rhbf_lo[gi] = (u32)l0b | ((u32)l1b << 16);
                }
            }
        }
        gbar(base + (++nbar));

        // ---- phase B epilogue prefetch ----
        const int cB = wn * 8 + tig * 2;
        float2 phB[2], hoB[2];
        #pragma unroll
        for (int i = 0; i < 2; i++) {
            const int rl = rA + 8 * i;
            const size_t prow = ((size_t)(m0 + rl) * T_ + t) * 1536;
            phB[i] = *(const float2*)&g_pre[prow + 1024 + j0 + cB];
            hoB[i] = *(const float2*)&hprev[(size_t)(m0 + rl) * HID_ + j0 + cB];
        }

        // ================= phase B GEMM =================
        float accB[4] = {0.0f, 0.0f, 0.0f, 0.0f};

        pfh0 = *(const uint4*)&g_rhbf_hi[(size_t)(m0 + srow0) * HID_ + sq0 * 8];
        pfh1 = *(const uint4*)&g_rhbf_hi[(size_t)(m0 + srow1) * HID_ + sq1 * 8];
        pfl0 = *(const uint4*)&g_rhbf_lo[(size_t)(m0 + srow0) * HID_ + sq0 * 8];
        pfl1 = *(const uint4*)&g_rhbf_lo[(size_t)(m0 + srow1) * HID_ + sq1 * 8];

        for (int kc = 0; kc < 4; kc++) {
            __syncthreads();
            *(uint4*)(sAhi + srow0 * APITCH + sq0 * 16) = pfh0;
            *(uint4*)(sAhi + srow1 * APITCH + sq1 * 16) = pfh1;
            *(uint4*)(sAlo + srow0 * APITCH + sq0 * 16) = pfl0;
            *(uint4*)(sAlo + srow1 * APITCH + sq1 * 16) = pfl1;
            __syncthreads();
            if (kc < 3) {
                const int kb = (kc + 1) * 128;
                pfh0 = *(const uint4*)&g_rhbf_hi[(size_t)(m0 + srow0) * HID_ + kb + sq0 * 8];
                pfh1 = *(const uint4*)&g_rhbf_hi[(size_t)(m0 + srow1) * HID_ + kb + sq1 * 8];
                pfl0 = *(const uint4*)&g_rhbf_lo[(size_t)(m0 + srow0) * HID_ + kb + sq0 * 8];
                pfl1 = *(const uint4*)&g_rhbf_lo[(size_t)(m0 + srow1) * HID_ + kb + sq1 * 8];
            }
            #pragma unroll
            for (int kk = 0; kk < 8; kk++) {
                const int ab = rA * APITCH + kk * 32 + tig * 4;
                u32 ah[4], al[4];
                ah[0] = *(const u32*)(sAhi + ab);
                ah[1] = *(const u32*)(sAhi + ab + 8 * APITCH);
                ah[2] = *(const u32*)(sAhi + ab + 16);
                ah[3] = *(const u32*)(sAhi + ab + 8 * APITCH + 16);
                al[0] = *(const u32*)(sAlo + ab);
                al[1] = *(const u32*)(sAlo + ab + 8 * APITCH);
                al[2] = *(const u32*)(sAlo + ab + 16);
                al[3] = *(const u32*)(sAlo + ab + 8 * APITCH + 16);
                const int col = wn * 8 + g;
                const int bb = col * WPITCH + kc * 128 + kk * 16 + tig * 2;
                u32 bh2[2], bl2[2];
                bh2[0] = *(const u32*)&wHhi[bb];
                bh2[1] = *(const u32*)&wHhi[bb + 8];
                bl2[0] = *(const u32*)&wHlo[bb];
                bl2[1] = *(const u32*)&wHlo[bb + 8];
                MMA16816(accB, ah, bh2);
                MMA16816(accB, ah, bl2);
                MMA16816(accB, al, bh2);
            }
        }

        // ---- phase B epilogue ----
        #pragma unroll
        for (int i = 0; i < 2; i++) {
            const int rl = rA + 8 * i;
            const float ht0 = tanhf(phB[i].x + accB[2 * i]);
            const float ht1 = tanhf(phB[i].y + accB[2 * i + 1]);
            const float z0 = zbuf[rl * 33 + cB];
            const float z1 = zbuf[rl * 33 + cB + 1];
            const float hn0 = fmaf(z0, ht0 - hoB[i].x, hoB[i].x);
            const float hn1 = fmaf(z1, ht1 - hoB[i].y, hoB[i].y);
            const size_t gi = (size_t)(m0 + rl) * HID_ + j0 + cB;
            *(float2*)&hnext[gi] = make_float2(hn0, hn1);
            u16 hh0, ll0, hh1, ll1;
            bsplit(hn0, hh0, ll0);
            bsplit(hn1, hh1, ll1);
            *(u32*)&g_hbf_hi[pp ^ 1][gi] = (u32)hh0 | ((u32)hh1 << 16);
            *(u32*)&g_hbf_lo[pp ^ 1][gi] = (u32)ll0 | ((u32)ll1 << 16);
            *(float2*)&hs_out[((size_t)(m0 + rl) * T_ + t) * HID_ + j0 + cB] =
                make_float2(hn0, hn1);
        }
        if (t < T_ - 1) gbar(base + (++nbar));
    }
}

// =====================================================================================
// out = relu(h_last @ w_out + b_out)  (unchanged)
// =====================================================================================
__global__ __launch_bounds__(256) void out_kernel(
    const float* __restrict__ w_out, const float* __restrict__ b_out,
    float* __restrict__ out)
{
    __shared__ __align__(16) float As[32][36];
    __shared__ __align__(16) float Bs[32][36];

    const float* __restrict__ hlast = g_h[0];

    const int tid = threadIdx.x;
    const int m0 = blockIdx.y * 32;
    const int n0 = blockIdx.x * 32;

    const int ttr = tid >> 4;
    const int ttc = tid & 15;
    const int arow = tid >> 3;
    const int akq  = tid & 7;
    const int bkr  = tid >> 3;
    const int bnq  = tid & 7;

    u64 acc[2][2];
    #pragma unroll
    for (int i = 0; i < 2; i++)
        #pragma unroll
        for (int p = 0; p < 2; p++) acc[i][p] = 0ull;

    for (int k0 = 0; k0 < HID_; k0 += 32) {
        float4 av = *(const float4*)&hlast[(size_t)(m0 + arow) * HID_ + k0 + akq * 4];
        float4 bv = *(const float4*)&w_out[(size_t)(k0 + bkr) * OUT_ + n0 + bnq * 4];

        __syncthreads();
        *(float4*)&As[arow][akq * 4] = av;
        Bs[bnq * 4 + 0][bkr] = bv.x; Bs[bnq * 4 + 1][bkr] = bv.y;
        Bs[bnq * 4 + 2][bkr] = bv.z; Bs[bnq * 4 + 3][bkr] = bv.w;
        __syncthreads();

        #pragma unroll
        for (int q = 0; q < 8; q++) {
            ulonglong2 a0 = *(const ulonglong2*)&As[ttr * 2 + 0][q * 4];
            ulonglong2 a1 = *(const ulonglong2*)&As[ttr * 2 + 1][q * 4];
            #pragma unroll
            for (int p = 0; p < 2; p++) {
                ulonglong2 bb = *(const ulonglong2*)&Bs[ttc + 16 * p][q * 4];
                f2fma(acc[0][p], a0.x, bb.x); f2fma(acc[0][p], a0.y, bb.y);
                f2fma(acc[1][p], a1.x, bb.x); f2fma(acc[1][p], a1.y, bb.y);
            }
        }
    }

    #pragma unroll
    for (int i = 0; i < 2; i++) {
        const int b = m0 + ttr * 2 + i;
        #pragma unroll
        for (int p = 0; p < 2; p++) {
            const int j = n0 + ttc + 16 * p;
            const float s = f2sum(acc[i][p]) + b_out[j];
            out[(size_t)b * OUT_ + j] = fmaxf(s, 0.0f);
        }
    }
}

// =====================================================================================
extern "C" void kernel_launch(void* const* d_in, const int* in_sizes, int n_in,
                              void* d_out, int out_size)
{
    const float* x     = (const float*)d_in[0];
    const float* c     = (const float*)d_in[1];
    const float* h0    = (const float*)d_in[2];
    const float* w_xr  = (const float*)d_in[3];
    const float* w_hr  = (const float*)d_in[4];
    const float* w_cr  = (const float*)d_in[5];
    const float* w_xz  = (const float*)d_in[6];
    const float* w_hz  = (const float*)d_in[7];
    const float* w_cz  = (const float*)d_in[8];
    const float* w_xh  = (const float*)d_in[9];
    const float* w_hh  = (const float*)d_in[10];
    const float* w_ch  = (const float*)d_in[11];
    const float* b_r   = (const float*)d_in[12];
    const float* b_z   = (const float*)d_in[13];
    const float* b_h   = (const float*)d_in[14];
    const float* w_out = (const float*)d_in[15];
    const float* b_out = (const float*)d_in[16];

    float* out = (float*)d_out;
    float* hs  = out + (size_t)B_ * OUT_;

    static int attr_set = 0;
    if (!attr_set) {
        cudaFuncSetAttribute(scan_mma_kernel, cudaFuncAttributeMaxDynamicSharedMemorySize,
                             SC2_SMEM);
        cudaFuncSetAttribute(pre_mma_kernel, cudaFuncAttributeMaxDynamicSharedMemorySize,
                             PM_SMEM);
        attr_set = 1;
    }

    init_h_kernel<<<512, 256>>>(h0);
    convertA_kernel<<<32768, 256>>>(x, c);
    convertB_kernel<<<768, 256>>>(w_xz, w_xr, w_xh, w_cz, w_cr, w_ch);
    pre_mma_kernel<<<dim3(12, 512), 256, PM_SMEM>>>(b_z, b_r, b_h);

    scan_mma_kernel<<<NBLK, 256, SC2_SMEM>>>(w_hz, w_hr, w_hh, hs);

    out_kernel<<<dim3(8, 8), 256>>>(w_out, b_out, out);
}

// round 12
// speedup vs baseline: 2.4401x; 1.0252x over previous
#include <cuda_runtime.h>
#include <cuda_bf16.h>
#include <math.h>

#define B_   256
#define T_   256
#define IN_  256
#define HID_ 512
#define OUT_ 256
#define NBLK 128

typedef unsigned long long u64;
typedef unsigned int u32;
typedef unsigned short u16;

// ---------- packed f32x2 FMA (out kernel) ----------
__device__ __forceinline__ void f2fma(u64 &d, u64 a, u64 b) {
    asm("fma.rn.f32x2 %0, %1, %2, %0;" : "+l"(d) : "l"(a), "l"(b));
}
__device__ __forceinline__ float f2sum(u64 v) {
    unsigned lo, hi;
    asm("mov.b64 {%0, %1}, %2;" : "=r"(lo), "=r"(hi) : "l"(v));
    return __uint_as_float(lo) + __uint_as_float(hi);
}
__device__ __forceinline__ float sigmoidf_(float x) { return 1.0f / (1.0f + expf(-x)); }

// ---------- warp mma.sync m16n8k16 bf16 ----------
#define MMA16816(d, a, b) \
    asm volatile("mma.sync.aligned.m16n8k16.row.col.f32.bf16.bf16.f32 " \
        "{%0,%1,%2,%3}, {%4,%5,%6,%7}, {%8,%9}, {%0,%1,%2,%3};" \
        : "+f"((d)[0]), "+f"((d)[1]), "+f"((d)[2]), "+f"((d)[3]) \
        : "r"((a)[0]), "r"((a)[1]), "r"((a)[2]), "r"((a)[3]), \
          "r"((b)[0]), "r"((b)[1]))

__device__ __forceinline__ void bsplit(float v, u16 &hi, u16 &lo) {
    __nv_bfloat16 h = __float2bfloat16(v);
    __nv_bfloat16 l = __float2bfloat16(v - __bfloat162float(h));
    hi = __bfloat16_as_ushort(h);
    lo = __bfloat16_as_ushort(l);
}

// ---------- device scratch ----------
__device__ float g_pre[(size_t)B_ * T_ * 3 * HID_];
__device__ float g_h[2][B_ * HID_];
__device__ unsigned g_flags[NBLK * 32];
// bf16 hi/lo state images for scan GEMMs
__device__ __align__(16) u16 g_hbf_hi[2][B_ * HID_];
__device__ __align__(16) u16 g_hbf_lo[2][B_ * HID_];
__device__ __align__(16) u16 g_rhbf_hi[B_ * HID_];
__device__ __align__(16) u16 g_rhbf_lo[B_ * HID_];
// pre-GEMM bf16 images
__device__ __align__(16) u16 g_Ahi[(size_t)65536 * 512];
__device__ __align__(16) u16 g_Alo[(size_t)65536 * 512];
__device__ __align__(16) u16 g_Bhi[3 * 512 * 512];
__device__ __align__(16) u16 g_Blo[3 * 512 * 512];

// =====================================================================================
// Convert A: [x|c] fp32 -> bf16 hi/lo row-major [m][512]   (unchanged)
// =====================================================================================
__global__ __launch_bounds__(256) void convertA_kernel(
    const float* __restrict__ x, const float* __restrict__ c)
{
    const size_t idx = (size_t)blockIdx.x * 256 + threadIdx.x;
    const int m  = (int)(idx >> 7);
    const int kq = ((int)idx & 127) << 2;
    const float* src = (kq < 256) ? &x[(size_t)m * 256 + kq]
                                  : &c[(size_t)m * 256 + (kq - 256)];
    float4 v = *(const float4*)src;
    float vv[4] = {v.x, v.y, v.z, v.w};
    unsigned h[4], l[4];
    #pragma unroll
    for (int i = 0; i < 4; i++) {
        u16 hh, ll; bsplit(vv[i], hh, ll);
        h[i] = hh; l[i] = ll;
    }
    const size_t base = (size_t)m * 512 + kq;
    *(uint2*)&g_Ahi[base] = make_uint2(h[0] | (h[1] << 16), h[2] | (h[3] << 16));
    *(uint2*)&g_Alo[base] = make_uint2(l[0] | (l[1] << 16), l[2] | (l[3] << 16));
}

// =====================================================================================
// Convert B (pre weights)  (unchanged)
// =====================================================================================
__global__ __launch_bounds__(256) void convertB_kernel(
    const float* __restrict__ wxz, const float* __restrict__ wxr, const float* __restrict__ wxh,
    const float* __restrict__ wcz, const float* __restrict__ wcr, const float* __restrict__ wch)
{
    const int idx = blockIdx.x * 256 + threadIdx.x;
    const int gate = idx >> 16;
    const int rem  = idx & 65535;
    const int k  = rem >> 7;
    const int nq = (rem & 127) << 2;
    const float* wx = (gate == 0) ? wxz : (gate == 1) ? wxr : wxh;
    const float* wc = (gate == 0) ? wcz : (gate == 1) ? wcr : wch;
    const float* src = (k < 256) ? &wx[(size_t)k * 512 + nq]
                                 : &wc[(size_t)(k - 256) * 512 + nq];
    float4 v = *(const float4*)src;
    float vv[4] = {v.x, v.y, v.z, v.w};
    #pragma unroll
    for (int i = 0; i < 4; i++) {
        u16 hh, ll; bsplit(vv[i], hh, ll);
        const size_t dst = ((size_t)(gate * 512 + nq + i)) * 512 + k;
        g_Bhi[dst] = hh;
        g_Blo[dst] = ll;
    }
}

// =====================================================================================
// init h0: fp32 copy + bf16 hi/lo images  (unchanged)
// =====================================================================================
__global__ __launch_bounds__(256) void init_h_kernel(const float* __restrict__ h0)
{
    const int idx = blockIdx.x * 256 + threadIdx.x;
    float v = h0[idx];
    g_h[0][idx] = v;
    u16 hh, ll; bsplit(v, hh, ll);
    g_hbf_hi[0][idx] = hh;
    g_hbf_lo[0][idx] = ll;
}

// =====================================================================================
// PRE via mma.sync  (unchanged)
// =====================================================================================
#define PMA_PITCH 144
#define PMA_IMG   (128 * PMA_PITCH)
#define PM_SMEM   (4 * PMA_IMG)

__global__ __launch_bounds__(256) void pre_mma_kernel(
    const float* __restrict__ bz, const float* __restrict__ br, const float* __restrict__ bh)
{
    extern __shared__ __align__(16) char psm[];
    char* sAhi = psm;
    char* sAlo = psm + PMA_IMG;
    char* sBhi = psm + 2 * PMA_IMG;
    char* sBlo = psm + 3 * PMA_IMG;

    const int tid = threadIdx.x;
    const int wid = tid >> 5, lane = tid & 31;
    const int g   = lane >> 2;
    const int tig = lane & 3;

    const int ntg   = blockIdx.x;
    const int mtile = blockIdx.y;
    const int gate  = ntg >> 2;
    const int n0    = (ntg & 3) * 128;

    const int wm = wid >> 2;
    const int wn = wid & 3;

    float acc[4][4][4];
    #pragma unroll
    for (int mi = 0; mi < 4; mi++)
        #pragma unroll
        for (int ni = 0; ni < 4; ni++)
            #pragma unroll
            for (int e = 0; e < 4; e++) acc[mi][ni][e] = 0.0f;

    for (int kc = 0; kc < 8; kc++) {
        __syncthreads();
        #pragma unroll
        for (int i = 0; i < 4; i++) {
            const int lin = tid + 256 * i;
            const int row = lin >> 3, q = lin & 7;
            const size_t asrc = ((size_t)(mtile * 128 + row)) * 512 + kc * 64 + q * 8;
            const size_t bsrc = ((size_t)(gate * 512 + n0 + row)) * 512 + kc * 64 + q * 8;
            *(uint4*)(sAhi + row * PMA_PITCH + q * 16) = *(const uint4*)&g_Ahi[asrc];
            *(uint4*)(sAlo + row * PMA_PITCH + q * 16) = *(const uint4*)&g_Alo[asrc];
            *(uint4*)(sBhi + row * PMA_PITCH + q * 16) = *(const uint4*)&g_Bhi[bsrc];
            *(uint4*)(sBlo + row * PMA_PITCH + q * 16) = *(const uint4*)&g_Blo[bsrc];
        }
        __syncthreads();

        #pragma unroll
        for (int kk = 0; kk < 4; kk++) {
            const int kb = kk * 32 + tig * 4;
            u32 ah[4][4], al[4][4], bhf[4][2], blf[4][2];
            #pragma unroll
            for (int mi = 0; mi < 4; mi++) {
                const int rbase = (wm * 64 + mi * 16 + g) * PMA_PITCH + kb;
                ah[mi][0] = *(const u32*)(sAhi + rbase);
                ah[mi][1] = *(const u32*)(sAhi + rbase + 8 * PMA_PITCH);
                ah[mi][2] = *(const u32*)(sAhi + rbase + 16);
                ah[mi][3] = *(const u32*)(sAhi + rbase + 8 * PMA_PITCH + 16);
                al[mi][0] = *(const u32*)(sAlo + rbase);
                al[mi][1] = *(const u32*)(sAlo + rbase + 8 * PMA_PITCH);
                al[mi][2] = *(const u32*)(sAlo + rbase + 16);
                al[mi][3] = *(const u32*)(sAlo + rbase + 8 * PMA_PITCH + 16);
            }
            #pragma unroll
            for (int ni = 0; ni < 4; ni++) {
                const int nbase = (wn * 32 + ni * 8 + g) * PMA_PITCH + kb;
                bhf[ni][0] = *(const u32*)(sBhi + nbase);
                bhf[ni][1] = *(const u32*)(sBhi + nbase + 16);
                blf[ni][0] = *(const u32*)(sBlo + nbase);
                blf[ni][1] = *(const u32*)(sBlo + nbase + 16);
            }
            #pragma unroll
            for (int mi = 0; mi < 4; mi++)
                #pragma unroll
                for (int ni = 0; ni < 4; ni++) {
                    MMA16816(acc[mi][ni], ah[mi], bhf[ni]);
                    MMA16816(acc[mi][ni], ah[mi], blf[ni]);
                    MMA16816(acc[mi][ni], al[mi], bhf[ni]);
                }
        }
    }

    const float* bias = (gate == 0) ? bz : (gate == 1) ? br : bh;
    #pragma unroll
    for (int mi = 0; mi < 4; mi++) {
        const int r0 = mtile * 128 + wm * 64 + mi * 16 + g;
        #pragma unroll
        for (int ni = 0; ni < 4; ni++) {
            const int cl = n0 + wn * 32 + ni * 8 + tig * 2;
            const float b0 = bias[cl], b1 = bias[cl + 1];
            float* d0 = &g_pre[(size_t)r0 * 1536 + gate * 512 + cl];
            float* d1 = &g_pre[(size_t)(r0 + 8) * 1536 + gate * 512 + cl];
            *(float2*)d0 = make_float2(acc[mi][ni][0] + b0, acc[mi][ni][1] + b1);
            *(float2*)d1 = make_float2(acc[mi][ni][2] + b0, acc[mi][ni][3] + b1);
        }
    }
}

// =====================================================================================
// GROUP grid barrier: 8 independent groups of 16 blocks (same bm). Each block has a
// 128B-spaced monotonic flag; arrival = release store; wait = poll the 16 group flags.
// =====================================================================================
__device__ __forceinline__ void gbar_group(unsigned want, int bm)
{
    __syncthreads();
    if (threadIdx.x == 0) {
        asm volatile("st.release.gpu.global.u32 [%0], %1;"
                     :: "l"(&g_flags[blockIdx.x * 32]), "r"(want) : "memory");
    }
    if (threadIdx.x < 16) {
        unsigned v;
        do {
            asm volatile("ld.acquire.gpu.global.u32 %0, [%1];"
                         : "=r"(v) : "l"(&g_flags[(bm * 16 + threadIdx.x) * 32]) : "memory");
        } while ((int)(v - want) < 0);
    }
    __syncthreads();
}

// =====================================================================================
// Tensor-core persistent scan (same compute as R10 kernel; barrier now per-group)
// =====================================================================================
#define WPITCH 520
#define APITCH 272
#define SOFF_WZR_HI 0
#define SOFF_WZR_LO (SOFF_WZR_HI + 64 * WPITCH * 2)
#define SOFF_WH_HI  (SOFF_WZR_LO + 64 * WPITCH * 2)
#define SOFF_WH_LO  (SOFF_WH_HI + 32 * WPITCH * 2)
#define SOFF_SA_HI  (SOFF_WH_LO + 32 * WPITCH * 2)
#define SOFF_SA_LO  (SOFF_SA_HI + 32 * APITCH)
#define SOFF_ZBUF   (SOFF_SA_LO + 32 * APITCH)
#define SC2_SMEM    (SOFF_ZBUF + 32 * 33 * 4)

__global__ __launch_bounds__(256, 1) void scan_mma_kernel(
    const float* __restrict__ w_hz, const float* __restrict__ w_hr,
    const float* __restrict__ w_hh, float* __restrict__ hs_out)
{
    extern __shared__ __align__(16) char sm2[];
    u16* wZRhi = (u16*)(sm2 + SOFF_WZR_HI);
    u16* wZRlo = (u16*)(sm2 + SOFF_WZR_LO);
    u16* wHhi  = (u16*)(sm2 + SOFF_WH_HI);
    u16* wHlo  = (u16*)(sm2 + SOFF_WH_LO);
    char* sAhi = sm2 + SOFF_SA_HI;
    char* sAlo = sm2 + SOFF_SA_LO;
    float* zbuf = (float*)(sm2 + SOFF_ZBUF);

    const int tid = threadIdx.x;
    const int bid = blockIdx.x;
    const int bm = bid >> 4;
    const int bn = bid & 15;
    const int m0 = bm * 32;
    const int j0 = bn * 32;

    // ---- one-time weight conversion to smem bf16 hi/lo, n-major ----
    for (int idx = tid; idx < 4096; idx += 256) {
        const int k  = idx >> 3;
        const int c4 = (idx & 7) * 4;
        float4 vz = *(const float4*)&w_hz[(size_t)k * HID_ + j0 + c4];
        float4 vr = *(const float4*)&w_hr[(size_t)k * HID_ + j0 + c4];
        float4 vh = *(const float4*)&w_hh[(size_t)k * HID_ + j0 + c4];
        float az[4] = {vz.x, vz.y, vz.z, vz.w};
        float ar[4] = {vr.x, vr.y, vr.z, vr.w};
        float ah[4] = {vh.x, vh.y, vh.z, vh.w};
        #pragma unroll
        for (int i = 0; i < 4; i++) {
            u16 hh, ll;
            bsplit(az[i], hh, ll);
            wZRhi[(c4 + i) * WPITCH + k] = hh; wZRlo[(c4 + i) * WPITCH + k] = ll;
            bsplit(ar[i], hh, ll);
            wZRhi[(32 + c4 + i) * WPITCH + k] = hh; wZRlo[(32 + c4 + i) * WPITCH + k] = ll;
            bsplit(ah[i], hh, ll);
            wHhi[(c4 + i) * WPITCH + k] = hh; wHlo[(c4 + i) * WPITCH + k] = ll;
        }
    }

    __shared__ unsigned s_base;
    if (tid == 0) s_base = *(volatile unsigned*)&g_flags[bid * 32];
    __syncthreads();
    const unsigned base = s_base;
    unsigned nbar = 0;

    const int wid = tid >> 5, lane = tid & 31;
    const int g   = lane >> 2;
    const int tig = lane & 3;
    const int wm  = wid >> 2;
    const int wn  = wid & 3;
    const int rA  = wm * 16 + g;
    const bool is_z = (wn < 2);
    const int c32b = (wn & 1) * 16;

    const int srow0 = tid >> 4, sq0 = tid & 15;
    const int srow1 = (tid + 256) >> 4, sq1 = (tid + 256) & 15;

    for (int t = 0; t < T_; t++) {
        const int pp = t & 1;
        const float* __restrict__ hprev = g_h[pp];
        float* __restrict__ hnext = g_h[pp ^ 1];
        const u16* __restrict__ hbh = g_hbf_hi[pp];
        const u16* __restrict__ hbl = g_hbf_lo[pp];

        // ---- phase A epilogue prefetch ----
        const int goff = is_z ? 0 : 512;
        float2 pvA[2][2], hvA[2][2];
        #pragma unroll
        for (int i = 0; i < 2; i++) {
            const int rl = rA + 8 * i;
            const size_t prow = ((size_t)(m0 + rl) * T_ + t) * 1536;
            #pragma unroll
            for (int s = 0; s < 2; s++) {
                const int c = c32b + s * 8 + tig * 2;
                pvA[i][s] = *(const float2*)&g_pre[prow + goff + j0 + c];
                if (!is_z)
                    hvA[i][s] = *(const float2*)&hprev[(size_t)(m0 + rl) * HID_ + j0 + c];
            }
        }

        // ================= phase A GEMM =================
        float accA[2][4];
        #pragma unroll
        for (int s = 0; s < 2; s++)
            #pragma unroll
            for (int e = 0; e < 4; e++) accA[s][e] = 0.0f;

        uint4 pfh0 = *(const uint4*)&hbh[(size_t)(m0 + srow0) * HID_ + sq0 * 8];
        uint4 pfh1 = *(const uint4*)&hbh[(size_t)(m0 + srow1) * HID_ + sq1 * 8];
        uint4 pfl0 = *(const uint4*)&hbl[(size_t)(m0 + srow0) * HID_ + sq0 * 8];
        uint4 pfl1 = *(const uint4*)&hbl[(size_t)(m0 + srow1) * HID_ + sq1 * 8];

        for (int kc = 0; kc < 4; kc++) {
            __syncthreads();
            *(uint4*)(sAhi + srow0 * APITCH + sq0 * 16) = pfh0;
            *(uint4*)(sAhi + srow1 * APITCH + sq1 * 16) = pfh1;
            *(uint4*)(sAlo + srow0 * APITCH + sq0 * 16) = pfl0;
            *(uint4*)(sAlo + srow1 * APITCH + sq1 * 16) = pfl1;
            __syncthreads();
            if (kc < 3) {
                const int kb = (kc + 1) * 128;
                pfh0 = *(const uint4*)&hbh[(size_t)(m0 + srow0) * HID_ + kb + sq0 * 8];
                pfh1 = *(const uint4*)&hbh[(size_t)(m0 + srow1) * HID_ + kb + sq1 * 8];
                pfl0 = *(const uint4*)&hbl[(size_t)(m0 + srow0) * HID_ + kb + sq0 * 8];
                pfl1 = *(const uint4*)&hbl[(size_t)(m0 + srow1) * HID_ + kb + sq1 * 8];
            }
            #pragma unroll
            for (int kk = 0; kk < 8; kk++) {
                const int ab = rA * APITCH + kk * 32 + tig * 4;
                u32 ah[4], al[4];
                ah[0] = *(const u32*)(sAhi + ab);
                ah[1] = *(const u32*)(sAhi + ab + 8 * APITCH);
                ah[2] = *(const u32*)(sAhi + ab + 16);
                ah[3] = *(const u32*)(sAhi + ab + 8 * APITCH + 16);
                al[0] = *(const u32*)(sAlo + ab);
                al[1] = *(const u32*)(sAlo + ab + 8 * APITCH);
                al[2] = *(const u32*)(sAlo + ab + 16);
                al[3] = *(const u32*)(sAlo + ab + 8 * APITCH + 16);
                #pragma unroll
                for (int s = 0; s < 2; s++) {
                    const int col = wn * 16 + s * 8 + g;
                    const int bb = col * WPITCH + kc * 128 + kk * 16 + tig * 2;
                    u32 bh2[2], bl2[2];
                    bh2[0] = *(const u32*)&wZRhi[bb];
                    bh2[1] = *(const u32*)&wZRhi[bb + 8];
                    bl2[0] = *(const u32*)&wZRlo[bb];
                    bl2[1] = *(const u32*)&wZRlo[bb + 8];
                    MMA16816(accA[s], ah, bh2);
                    MMA16816(accA[s], ah, bl2);
                    MMA16816(accA[s], al, bh2);
                }
            }
        }

        // ---- phase A epilogue ----
        if (is_z) {
            #pragma unroll
            for (int i = 0; i < 2; i++) {
                const int rl = rA + 8 * i;
                #pragma unroll
                for (int s = 0; s < 2; s++) {
                    const int c = c32b + s * 8 + tig * 2;
                    zbuf[rl * 33 + c]     = sigmoidf_(pvA[i][s].x + accA[s][2 * i]);
                    zbuf[rl * 33 + c + 1] = sigmoidf_(pvA[i][s].y + accA[s][2 * i + 1]);
                }
            }
        } else {
            #pragma unroll
            for (int i = 0; i < 2; i++) {
                const int rl = rA + 8 * i;
                #pragma unroll
                for (int s = 0; s < 2; s++) {
                    const int c = c32b + s * 8 + tig * 2;
                    const float r0 = sigmoidf_(pvA[i][s].x + accA[s][2 * i]);
                    const float r1 = sigmoidf_(pvA[i][s].y + accA[s][2 * i + 1]);
                    const float rh0 = r0 * hvA[i][s].x;
                    const float rh1 = r1 * hvA[i][s].y;
                    u16 h0b, l0b, h1b, l1b;
                    bsplit(rh0, h0b, l0b);
                    bsplit(rh1, h1b, l1b);
                    const size_t gi = (size_t)(m0 + rl) * HID_ + j0 + c;
                    *(u32*)&g_rhbf_hi[gi] = (u32)h0b | ((u32)h1b << 16);
                    *(u32*)&g_rhbf_lo[gi] = (u32)l0b | ((u32)l1b << 16);
                }
            }
        }
        gbar_group(base + (++nbar), bm);

        // ---- phase B epilogue prefetch ----
        const int cB = wn * 8 + tig * 2;
        float2 phB[2], hoB[2];
        #pragma unroll
        for (int i = 0; i < 2; i++) {
            const int rl = rA + 8 * i;
            const size_t prow = ((size_t)(m0 + rl) * T_ + t) * 1536;
            phB[i] = *(const float2*)&g_pre[prow + 1024 + j0 + cB];
            hoB[i] = *(const float2*)&hprev[(size_t)(m0 + rl) * HID_ + j0 + cB];
        }

        // ================= phase B GEMM =================
        float accB[4] = {0.0f, 0.0f, 0.0f, 0.0f};

        pfh0 = *(const uint4*)&g_rhbf_hi[(size_t)(m0 + srow0) * HID_ + sq0 * 8];
        pfh1 = *(const uint4*)&g_rhbf_hi[(size_t)(m0 + srow1) * HID_ + sq1 * 8];
        pfl0 = *(const uint4*)&g_rhbf_lo[(size_t)(m0 + srow0) * HID_ + sq0 * 8];
        pfl1 = *(const uint4*)&g_rhbf_lo[(size_t)(m0 + srow1) * HID_ + sq1 * 8];

        for (int kc = 0; kc < 4; kc++) {
            __syncthreads();
            *(uint4*)(sAhi + srow0 * APITCH + sq0 * 16) = pfh0;
            *(uint4*)(sAhi + srow1 * APITCH + sq1 * 16) = pfh1;
            *(uint4*)(sAlo + srow0 * APITCH + sq0 * 16) = pfl0;
            *(uint4*)(sAlo + srow1 * APITCH + sq1 * 16) = pfl1;
            __syncthreads();
            if (kc < 3) {
                const int kb = (kc + 1) * 128;
                pfh0 = *(const uint4*)&g_rhbf_hi[(size_t)(m0 + srow0) * HID_ + kb + sq0 * 8];
                pfh1 = *(const uint4*)&g_rhbf_hi[(size_t)(m0 + srow1) * HID_ + kb + sq1 * 8];
                pfl0 = *(const uint4*)&g_rhbf_lo[(size_t)(m0 + srow0) * HID_ + kb + sq0 * 8];
                pfl1 = *(const uint4*)&g_rhbf_lo[(size_t)(m0 + srow1) * HID_ + kb + sq1 * 8];
            }
            #pragma unroll
            for (int kk = 0; kk < 8; kk++) {
                const int ab = rA * APITCH + kk * 32 + tig * 4;
                u32 ah[4], al[4];
                ah[0] = *(const u32*)(sAhi + ab);
                ah[1] = *(const u32*)(sAhi + ab + 8 * APITCH);
                ah[2] = *(const u32*)(sAhi + ab + 16);
                ah[3] = *(const u32*)(sAhi + ab + 8 * APITCH + 16);
                al[0] = *(const u32*)(sAlo + ab);
                al[1] = *(const u32*)(sAlo + ab + 8 * APITCH);
                al[2] = *(const u32*)(sAlo + ab + 16);
                al[3] = *(const u32*)(sAlo + ab + 8 * APITCH + 16);
                const int col = wn * 8 + g;
                const int bb = col * WPITCH + kc * 128 + kk * 16 + tig * 2;
                u32 bh2[2], bl2[2];
                bh2[0] = *(const u32*)&wHhi[bb];
                bh2[1] = *(const u32*)&wHhi[bb + 8];
                bl2[0] = *(const u32*)&wHlo[bb];
                bl2[1] = *(const u32*)&wHlo[bb + 8];
                MMA16816(accB, ah, bh2);
                MMA16816(accB, ah, bl2);
                MMA16816(accB, al, bh2);
            }
        }

        // ---- phase B epilogue ----
        #pragma unroll
        for (int i = 0; i < 2; i++) {
            const int rl = rA + 8 * i;
            const float ht0 = tanhf(phB[i].x + accB[2 * i]);
            const float ht1 = tanhf(phB[i].y + accB[2 * i + 1]);
            const float z0 = zbuf[rl * 33 + cB];
            const float z1 = zbuf[rl * 33 + cB + 1];
            const float hn0 = fmaf(z0, ht0 - hoB[i].x, hoB[i].x);
            const float hn1 = fmaf(z1, ht1 - hoB[i].y, hoB[i].y);
            const size_t gi = (size_t)(m0 + rl) * HID_ + j0 + cB;
            *(float2*)&hnext[gi] = make_float2(hn0, hn1);
            u16 hh0, ll0, hh1, ll1;
            bsplit(hn0, hh0, ll0);
            bsplit(hn1, hh1, ll1);
            *(u32*)&g_hbf_hi[pp ^ 1][gi] = (u32)hh0 | ((u32)hh1 << 16);
            *(u32*)&g_hbf_lo[pp ^ 1][gi] = (u32)ll0 | ((u32)ll1 << 16);
            *(float2*)&hs_out[((size_t)(m0 + rl) * T_ + t) * HID_ + j0 + cB] =
                make_float2(hn0, hn1);
        }
        if (t < T_ - 1) gbar_group(base + (++nbar), bm);
    }
}

// =====================================================================================
// out = relu(h_last @ w_out + b_out)  (unchanged)
// =====================================================================================
__global__ __launch_bounds__(256) void out_kernel(
    const float* __restrict__ w_out, const float* __restrict__ b_out,
    float* __restrict__ out)
{
    __shared__ __align__(16) float As[32][36];
    __shared__ __align__(16) float Bs[32][36];

    const float* __restrict__ hlast = g_h[0];

    const int tid = threadIdx.x;
    const int m0 = blockIdx.y * 32;
    const int n0 = blockIdx.x * 32;

    const int ttr = tid >> 4;
    const int ttc = tid & 15;
    const int arow = tid >> 3;
    const int akq  = tid & 7;
    const int bkr  = tid >> 3;
    const int bnq  = tid & 7;

    u64 acc[2][2];
    #pragma unroll
    for (int i = 0; i < 2; i++)
        #pragma unroll
        for (int p = 0; p < 2; p++) acc[i][p] = 0ull;

    for (int k0 = 0; k0 < HID_; k0 += 32) {
        float4 av = *(const float4*)&hlast[(size_t)(m0 + arow) * HID_ + k0 + akq * 4];
        float4 bv = *(const float4*)&w_out[(size_t)(k0 + bkr) * OUT_ + n0 + bnq * 4];

        __syncthreads();
        *(float4*)&As[arow][akq * 4] = av;
        Bs[bnq * 4 + 0][bkr] = bv.x; Bs[bnq * 4 + 1][bkr] = bv.y;
        Bs[bnq * 4 + 2][bkr] = bv.z; Bs[bnq * 4 + 3][bkr] = bv.w;
        __syncthreads();

        #pragma unroll
        for (int q = 0; q < 8; q++) {
            ulonglong2 a0 = *(const ulonglong2*)&As[ttr * 2 + 0][q * 4];
            ulonglong2 a1 = *(const ulonglong2*)&As[ttr * 2 + 1][q * 4];
            #pragma unroll
            for (int p = 0; p < 2; p++) {
                ulonglong2 bb = *(const ulonglong2*)&Bs[ttc + 16 * p][q * 4];
                f2fma(acc[0][p], a0.x, bb.x); f2fma(acc[0][p], a0.y, bb.y);
                f2fma(acc[1][p], a1.x, bb.x); f2fma(acc[1][p], a1.y, bb.y);
            }
        }
    }

    #pragma unroll
    for (int i = 0; i < 2; i++) {
        const int b = m0 + ttr * 2 + i;
        #pragma unroll
        for (int p = 0; p < 2; p++) {
            const int j = n0 + ttc + 16 * p;
            const float s = f2sum(acc[i][p]) + b_out[j];
            out[(size_t)b * OUT_ + j] = fmaxf(s, 0.0f);
        }
    }
}

// =====================================================================================
extern "C" void kernel_launch(void* const* d_in, const int* in_sizes, int n_in,
                              void* d_out, int out_size)
{
    const float* x     = (const float*)d_in[0];
    const float* c     = (const float*)d_in[1];
    const float* h0    = (const float*)d_in[2];
    const float* w_xr  = (const float*)d_in[3];
    const float* w_hr  = (const float*)d_in[4];
    const float* w_cr  = (const float*)d_in[5];
    const float* w_xz  = (const float*)d_in[6];
    const float* w_hz  = (const float*)d_in[7];
    const float* w_cz  = (const float*)d_in[8];
    const float* w_xh  = (const float*)d_in[9];
    const float* w_hh  = (const float*)d_in[10];
    const float* w_ch  = (const float*)d_in[11];
    const float* b_r   = (const float*)d_in[12];
    const float* b_z   = (const float*)d_in[13];
    const float* b_h   = (const float*)d_in[14];
    const float* w_out = (const float*)d_in[15];
    const float* b_out = (const float*)d_in[16];

    float* out = (float*)d_out;
    float* hs  = out + (size_t)B_ * OUT_;

    static int attr_set = 0;
    if (!attr_set) {
        cudaFuncSetAttribute(scan_mma_kernel, cudaFuncAttributeMaxDynamicSharedMemorySize,
                             SC2_SMEM);
        cudaFuncSetAttribute(pre_mma_kernel, cudaFuncAttributeMaxDynamicSharedMemorySize,
                             PM_SMEM);
        attr_set = 1;
    }

    init_h_kernel<<<512, 256>>>(h0);
    convertA_kernel<<<32768, 256>>>(x, c);
    convertB_kernel<<<768, 256>>>(w_xz, w_xr, w_xh, w_cz, w_cr, w_ch);
    pre_mma_kernel<<<dim3(12, 512), 256, PM_SMEM>>>(b_z, b_r, b_h);

    scan_mma_kernel<<<NBLK, 256, SC2_SMEM>>>(w_hz, w_hr, w_hh, hs);

    out_kernel<<<dim3(8, 8), 256>>>(w_out, b_out, out);
}

// round 14
// speedup vs baseline: 3.5909x; 1.4716x over previous
#include <cuda_runtime.h>
#include <cuda_fp16.h>
#include <math.h>

#define B_   256
#define T_   256
#define IN_  256
#define HID_ 512
#define OUT_ 256
#define NBLK 128

typedef unsigned long long u64;
typedef unsigned int u32;
typedef unsigned short u16;

// ---------- packed f32x2 FMA (out kernel) ----------
__device__ __forceinline__ void f2fma(u64 &d, u64 a, u64 b) {
    asm("fma.rn.f32x2 %0, %1, %2, %0;" : "+l"(d) : "l"(a), "l"(b));
}
__device__ __forceinline__ float f2sum(u64 v) {
    unsigned lo, hi;
    asm("mov.b64 {%0, %1}, %2;" : "=r"(lo), "=r"(hi) : "l"(v));
    return __uint_as_float(lo) + __uint_as_float(hi);
}
__device__ __forceinline__ float sigmoidf_(float x) { return 1.0f / (1.0f + expf(-x)); }

// ---------- warp mma.sync m16n8k16 fp16 ----------
#define MMAF16(d, a, b) \
    asm volatile("mma.sync.aligned.m16n8k16.row.col.f32.f16.f16.f32 " \
        "{%0,%1,%2,%3}, {%4,%5,%6,%7}, {%8,%9}, {%0,%1,%2,%3};" \
        : "+f"((d)[0]), "+f"((d)[1]), "+f"((d)[2]), "+f"((d)[3]) \
        : "r"((a)[0]), "r"((a)[1]), "r"((a)[2]), "r"((a)[3]), \
          "r"((b)[0]), "r"((b)[1]))

__device__ __forceinline__ u16 f2h(float v) {
    return __half_as_ushort(__float2half(v));
}

// ---------- device scratch ----------
__device__ float g_pre[(size_t)B_ * T_ * 3 * HID_];
__device__ float g_h[2][B_ * HID_];
__device__ unsigned g_flags[NBLK * 32];
// fp16 state images for scan GEMMs
__device__ __align__(16) u16 g_hf[2][B_ * HID_];
__device__ __align__(16) u16 g_rhf[B_ * HID_];
// pre-GEMM fp16 images
__device__ __align__(16) u16 g_Af[(size_t)65536 * 512];
__device__ __align__(16) u16 g_Bf[3 * 512 * 512];

// =====================================================================================
// Convert A: [x|c] fp32 -> fp16 row-major [m][512]
// =====================================================================================
__global__ __launch_bounds__(256) void convertA_kernel(
    const float* __restrict__ x, const float* __restrict__ c)
{
    const size_t idx = (size_t)blockIdx.x * 256 + threadIdx.x;
    const int m  = (int)(idx >> 7);
    const int kq = ((int)idx & 127) << 2;
    const float* src = (kq < 256) ? &x[(size_t)m * 256 + kq]
                                  : &c[(size_t)m * 256 + (kq - 256)];
    float4 v = *(const float4*)src;
    u32 p0 = (u32)f2h(v.x) | ((u32)f2h(v.y) << 16);
    u32 p1 = (u32)f2h(v.z) | ((u32)f2h(v.w) << 16);
    *(uint2*)&g_Af[(size_t)m * 512 + kq] = make_uint2(p0, p1);
}

// =====================================================================================
// Convert B (pre weights): [k][n] -> fp16 n-major [gate][n][k]
// =====================================================================================
__global__ __launch_bounds__(256) void convertB_kernel(
    const float* __restrict__ wxz, const float* __restrict__ wxr, const float* __restrict__ wxh,
    const float* __restrict__ wcz, const float* __restrict__ wcr, const float* __restrict__ wch)
{
    const int idx = blockIdx.x * 256 + threadIdx.x;
    const int gate = idx >> 16;
    const int rem  = idx & 65535;
    const int k  = rem >> 7;
    const int nq = (rem & 127) << 2;
    const float* wx = (gate == 0) ? wxz : (gate == 1) ? wxr : wxh;
    const float* wc = (gate == 0) ? wcz : (gate == 1) ? wcr : wch;
    const float* src = (k < 256) ? &wx[(size_t)k * 512 + nq]
                                 : &wc[(size_t)(k - 256) * 512 + nq];
    float4 v = *(const float4*)src;
    float vv[4] = {v.x, v.y, v.z, v.w};
    #pragma unroll
    for (int i = 0; i < 4; i++)
        g_Bf[((size_t)(gate * 512 + nq + i)) * 512 + k] = f2h(vv[i]);
}

// =====================================================================================
// init h0: fp32 copy + fp16 image
// =====================================================================================
__global__ __launch_bounds__(256) void init_h_kernel(const float* __restrict__ h0)
{
    const int idx = blockIdx.x * 256 + threadIdx.x;
    float v = h0[idx];
    g_h[0][idx] = v;
    g_hf[0][idx] = f2h(v);
}

// =====================================================================================
// PRE via mma.sync fp16 (structure proven in R10/R12; full-tile staging verified)
// =====================================================================================
#define PMA_PITCH 144
#define PMA_IMG   (128 * PMA_PITCH)
#define PM_SMEM   (2 * PMA_IMG)

__global__ __launch_bounds__(256) void pre_mma_kernel(
    const float* __restrict__ bz, const float* __restrict__ br, const float* __restrict__ bh)
{
    extern __shared__ __align__(16) char psm[];
    char* sA = psm;
    char* sB = psm + PMA_IMG;

    const int tid = threadIdx.x;
    const int wid = tid >> 5, lane = tid & 31;
    const int g   = lane >> 2;
    const int tig = lane & 3;

    const int ntg   = blockIdx.x;
    const int mtile = blockIdx.y;
    const int gate  = ntg >> 2;
    const int n0    = (ntg & 3) * 128;

    const int wm = wid >> 2;
    const int wn = wid & 3;

    float acc[4][4][4];
    #pragma unroll
    for (int mi = 0; mi < 4; mi++)
        #pragma unroll
        for (int ni = 0; ni < 4; ni++)
            #pragma unroll
            for (int e = 0; e < 4; e++) acc[mi][ni][e] = 0.0f;

    for (int kc = 0; kc < 8; kc++) {
        __syncthreads();
        #pragma unroll
        for (int i = 0; i < 4; i++) {
            const int lin = tid + 256 * i;
            const int row = lin >> 3, q = lin & 7;
            const size_t asrc = ((size_t)(mtile * 128 + row)) * 512 + kc * 64 + q * 8;
            const size_t bsrc = ((size_t)(gate * 512 + n0 + row)) * 512 + kc * 64 + q * 8;
            *(uint4*)(sA + row * PMA_PITCH + q * 16) = *(const uint4*)&g_Af[asrc];
            *(uint4*)(sB + row * PMA_PITCH + q * 16) = *(const uint4*)&g_Bf[bsrc];
        }
        __syncthreads();

        #pragma unroll
        for (int kk = 0; kk < 4; kk++) {
            const int kb = kk * 32 + tig * 4;
            u32 af[4][4], bf[4][2];
            #pragma unroll
            for (int mi = 0; mi < 4; mi++) {
                const int rbase = (wm * 64 + mi * 16 + g) * PMA_PITCH + kb;
                af[mi][0] = *(const u32*)(sA + rbase);
                af[mi][1] = *(const u32*)(sA + rbase + 8 * PMA_PITCH);
                af[mi][2] = *(const u32*)(sA + rbase + 16);
                af[mi][3] = *(const u32*)(sA + rbase + 8 * PMA_PITCH + 16);
            }
            #pragma unroll
            for (int ni = 0; ni < 4; ni++) {
                const int nbase = (wn * 32 + ni * 8 + g) * PMA_PITCH + kb;
                bf[ni][0] = *(const u32*)(sB + nbase);
                bf[ni][1] = *(const u32*)(sB + nbase + 16);
            }
            #pragma unroll
            for (int mi = 0; mi < 4; mi++)
                #pragma unroll
                for (int ni = 0; ni < 4; ni++)
                    MMAF16(acc[mi][ni], af[mi], bf[ni]);
        }
    }

    const float* bias = (gate == 0) ? bz : (gate == 1) ? br : bh;
    #pragma unroll
    for (int mi = 0; mi < 4; mi++) {
        const int r0 = mtile * 128 + wm * 64 + mi * 16 + g;
        #pragma unroll
        for (int ni = 0; ni < 4; ni++) {
            const int cl = n0 + wn * 32 + ni * 8 + tig * 2;
            const float b0 = bias[cl], b1 = bias[cl + 1];
            float* d0 = &g_pre[(size_t)r0 * 1536 + gate * 512 + cl];
            float* d1 = &g_pre[(size_t)(r0 + 8) * 1536 + gate * 512 + cl];
            *(float2*)d0 = make_float2(acc[mi][ni][0] + b0, acc[mi][ni][1] + b1);
            *(float2*)d1 = make_float2(acc[mi][ni][2] + b0, acc[mi][ni][3] + b1);
        }
    }
}

// =====================================================================================
// GROUP grid barrier: 8 independent groups of 16 blocks (same bm).
// =====================================================================================
__device__ __forceinline__ void gbar_group(unsigned want, int bm)
{
    __syncthreads();
    if (threadIdx.x == 0) {
        asm volatile("st.release.gpu.global.u32 [%0], %1;"
                     :: "l"(&g_flags[blockIdx.x * 32]), "r"(want) : "memory");
    }
    if (threadIdx.x < 16) {
        unsigned v;
        do {
            asm volatile("ld.acquire.gpu.global.u32 %0, [%1];"
                         : "=r"(v) : "l"(&g_flags[(bm * 16 + threadIdx.x) * 32]) : "memory");
        } while ((int)(v - want) < 0);
    }
    __syncthreads();
}

// =====================================================================================
// Tensor-core persistent scan, fp16 single image.
// FIX vs R12: staging now writes BOTH slots (tid and tid+256) -> full 32-row tile.
// =====================================================================================
#define WPITCH 520
#define APITCH 272
#define SOFF_WZR  0
#define SOFF_WH   (SOFF_WZR + 64 * WPITCH * 2)
#define SOFF_SA   (SOFF_WH + 32 * WPITCH * 2)
#define SOFF_ZBUF (SOFF_SA + 32 * APITCH)
#define SC2_SMEM  (SOFF_ZBUF + 32 * 33 * 4)

__global__ __launch_bounds__(256, 1) void scan_mma_kernel(
    const float* __restrict__ w_hz, const float* __restrict__ w_hr,
    const float* __restrict__ w_hh, float* __restrict__ hs_out)
{
    extern __shared__ __align__(16) char sm2[];
    u16* wZR = (u16*)(sm2 + SOFF_WZR);
    u16* wH  = (u16*)(sm2 + SOFF_WH);
    char* sA = sm2 + SOFF_SA;
    float* zbuf = (float*)(sm2 + SOFF_ZBUF);

    const int tid = threadIdx.x;
    const int bid = blockIdx.x;
    const int bm = bid >> 4;
    const int bn = bid & 15;
    const int m0 = bm * 32;
    const int j0 = bn * 32;

    // ---- one-time weight conversion to smem fp16, n-major ----
    for (int idx = tid; idx < 4096; idx += 256) {
        const int k  = idx >> 3;
        const int c4 = (idx & 7) * 4;
        float4 vz = *(const float4*)&w_hz[(size_t)k * HID_ + j0 + c4];
        float4 vr = *(const float4*)&w_hr[(size_t)k * HID_ + j0 + c4];
        float4 vh = *(const float4*)&w_hh[(size_t)k * HID_ + j0 + c4];
        float az[4] = {vz.x, vz.y, vz.z, vz.w};
        float ar[4] = {vr.x, vr.y, vr.z, vr.w};
        float ah[4] = {vh.x, vh.y, vh.z, vh.w};
        #pragma unroll
        for (int i = 0; i < 4; i++) {
            wZR[(c4 + i) * WPITCH + k]      = f2h(az[i]);
            wZR[(32 + c4 + i) * WPITCH + k] = f2h(ar[i]);
            wH[(c4 + i) * WPITCH + k]       = f2h(ah[i]);
        }
    }

    __shared__ unsigned s_base;
    if (tid == 0) s_base = *(volatile unsigned*)&g_flags[bid * 32];
    __syncthreads();
    const unsigned base = s_base;
    unsigned nbar = 0;

    const int wid = tid >> 5, lane = tid & 31;
    const int g   = lane >> 2;
    const int tig = lane & 3;
    const int wm  = wid >> 2;
    const int wn  = wid & 3;
    const int rA  = wm * 16 + g;
    const bool is_z = (wn < 2);
    const int c32b = (wn & 1) * 16;

    // staging: 32 rows x 256 B = 8 KB; 256 threads x 2 slots x 16 B
    const int srow0 = tid >> 4,          sq0 = tid & 15;          // rows 0..15
    const int srow1 = ((tid + 256) >> 4), sq1 = tid & 15;         // rows 16..31

    for (int t = 0; t < T_; t++) {
        const int pp = t & 1;
        const float* __restrict__ hprev = g_h[pp];
        float* __restrict__ hnext = g_h[pp ^ 1];
        const u16* __restrict__ hf = g_hf[pp];

        // ---- phase A epilogue prefetch ----
        const int goff = is_z ? 0 : 512;
        float2 pvA[2][2], hvA[2][2];
        #pragma unroll
        for (int i = 0; i < 2; i++) {
            const int rl = rA + 8 * i;
            const size_t prow = ((size_t)(m0 + rl) * T_ + t) * 1536;
            #pragma unroll
            for (int s = 0; s < 2; s++) {
                const int c = c32b + s * 8 + tig * 2;
                pvA[i][s] = *(const float2*)&g_pre[prow + goff + j0 + c];
                if (!is_z)
                    hvA[i][s] = *(const float2*)&hprev[(size_t)(m0 + rl) * HID_ + j0 + c];
            }
        }

        // ================= phase A GEMM =================
        float accA[2][4];
        #pragma unroll
        for (int s = 0; s < 2; s++)
            #pragma unroll
            for (int e = 0; e < 4; e++) accA[s][e] = 0.0f;

        uint4 pf0 = *(const uint4*)&hf[(size_t)(m0 + srow0) * HID_ + sq0 * 8];
        uint4 pf1 = *(const uint4*)&hf[(size_t)(m0 + srow1) * HID_ + sq1 * 8];

        for (int kc = 0; kc < 4; kc++) {
            __syncthreads();
            *(uint4*)(sA + srow0 * APITCH + sq0 * 16) = pf0;
            *(uint4*)(sA + srow1 * APITCH + sq1 * 16) = pf1;
            __syncthreads();
            if (kc < 3) {
                const int kb = (kc + 1) * 128;
                pf0 = *(const uint4*)&hf[(size_t)(m0 + srow0) * HID_ + kb + sq0 * 8];
                pf1 = *(const uint4*)&hf[(size_t)(m0 + srow1) * HID_ + kb + sq1 * 8];
            }
            #pragma unroll
            for (int kk = 0; kk < 8; kk++) {
                const int ab = rA * APITCH + kk * 32 + tig * 4;
                u32 af[4];
                af[0] = *(const u32*)(sA + ab);
                af[1] = *(const u32*)(sA + ab + 8 * APITCH);
                af[2] = *(const u32*)(sA + ab + 16);
                af[3] = *(const u32*)(sA + ab + 8 * APITCH + 16);
                #pragma unroll
                for (int s = 0; s < 2; s++) {
                    const int col = wn * 16 + s * 8 + g;
                    const int bb = col * WPITCH + kc * 128 + kk * 16 + tig * 2;
                    u32 bf[2];
                    bf[0] = *(const u32*)&wZR[bb];
                    bf[1] = *(const u32*)&wZR[bb + 8];
                    MMAF16(accA[s], af, bf);
                }
            }
        }

        // ---- phase A epilogue ----
        if (is_z) {
            #pragma unroll
            for (int i = 0; i < 2; i++) {
                const int rl = rA + 8 * i;
                #pragma unroll
                for (int s = 0; s < 2; s++) {
                    const int c = c32b + s * 8 + tig * 2;
                    zbuf[rl * 33 + c]     = sigmoidf_(pvA[i][s].x + accA[s][2 * i]);
                    zbuf[rl * 33 + c + 1] = sigmoidf_(pvA[i][s].y + accA[s][2 * i + 1]);
                }
            }
        } else {
            #pragma unroll
            for (int i = 0; i < 2; i++) {
                const int rl = rA + 8 * i;
                #pragma unroll
                for (int s = 0; s < 2; s++) {
                    const int c = c32b + s * 8 + tig * 2;
                    const float r0 = sigmoidf_(pvA[i][s].x + accA[s][2 * i]);
                    const float r1 = sigmoidf_(pvA[i][s].y + accA[s][2 * i + 1]);
                    const float rh0 = r0 * hvA[i][s].x;
                    const float rh1 = r1 * hvA[i][s].y;
                    const size_t gi = (size_t)(m0 + rl) * HID_ + j0 + c;
                    *(u32*)&g_rhf[gi] = (u32)f2h(rh0) | ((u32)f2h(rh1) << 16);
                }
            }
        }
        gbar_group(base + (++nbar), bm);

        // ---- phase B epilogue prefetch ----
        const int cB = wn * 8 + tig * 2;
        float2 phB[2], hoB[2];
        #pragma unroll
        for (int i = 0; i < 2; i++) {
            const int rl = rA + 8 * i;
            const size_t prow = ((size_t)(m0 + rl) * T_ + t) * 1536;
            phB[i] = *(const float2*)&g_pre[prow + 1024 + j0 + cB];
            hoB[i] = *(const float2*)&hprev[(size_t)(m0 + rl) * HID_ + j0 + cB];
        }

        // ================= phase B GEMM =================
        float accB[4] = {0.0f, 0.0f, 0.0f, 0.0f};

        pf0 = *(const uint4*)&g_rhf[(size_t)(m0 + srow0) * HID_ + sq0 * 8];
        pf1 = *(const uint4*)&g_rhf[(size_t)(m0 + srow1) * HID_ + sq1 * 8];

        for (int kc = 0; kc < 4; kc++) {
            __syncthreads();
            *(uint4*)(sA + srow0 * APITCH + sq0 * 16) = pf0;
            *(uint4*)(sA + srow1 * APITCH + sq1 * 16) = pf1;
            __syncthreads();
            if (kc < 3) {
                const int kb = (kc + 1) * 128;
                pf0 = *(const uint4*)&g_rhf[(size_t)(m0 + srow0) * HID_ + kb + sq0 * 8];
                pf1 = *(const uint4*)&g_rhf[(size_t)(m0 + srow1) * HID_ + kb + sq1 * 8];
            }
            #pragma unroll
            for (int kk = 0; kk < 8; kk++) {
                const int ab = rA * APITCH + kk * 32 + tig * 4;
                u32 af[4];
                af[0] = *(const u32*)(sA + ab);
                af[1] = *(const u32*)(sA + ab + 8 * APITCH);
                af[2] = *(const u32*)(sA + ab + 16);
                af[3] = *(const u32*)(sA + ab + 8 * APITCH + 16);
                const int col = wn * 8 + g;
                const int bb = col * WPITCH + kc * 128 + kk * 16 + tig * 2;
                u32 bf[2];
                bf[0] = *(const u32*)&wH[bb];
                bf[1] = *(const u32*)&wH[bb + 8];
                MMAF16(accB, af, bf);
            }
        }

        // ---- phase B epilogue ----
        #pragma unroll
        for (int i = 0; i < 2; i++) {
            const int rl = rA + 8 * i;
            const float ht0 = tanhf(phB[i].x + accB[2 * i]);
            const float ht1 = tanhf(phB[i].y + accB[2 * i + 1]);
            const float z0 = zbuf[rl * 33 + cB];
            const float z1 = zbuf[rl * 33 + cB + 1];
            const float hn0 = fmaf(z0, ht0 - hoB[i].x, hoB[i].x);
            const float hn1 = fmaf(z1, ht1 - hoB[i].y, hoB[i].y);
            const size_t gi = (size_t)(m0 + rl) * HID_ + j0 + cB;
            *(float2*)&hnext[gi] = make_float2(hn0, hn1);
            *(u32*)&g_hf[pp ^ 1][gi] = (u32)f2h(hn0) | ((u32)f2h(hn1) << 16);
            *(float2*)&hs_out[((size_t)(m0 + rl) * T_ + t) * HID_ + j0 + cB] =
                make_float2(hn0, hn1);
        }
        if (t < T_ - 1) gbar_group(base + (++nbar), bm);
    }
}

// =====================================================================================
// out = relu(h_last @ w_out + b_out)  (unchanged)
// =====================================================================================
__global__ __launch_bounds__(256) void out_kernel(
    const float* __restrict__ w_out, const float* __restrict__ b_out,
    float* __restrict__ out)
{
    __shared__ __align__(16) float As[32][36];
    __shared__ __align__(16) float Bs[32][36];

    const float* __restrict__ hlast = g_h[0];

    const int tid = threadIdx.x;
    const int m0 = blockIdx.y * 32;
    const int n0 = blockIdx.x * 32;

    const int ttr = tid >> 4;
    const int ttc = tid & 15;
    const int arow = tid >> 3;
    const int akq  = tid & 7;
    const int bkr  = tid >> 3;
    const int bnq  = tid & 7;

    u64 acc[2][2];
    #pragma unroll
    for (int i = 0; i < 2; i++)
        #pragma unroll
        for (int p = 0; p < 2; p++) acc[i][p] = 0ull;

    for (int k0 = 0; k0 < HID_; k0 += 32) {
        float4 av = *(const float4*)&hlast[(size_t)(m0 + arow) * HID_ + k0 + akq * 4];
        float4 bv = *(const float4*)&w_out[(size_t)(k0 + bkr) * OUT_ + n0 + bnq * 4];

        __syncthreads();
        *(float4*)&As[arow][akq * 4] = av;
        Bs[bnq * 4 + 0][bkr] = bv.x; Bs[bnq * 4 + 1][bkr] = bv.y;
        Bs[bnq * 4 + 2][bkr] = bv.z; Bs[bnq * 4 + 3][bkr] = bv.w;
        __syncthreads();

        #pragma unroll
        for (int q = 0; q < 8; q++) {
            ulonglong2 a0 = *(const ulonglong2*)&As[ttr * 2 + 0][q * 4];
            ulonglong2 a1 = *(const ulonglong2*)&As[ttr * 2 + 1][q * 4];
            #pragma unroll
            for (int p = 0; p < 2; p++) {
                ulonglong2 bb = *(const ulonglong2*)&Bs[ttc + 16 * p][q * 4];
                f2fma(acc[0][p], a0.x, bb.x); f2fma(acc[0][p], a0.y, bb.y);
                f2fma(acc[1][p], a1.x, bb.x); f2fma(acc[1][p], a1.y, bb.y);
            }
        }
    }

    #pragma unroll
    for (int i = 0; i < 2; i++) {
        const int b = m0 + ttr * 2 + i;
        #pragma unroll
        for (int p = 0; p < 2; p++) {
            const int j = n0 + ttc + 16 * p;
            const float s = f2sum(acc[i][p]) + b_out[j];
            out[(size_t)b * OUT_ + j] = fmaxf(s, 0.0f);
        }
    }
}

// =====================================================================================
extern "C" void kernel_launch(void* const* d_in, const int* in_sizes, int n_in,
                              void* d_out, int out_size)
{
    const float* x     = (const float*)d_in[0];
    const float* c     = (const float*)d_in[1];
    const float* h0    = (const float*)d_in[2];
    const float* w_xr  = (const float*)d_in[3];
    const float* w_hr  = (const float*)d_in[4];
    const float* w_cr  = (const float*)d_in[5];
    const float* w_xz  = (const float*)d_in[6];
    const float* w_hz  = (const float*)d_in[7];
    const float* w_cz  = (const float*)d_in[8];
    const float* w_xh  = (const float*)d_in[9];
    const float* w_hh  = (const float*)d_in[10];
    const float* w_ch  = (const float*)d_in[11];
    const float* b_r   = (const float*)d_in[12];
    const float* b_z   = (const float*)d_in[13];
    const float* b_h   = (const float*)d_in[14];
    const float* w_out = (const float*)d_in[15];
    const float* b_out = (const float*)d_in[16];

    float* out = (float*)d_out;
    float* hs  = out + (size_t)B_ * OUT_;

    static int attr_set = 0;
    if (!attr_set) {
        cudaFuncSetAttribute(scan_mma_kernel, cudaFuncAttributeMaxDynamicSharedMemorySize,
                             SC2_SMEM);
        cudaFuncSetAttribute(pre_mma_kernel, cudaFuncAttributeMaxDynamicSharedMemorySize,
                             PM_SMEM);
        attr_set = 1;
    }

    init_h_kernel<<<512, 256>>>(h0);
    convertA_kernel<<<32768, 256>>>(x, c);
    convertB_kernel<<<768, 256>>>(w_xz, w_xr, w_xh, w_cz, w_cr, w_ch);
    pre_mma_kernel<<<dim3(12, 512), 256, PM_SMEM>>>(b_z, b_r, b_h);

    scan_mma_kernel<<<NBLK, 256, SC2_SMEM>>>(w_hz, w_hr, w_hh, hs);

    out_kernel<<<dim3(8, 8), 256>>>(w_out, b_out, out);
}

// round 15
// speedup vs baseline: 4.2557x; 1.1851x over previous
#include <cuda_runtime.h>
#include <cuda_fp16.h>
#include <math.h>

#define B_   256
#define T_   256
#define IN_  256
#define HID_ 512
#define OUT_ 256
#define NBLK 128

typedef unsigned long long u64;
typedef unsigned int u32;
typedef unsigned short u16;

// ---------- packed f32x2 FMA (out kernel) ----------
__device__ __forceinline__ void f2fma(u64 &d, u64 a, u64 b) {
    asm("fma.rn.f32x2 %0, %1, %2, %0;" : "+l"(d) : "l"(a), "l"(b));
}
__device__ __forceinline__ float f2sum(u64 v) {
    unsigned lo, hi;
    asm("mov.b64 {%0, %1}, %2;" : "=r"(lo), "=r"(hi) : "l"(v));
    return __uint_as_float(lo) + __uint_as_float(hi);
}
__device__ __forceinline__ float sigmoidf_(float x) { return 1.0f / (1.0f + expf(-x)); }

// ---------- warp mma.sync m16n8k16 fp16 ----------
#define MMAF16(d, a, b) \
    asm volatile("mma.sync.aligned.m16n8k16.row.col.f32.f16.f16.f32 " \
        "{%0,%1,%2,%3}, {%4,%5,%6,%7}, {%8,%9}, {%0,%1,%2,%3};" \
        : "+f"((d)[0]), "+f"((d)[1]), "+f"((d)[2]), "+f"((d)[3]) \
        : "r"((a)[0]), "r"((a)[1]), "r"((a)[2]), "r"((a)[3]), \
          "r"((b)[0]), "r"((b)[1]))

__device__ __forceinline__ u16 f2h(float v) {
    return __half_as_ushort(__float2half(v));
}

// ---------- device scratch ----------
__device__ float g_pre[(size_t)B_ * T_ * 3 * HID_];
__device__ float g_h[2][B_ * HID_];
__device__ unsigned g_flags[NBLK * 32];
__device__ __align__(16) u16 g_hf[2][B_ * HID_];
__device__ __align__(16) u16 g_rhf[B_ * HID_];
__device__ __align__(16) u16 g_Af[(size_t)65536 * 512];
__device__ __align__(16) u16 g_Bf[3 * 512 * 512];

// =====================================================================================
// Convert A: [x|c] fp32 -> fp16 row-major [m][512]  (unchanged)
// =====================================================================================
__global__ __launch_bounds__(256) void convertA_kernel(
    const float* __restrict__ x, const float* __restrict__ c)
{
    const size_t idx = (size_t)blockIdx.x * 256 + threadIdx.x;
    const int m  = (int)(idx >> 7);
    const int kq = ((int)idx & 127) << 2;
    const float* src = (kq < 256) ? &x[(size_t)m * 256 + kq]
                                  : &c[(size_t)m * 256 + (kq - 256)];
    float4 v = *(const float4*)src;
    u32 p0 = (u32)f2h(v.x) | ((u32)f2h(v.y) << 16);
    u32 p1 = (u32)f2h(v.z) | ((u32)f2h(v.w) << 16);
    *(uint2*)&g_Af[(size_t)m * 512 + kq] = make_uint2(p0, p1);
}

// =====================================================================================
// Convert B (pre weights)  (unchanged)
// =====================================================================================
__global__ __launch_bounds__(256) void convertB_kernel(
    const float* __restrict__ wxz, const float* __restrict__ wxr, const float* __restrict__ wxh,
    const float* __restrict__ wcz, const float* __restrict__ wcr, const float* __restrict__ wch)
{
    const int idx = blockIdx.x * 256 + threadIdx.x;
    const int gate = idx >> 16;
    const int rem  = idx & 65535;
    const int k  = rem >> 7;
    const int nq = (rem & 127) << 2;
    const float* wx = (gate == 0) ? wxz : (gate == 1) ? wxr : wxh;
    const float* wc = (gate == 0) ? wcz : (gate == 1) ? wcr : wch;
    const float* src = (k < 256) ? &wx[(size_t)k * 512 + nq]
                                 : &wc[(size_t)(k - 256) * 512 + nq];
    float4 v = *(const float4*)src;
    float vv[4] = {v.x, v.y, v.z, v.w};
    #pragma unroll
    for (int i = 0; i < 4; i++)
        g_Bf[((size_t)(gate * 512 + nq + i)) * 512 + k] = f2h(vv[i]);
}

// =====================================================================================
// init h0  (unchanged)
// =====================================================================================
__global__ __launch_bounds__(256) void init_h_kernel(const float* __restrict__ h0)
{
    const int idx = blockIdx.x * 256 + threadIdx.x;
    float v = h0[idx];
    g_h[0][idx] = v;
    g_hf[0][idx] = f2h(v);
}

// =====================================================================================
// PRE via mma.sync fp16  (unchanged, 386us, passed)
// =====================================================================================
#define PMA_PITCH 144
#define PMA_IMG   (128 * PMA_PITCH)
#define PM_SMEM   (2 * PMA_IMG)

__global__ __launch_bounds__(256) void pre_mma_kernel(
    const float* __restrict__ bz, const float* __restrict__ br, const float* __restrict__ bh)
{
    extern __shared__ __align__(16) char psm[];
    char* sA = psm;
    char* sB = psm + PMA_IMG;

    const int tid = threadIdx.x;
    const int wid = tid >> 5, lane = tid & 31;
    const int g   = lane >> 2;
    const int tig = lane & 3;

    const int ntg   = blockIdx.x;
    const int mtile = blockIdx.y;
    const int gate  = ntg >> 2;
    const int n0    = (ntg & 3) * 128;

    const int wm = wid >> 2;
    const int wn = wid & 3;

    float acc[4][4][4];
    #pragma unroll
    for (int mi = 0; mi < 4; mi++)
        #pragma unroll
        for (int ni = 0; ni < 4; ni++)
            #pragma unroll
            for (int e = 0; e < 4; e++) acc[mi][ni][e] = 0.0f;

    for (int kc = 0; kc < 8; kc++) {
        __syncthreads();
        #pragma unroll
        for (int i = 0; i < 4; i++) {
            const int lin = tid + 256 * i;
            const int row = lin >> 3, q = lin & 7;
            const size_t asrc = ((size_t)(mtile * 128 + row)) * 512 + kc * 64 + q * 8;
            const size_t bsrc = ((size_t)(gate * 512 + n0 + row)) * 512 + kc * 64 + q * 8;
            *(uint4*)(sA + row * PMA_PITCH + q * 16) = *(const uint4*)&g_Af[asrc];
            *(uint4*)(sB + row * PMA_PITCH + q * 16) = *(const uint4*)&g_Bf[bsrc];
        }
        __syncthreads();

        #pragma unroll
        for (int kk = 0; kk < 4; kk++) {
            const int kb = kk * 32 + tig * 4;
            u32 af[4][4], bf[4][2];
            #pragma unroll
            for (int mi = 0; mi < 4; mi++) {
                const int rbase = (wm * 64 + mi * 16 + g) * PMA_PITCH + kb;
                af[mi][0] = *(const u32*)(sA + rbase);
                af[mi][1] = *(const u32*)(sA + rbase + 8 * PMA_PITCH);
                af[mi][2] = *(const u32*)(sA + rbase + 16);
                af[mi][3] = *(const u32*)(sA + rbase + 8 * PMA_PITCH + 16);
            }
            #pragma unroll
            for (int ni = 0; ni < 4; ni++) {
                const int nbase = (wn * 32 + ni * 8 + g) * PMA_PITCH + kb;
                bf[ni][0] = *(const u32*)(sB + nbase);
                bf[ni][1] = *(const u32*)(sB + nbase + 16);
            }
            #pragma unroll
            for (int mi = 0; mi < 4; mi++)
                #pragma unroll
                for (int ni = 0; ni < 4; ni++)
                    MMAF16(acc[mi][ni], af[mi], bf[ni]);
        }
    }

    const float* bias = (gate == 0) ? bz : (gate == 1) ? br : bh;
    #pragma unroll
    for (int mi = 0; mi < 4; mi++) {
        const int r0 = mtile * 128 + wm * 64 + mi * 16 + g;
        #pragma unroll
        for (int ni = 0; ni < 4; ni++) {
            const int cl = n0 + wn * 32 + ni * 8 + tig * 2;
            const float b0 = bias[cl], b1 = bias[cl + 1];
            float* d0 = &g_pre[(size_t)r0 * 1536 + gate * 512 + cl];
            float* d1 = &g_pre[(size_t)(r0 + 8) * 1536 + gate * 512 + cl];
            *(float2*)d0 = make_float2(acc[mi][ni][0] + b0, acc[mi][ni][1] + b1);
            *(float2*)d1 = make_float2(acc[mi][ni][2] + b0, acc[mi][ni][3] + b1);
        }
    }
}

// =====================================================================================
// GROUP grid barrier  (unchanged)
// =====================================================================================
__device__ __forceinline__ void gbar_group(unsigned want, int bm)
{
    __syncthreads();
    if (threadIdx.x == 0) {
        asm volatile("st.release.gpu.global.u32 [%0], %1;"
                     :: "l"(&g_flags[blockIdx.x * 32]), "r"(want) : "memory");
    }
    if (threadIdx.x < 16) {
        unsigned v;
        do {
            asm volatile("ld.acquire.gpu.global.u32 %0, [%1];"
                         : "=r"(v) : "l"(&g_flags[(bm * 16 + threadIdx.x) * 32]) : "memory");
        } while ((int)(v - want) < 0);
    }
    __syncthreads();
}

// =====================================================================================
// Tensor-core persistent scan, fp16. FULL 512-k staging: one sync-pair per phase
// (4 syncs/step instead of 16), staging stores bank-rotated (conflict-free).
// =====================================================================================
#define WPITCH 520
#define APITCH 1040                            // 512 halfs + 8 pad (260 words = 4 mod 32)
#define SOFF_WZR  0
#define SOFF_WH   (SOFF_WZR + 64 * WPITCH * 2)        // 66560
#define SOFF_SA   (SOFF_WH + 32 * WPITCH * 2)         // 99840
#define SOFF_ZBUF (SOFF_SA + 32 * APITCH)             // 133120
#define SC2_SMEM  (SOFF_ZBUF + 32 * 33 * 4)           // 137344

__global__ __launch_bounds__(256, 1) void scan_mma_kernel(
    const float* __restrict__ w_hz, const float* __restrict__ w_hr,
    const float* __restrict__ w_hh, float* __restrict__ hs_out)
{
    extern __shared__ __align__(16) char sm2[];
    u16* wZR = (u16*)(sm2 + SOFF_WZR);
    u16* wH  = (u16*)(sm2 + SOFF_WH);
    char* sA = sm2 + SOFF_SA;
    float* zbuf = (float*)(sm2 + SOFF_ZBUF);

    const int tid = threadIdx.x;
    const int bid = blockIdx.x;
    const int bm = bid >> 4;
    const int bn = bid & 15;
    const int m0 = bm * 32;
    const int j0 = bn * 32;

    // ---- one-time weight conversion to smem fp16, n-major ----
    for (int idx = tid; idx < 4096; idx += 256) {
        const int k  = idx >> 3;
        const int c4 = (idx & 7) * 4;
        float4 vz = *(const float4*)&w_hz[(size_t)k * HID_ + j0 + c4];
        float4 vr = *(const float4*)&w_hr[(size_t)k * HID_ + j0 + c4];
        float4 vh = *(const float4*)&w_hh[(size_t)k * HID_ + j0 + c4];
        float az[4] = {vz.x, vz.y, vz.z, vz.w};
        float ar[4] = {vr.x, vr.y, vr.z, vr.w};
        float ah[4] = {vh.x, vh.y, vh.z, vh.w};
        #pragma unroll
        for (int i = 0; i < 4; i++) {
            wZR[(c4 + i) * WPITCH + k]      = f2h(az[i]);
            wZR[(32 + c4 + i) * WPITCH + k] = f2h(ar[i]);
            wH[(c4 + i) * WPITCH + k]       = f2h(ah[i]);
        }
    }

    __shared__ unsigned s_base;
    if (tid == 0) s_base = *(volatile unsigned*)&g_flags[bid * 32];
    __syncthreads();
    const unsigned base = s_base;
    unsigned nbar = 0;

    const int wid = tid >> 5, lane = tid & 31;
    const int g   = lane >> 2;
    const int tig = lane & 3;
    const int wm  = wid >> 2;
    const int wn  = wid & 3;
    const int rA  = wm * 16 + g;
    const bool is_z = (wn < 2);
    const int c32b = (wn & 1) * 16;

    // full-image staging mapping: thread -> row (tid>>3), 8 bank-rotated 16B slots
    const int srow = tid >> 3;
    const int sb0  = ((tid & 7) - srow) & 7;       // rotated base slot (bank = 4*(tid&7))

    for (int t = 0; t < T_; t++) {
        const int pp = t & 1;
        const float* __restrict__ hprev = g_h[pp];
        float* __restrict__ hnext = g_h[pp ^ 1];
        const u16* __restrict__ hf = g_hf[pp];

        // ---- phase A epilogue prefetch ----
        const int goff = is_z ? 0 : 512;
        float2 pvA[2][2], hvA[2][2];
        #pragma unroll
        for (int i = 0; i < 2; i++) {
            const int rl = rA + 8 * i;
            const size_t prow = ((size_t)(m0 + rl) * T_ + t) * 1536;
            #pragma unroll
            for (int s = 0; s < 2; s++) {
                const int c = c32b + s * 8 + tig * 2;
                pvA[i][s] = *(const float2*)&g_pre[prow + goff + j0 + c];
                if (!is_z)
                    hvA[i][s] = *(const float2*)&hprev[(size_t)(m0 + rl) * HID_ + j0 + c];
            }
        }

        // ================= phase A GEMM =================
        float accA[2][4];
        #pragma unroll
        for (int s = 0; s < 2; s++)
            #pragma unroll
            for (int e = 0; e < 4; e++) accA[s][e] = 0.0f;

        {
            uint4 pf[8];
            #pragma unroll
            for (int i = 0; i < 8; i++) {
                const int slot = sb0 + 8 * i;
                pf[i] = *(const uint4*)&hf[(size_t)(m0 + srow) * HID_ + slot * 8];
            }
            __syncthreads();
            #pragma unroll
            for (int i = 0; i < 8; i++) {
                const int slot = sb0 + 8 * i;
                *(uint4*)(sA + srow * APITCH + slot * 16) = pf[i];
            }
            __syncthreads();
        }

        #pragma unroll 8
        for (int kk2 = 0; kk2 < 32; kk2++) {
            const int ab = rA * APITCH + kk2 * 32 + tig * 4;
            u32 af[4];
            af[0] = *(const u32*)(sA + ab);
            af[1] = *(const u32*)(sA + ab + 8 * APITCH);
            af[2] = *(const u32*)(sA + ab + 16);
            af[3] = *(const u32*)(sA + ab + 8 * APITCH + 16);
            #pragma unroll
            for (int s = 0; s < 2; s++) {
                const int col = wn * 16 + s * 8 + g;
                const int bb = col * WPITCH + kk2 * 16 + tig * 2;
                u32 bf[2];
                bf[0] = *(const u32*)&wZR[bb];
                bf[1] = *(const u32*)&wZR[bb + 8];
                MMAF16(accA[s], af, bf);
            }
        }

        // ---- phase A epilogue ----
        if (is_z) {
            #pragma unroll
            for (int i = 0; i < 2; i++) {
                const int rl = rA + 8 * i;
                #pragma unroll
                for (int s = 0; s < 2; s++) {
                    const int c = c32b + s * 8 + tig * 2;
                    zbuf[rl * 33 + c]     = sigmoidf_(pvA[i][s].x + accA[s][2 * i]);
                    zbuf[rl * 33 + c + 1] = sigmoidf_(pvA[i][s].y + accA[s][2 * i + 1]);
                }
            }
        } else {
            #pragma unroll
            for (int i = 0; i < 2; i++) {
                const int rl = rA + 8 * i;
                #pragma unroll
                for (int s = 0; s < 2; s++) {
                    const int c = c32b + s * 8 + tig * 2;
                    const float r0 = sigmoidf_(pvA[i][s].x + accA[s][2 * i]);
                    const float r1 = sigmoidf_(pvA[i][s].y + accA[s][2 * i + 1]);
                    const float rh0 = r0 * hvA[i][s].x;
                    const float rh1 = r1 * hvA[i][s].y;
                    const size_t gi = (size_t)(m0 + rl) * HID_ + j0 + c;
                    *(u32*)&g_rhf[gi] = (u32)f2h(rh0) | ((u32)f2h(rh1) << 16);
                }
            }
        }
        gbar_group(base + (++nbar), bm);

        // ---- phase B epilogue prefetch ----
        const int cB = wn * 8 + tig * 2;
        float2 phB[2], hoB[2];
        #pragma unroll
        for (int i = 0; i < 2; i++) {
            const int rl = rA + 8 * i;
            const size_t prow = ((size_t)(m0 + rl) * T_ + t) * 1536;
            phB[i] = *(const float2*)&g_pre[prow + 1024 + j0 + cB];
            hoB[i] = *(const float2*)&hprev[(size_t)(m0 + rl) * HID_ + j0 + cB];
        }

        // ================= phase B GEMM =================
        float accB[4] = {0.0f, 0.0f, 0.0f, 0.0f};

        {
            uint4 pf[8];
            #pragma unroll
            for (int i = 0; i < 8; i++) {
                const int slot = sb0 + 8 * i;
                pf[i] = *(const uint4*)&g_rhf[(size_t)(m0 + srow) * HID_ + slot * 8];
            }
            __syncthreads();
            #pragma unroll
            for (int i = 0; i < 8; i++) {
                const int slot = sb0 + 8 * i;
                *(uint4*)(sA + srow * APITCH + slot * 16) = pf[i];
            }
            __syncthreads();
        }

        #pragma unroll 8
        for (int kk2 = 0; kk2 < 32; kk2++) {
            const int ab = rA * APITCH + kk2 * 32 + tig * 4;
            u32 af[4];
            af[0] = *(const u32*)(sA + ab);
            af[1] = *(const u32*)(sA + ab + 8 * APITCH);
            af[2] = *(const u32*)(sA + ab + 16);
            af[3] = *(const u32*)(sA + ab + 8 * APITCH + 16);
            const int col = wn * 8 + g;
            const int bb = col * WPITCH + kk2 * 16 + tig * 2;
            u32 bf[2];
            bf[0] = *(const u32*)&wH[bb];
            bf[1] = *(const u32*)&wH[bb + 8];
            MMAF16(accB, af, bf);
        }

        // ---- phase B epilogue ----
        #pragma unroll
        for (int i = 0; i < 2; i++) {
            const int rl = rA + 8 * i;
            const float ht0 = tanhf(phB[i].x + accB[2 * i]);
            const float ht1 = tanhf(phB[i].y + accB[2 * i + 1]);
            const float z0 = zbuf[rl * 33 + cB];
            const float z1 = zbuf[rl * 33 + cB + 1];
            const float hn0 = fmaf(z0, ht0 - hoB[i].x, hoB[i].x);
            const float hn1 = fmaf(z1, ht1 - hoB[i].y, hoB[i].y);
            const size_t gi = (size_t)(m0 + rl) * HID_ + j0 + cB;
            *(float2*)&hnext[gi] = make_float2(hn0, hn1);
            *(u32*)&g_hf[pp ^ 1][gi] = (u32)f2h(hn0) | ((u32)f2h(hn1) << 16);
            *(float2*)&hs_out[((size_t)(m0 + rl) * T_ + t) * HID_ + j0 + cB] =
                make_float2(hn0, hn1);
        }
        if (t < T_ - 1) gbar_group(base + (++nbar), bm);
    }
}

// =====================================================================================
// out = relu(h_last @ w_out + b_out)  (unchanged)
// =====================================================================================
__global__ __launch_bounds__(256) void out_kernel(
    const float* __restrict__ w_out, const float* __restrict__ b_out,
    float* __restrict__ out)
{
    __shared__ __align__(16) float As[32][36];
    __shared__ __align__(16) float Bs[32][36];

    const float* __restrict__ hlast = g_h[0];

    const int tid = threadIdx.x;
    const int m0 = blockIdx.y * 32;
    const int n0 = blockIdx.x * 32;

    const int ttr = tid >> 4;
    const int ttc = tid & 15;
    const int arow = tid >> 3;
    const int akq  = tid & 7;
    const int bkr  = tid >> 3;
    const int bnq  = tid & 7;

    u64 acc[2][2];
    #pragma unroll
    for (int i = 0; i < 2; i++)
        #pragma unroll
        for (int p = 0; p < 2; p++) acc[i][p] = 0ull;

    for (int k0 = 0; k0 < HID_; k0 += 32) {
        float4 av = *(const float4*)&hlast[(size_t)(m0 + arow) * HID_ + k0 + akq * 4];
        float4 bv = *(const float4*)&w_out[(size_t)(k0 + bkr) * OUT_ + n0 + bnq * 4];

        __syncthreads();
        *(float4*)&As[arow][akq * 4] = av;
        Bs[bnq * 4 + 0][bkr] = bv.x; Bs[bnq * 4 + 1][bkr] = bv.y;
        Bs[bnq * 4 + 2][bkr] = bv.z; Bs[bnq * 4 + 3][bkr] = bv.w;
        __syncthreads();

        #pragma unroll
        for (int q = 0; q < 8; q++) {
            ulonglong2 a0 = *(const ulonglong2*)&As[ttr * 2 + 0][q * 4];
            ulonglong2 a1 = *(const ulonglong2*)&As[ttr * 2 + 1][q * 4];
            #pragma unroll
            for (int p = 0; p < 2; p++) {
                ulonglong2 bb = *(const ulonglong2*)&Bs[ttc + 16 * p][q * 4];
                f2fma(acc[0][p], a0.x, bb.x); f2fma(acc[0][p], a0.y, bb.y);
                f2fma(acc[1][p], a1.x, bb.x); f2fma(acc[1][p], a1.y, bb.y);
            }
        }
    }

    #pragma unroll
    for (int i = 0; i < 2; i++) {
        const int b = m0 + ttr * 2 + i;
        #pragma unroll
        for (int p = 0; p < 2; p++) {
            const int j = n0 + ttc + 16 * p;
            const float s = f2sum(acc[i][p]) + b_out[j];
            out[(size_t)b * OUT_ + j] = fmaxf(s, 0.0f);
        }
    }
}

// =====================================================================================
extern "C" void kernel_launch(void* const* d_in, const int* in_sizes, int n_in,
                              void* d_out, int out_size)
{
    const float* x     = (const float*)d_in[0];
    const float* c     = (const float*)d_in[1];
    const float* h0    = (const float*)d_in[2];
    const float* w_xr  = (const float*)d_in[3];
    const float* w_hr  = (const float*)d_in[4];
    const float* w_cr  = (const float*)d_in[5];
    const float* w_xz  = (const float*)d_in[6];
    const float* w_hz  = (const float*)d_in[7];
    const float* w_cz  = (const float*)d_in[8];
    const float* w_xh  = (const float*)d_in[9];
    const float* w_hh  = (const float*)d_in[10];
    const float* w_ch  = (const float*)d_in[11];
    const float* b_r   = (const float*)d_in[12];
    const float* b_z   = (const float*)d_in[13];
    const float* b_h   = (const float*)d_in[14];
    const float* w_out = (const float*)d_in[15];
    const float* b_out = (const float*)d_in[16];

    float* out = (float*)d_out;
    float* hs  = out + (size_t)B_ * OUT_;

    static int attr_set = 0;
    if (!attr_set) {
        cudaFuncSetAttribute(scan_mma_kernel, cudaFuncAttributeMaxDynamicSharedMemorySize,
                             SC2_SMEM);
        cudaFuncSetAttribute(pre_mma_kernel, cudaFuncAttributeMaxDynamicSharedMemorySize,
                             PM_SMEM);
        attr_set = 1;
    }

    init_h_kernel<<<512, 256>>>(h0);
    convertA_kernel<<<32768, 256>>>(x, c);
    convertB_kernel<<<768, 256>>>(w_xz, w_xr, w_xh, w_cz, w_cr, w_ch);
    pre_mma_kernel<<<dim3(12, 512), 256, PM_SMEM>>>(b_z, b_r, b_h);

    scan_mma_kernel<<<NBLK, 256, SC2_SMEM>>>(w_hz, w_hr, w_hh, hs);

    out_kernel<<<dim3(8, 8), 256>>>(w_out, b_out, out);
}

// round 16
// speedup vs baseline: 4.3203x; 1.0152x over previous
#include <cuda_runtime.h>
#include <cuda_fp16.h>
#include <math.h>

#define B_   256
#define T_   256
#define IN_  256
#define HID_ 512
#define OUT_ 256
#define NBLK 128

typedef unsigned long long u64;
typedef unsigned int u32;
typedef unsigned short u16;

// ---------- packed f32x2 FMA (out kernel) ----------
__device__ __forceinline__ void f2fma(u64 &d, u64 a, u64 b) {
    asm("fma.rn.f32x2 %0, %1, %2, %0;" : "+l"(d) : "l"(a), "l"(b));
}
__device__ __forceinline__ float f2sum(u64 v) {
    unsigned lo, hi;
    asm("mov.b64 {%0, %1}, %2;" : "=r"(lo), "=r"(hi) : "l"(v));
    return __uint_as_float(lo) + __uint_as_float(hi);
}
__device__ __forceinline__ float sigmoidf_(float x) { return 1.0f / (1.0f + expf(-x)); }

// ---------- warp mma.sync m16n8k16 fp16 ----------
#define MMAF16(d, a, b) \
    asm volatile("mma.sync.aligned.m16n8k16.row.col.f32.f16.f16.f32 " \
        "{%0,%1,%2,%3}, {%4,%5,%6,%7}, {%8,%9}, {%0,%1,%2,%3};" \
        : "+f"((d)[0]), "+f"((d)[1]), "+f"((d)[2]), "+f"((d)[3]) \
        : "r"((a)[0]), "r"((a)[1]), "r"((a)[2]), "r"((a)[3]), \
          "r"((b)[0]), "r"((b)[1]))

__device__ __forceinline__ u16 f2h(float v) {
    return __half_as_ushort(__float2half(v));
}

#define TBAR(id) asm volatile("bar.sync %0, 128;" :: "r"(id) : "memory")

// ---------- device scratch ----------
__device__ float g_pre[(size_t)B_ * T_ * 3 * HID_];
__device__ float g_h[2][B_ * HID_];
__device__ unsigned g_flags[NBLK * 2 * 32];      // per-(block,team) 128B-spaced flags
__device__ __align__(16) u16 g_hf[2][B_ * HID_];
__device__ __align__(16) u16 g_rhf[B_ * HID_];
__device__ __align__(16) u16 g_Af[(size_t)65536 * 512];
__device__ __align__(16) u16 g_Bf[3 * 512 * 512];

// =====================================================================================
// Convert A  (unchanged)
// =====================================================================================
__global__ __launch_bounds__(256) void convertA_kernel(
    const float* __restrict__ x, const float* __restrict__ c)
{
    const size_t idx = (size_t)blockIdx.x * 256 + threadIdx.x;
    const int m  = (int)(idx >> 7);
    const int kq = ((int)idx & 127) << 2;
    const float* src = (kq < 256) ? &x[(size_t)m * 256 + kq]
                                  : &c[(size_t)m * 256 + (kq - 256)];
    float4 v = *(const float4*)src;
    u32 p0 = (u32)f2h(v.x) | ((u32)f2h(v.y) << 16);
    u32 p1 = (u32)f2h(v.z) | ((u32)f2h(v.w) << 16);
    *(uint2*)&g_Af[(size_t)m * 512 + kq] = make_uint2(p0, p1);
}

// =====================================================================================
// Convert B  (unchanged)
// =====================================================================================
__global__ __launch_bounds__(256) void convertB_kernel(
    const float* __restrict__ wxz, const float* __restrict__ wxr, const float* __restrict__ wxh,
    const float* __restrict__ wcz, const float* __restrict__ wcr, const float* __restrict__ wch)
{
    const int idx = blockIdx.x * 256 + threadIdx.x;
    const int gate = idx >> 16;
    const int rem  = idx & 65535;
    const int k  = rem >> 7;
    const int nq = (rem & 127) << 2;
    const float* wx = (gate == 0) ? wxz : (gate == 1) ? wxr : wxh;
    const float* wc = (gate == 0) ? wcz : (gate == 1) ? wcr : wch;
    const float* src = (k < 256) ? &wx[(size_t)k * 512 + nq]
                                 : &wc[(size_t)(k - 256) * 512 + nq];
    float4 v = *(const float4*)src;
    float vv[4] = {v.x, v.y, v.z, v.w};
    #pragma unroll
    for (int i = 0; i < 4; i++)
        g_Bf[((size_t)(gate * 512 + nq + i)) * 512 + k] = f2h(vv[i]);
}

// =====================================================================================
// init h0  (unchanged)
// =====================================================================================
__global__ __launch_bounds__(256) void init_h_kernel(const float* __restrict__ h0)
{
    const int idx = blockIdx.x * 256 + threadIdx.x;
    float v = h0[idx];
    g_h[0][idx] = v;
    g_hf[0][idx] = f2h(v);
}

// =====================================================================================
// PRE via mma.sync fp16  (unchanged, 384us, passed)
// =====================================================================================
#define PMA_PITCH 144
#define PMA_IMG   (128 * PMA_PITCH)
#define PM_SMEM   (2 * PMA_IMG)

__global__ __launch_bounds__(256) void pre_mma_kernel(
    const float* __restrict__ bz, const float* __restrict__ br, const float* __restrict__ bh)
{
    extern __shared__ __align__(16) char psm[];
    char* sA = psm;
    char* sB = psm + PMA_IMG;

    const int tid = threadIdx.x;
    const int wid = tid >> 5, lane = tid & 31;
    const int g   = lane >> 2;
    const int tig = lane & 3;

    const int ntg   = blockIdx.x;
    const int mtile = blockIdx.y;
    const int gate  = ntg >> 2;
    const int n0    = (ntg & 3) * 128;

    const int wm = wid >> 2;
    const int wn = wid & 3;

    float acc[4][4][4];
    #pragma unroll
    for (int mi = 0; mi < 4; mi++)
        #pragma unroll
        for (int ni = 0; ni < 4; ni++)
            #pragma unroll
            for (int e = 0; e < 4; e++) acc[mi][ni][e] = 0.0f;

    for (int kc = 0; kc < 8; kc++) {
        __syncthreads();
        #pragma unroll
        for (int i = 0; i < 4; i++) {
            const int lin = tid + 256 * i;
            const int row = lin >> 3, q = lin & 7;
            const size_t asrc = ((size_t)(mtile * 128 + row)) * 512 + kc * 64 + q * 8;
            const size_t bsrc = ((size_t)(gate * 512 + n0 + row)) * 512 + kc * 64 + q * 8;
            *(uint4*)(sA + row * PMA_PITCH + q * 16) = *(const uint4*)&g_Af[asrc];
            *(uint4*)(sB + row * PMA_PITCH + q * 16) = *(const uint4*)&g_Bf[bsrc];
        }
        __syncthreads();

        #pragma unroll
        for (int kk = 0; kk < 4; kk++) {
            const int kb = kk * 32 + tig * 4;
            u32 af[4][4], bf[4][2];
            #pragma unroll
            for (int mi = 0; mi < 4; mi++) {
                const int rbase = (wm * 64 + mi * 16 + g) * PMA_PITCH + kb;
                af[mi][0] = *(const u32*)(sA + rbase);
                af[mi][1] = *(const u32*)(sA + rbase + 8 * PMA_PITCH);
                af[mi][2] = *(const u32*)(sA + rbase + 16);
                af[mi][3] = *(const u32*)(sA + rbase + 8 * PMA_PITCH + 16);
            }
            #pragma unroll
            for (int ni = 0; ni < 4; ni++) {
                const int nbase = (wn * 32 + ni * 8 + g) * PMA_PITCH + kb;
                bf[ni][0] = *(const u32*)(sB + nbase);
                bf[ni][1] = *(const u32*)(sB + nbase + 16);
            }
            #pragma unroll
            for (int mi = 0; mi < 4; mi++)
                #pragma unroll
                for (int ni = 0; ni < 4; ni++)
                    MMAF16(acc[mi][ni], af[mi], bf[ni]);
        }
    }

    const float* bias = (gate == 0) ? bz : (gate == 1) ? br : bh;
    #pragma unroll
    for (int mi = 0; mi < 4; mi++) {
        const int r0 = mtile * 128 + wm * 64 + mi * 16 + g;
        #pragma unroll
        for (int ni = 0; ni < 4; ni++) {
            const int cl = n0 + wn * 32 + ni * 8 + tig * 2;
            const float b0 = bias[cl], b1 = bias[cl + 1];
            float* d0 = &g_pre[(size_t)r0 * 1536 + gate * 512 + cl];
            float* d1 = &g_pre[(size_t)(r0 + 8) * 1536 + gate * 512 + cl];
            *(float2*)d0 = make_float2(acc[mi][ni][0] + b0, acc[mi][ni][1] + b1);
            *(float2*)d1 = make_float2(acc[mi][ni][2] + b0, acc[mi][ni][3] + b1);
        }
    }
}

// =====================================================================================
// Per-TEAM group barrier: team = half-block (128 threads). 8 groups x 16 blocks x 2 teams.
// =====================================================================================
__device__ __forceinline__ void gbar_team(unsigned want, int bm, int team, int ttid)
{
    TBAR(team + 1);
    if (ttid == 0) {
        asm volatile("st.release.gpu.global.u32 [%0], %1;"
                     :: "l"(&g_flags[(blockIdx.x * 2 + team) * 32]), "r"(want) : "memory");
    }
    if (ttid < 16) {
        unsigned v;
        do {
            asm volatile("ld.acquire.gpu.global.u32 %0, [%1];"
                         : "=r"(v)
                         : "l"(&g_flags[((bm * 16 + ttid) * 2 + team) * 32]) : "memory");
        } while ((int)(v - want) < 0);
    }
    TBAR(team + 1);
}

// =====================================================================================
// Tensor-core persistent scan, fp16, TWO INDEPENDENT TEAMS per block (16 rows each).
// Team barrier latency overlaps the other team's compute on the same SM.
// =====================================================================================
#define WPITCH 520
#define APITCH 1040
#define SOFF_WZR  0
#define SOFF_WH   (SOFF_WZR + 64 * WPITCH * 2)        // 66560
#define SOFF_SA   (SOFF_WH + 32 * WPITCH * 2)         // 99840
#define SOFF_ZBUF (SOFF_SA + 2 * 16 * APITCH)         // 133120
#define SC2_SMEM  (SOFF_ZBUF + 2 * 16 * 33 * 4)       // 137344

__global__ __launch_bounds__(256, 1) void scan_mma_kernel(
    const float* __restrict__ w_hz, const float* __restrict__ w_hr,
    const float* __restrict__ w_hh, float* __restrict__ hs_out)
{
    extern __shared__ __align__(16) char sm2[];
    u16* wZR = (u16*)(sm2 + SOFF_WZR);
    u16* wH  = (u16*)(sm2 + SOFF_WH);
    char* sAall = sm2 + SOFF_SA;
    float* zball = (float*)(sm2 + SOFF_ZBUF);

    const int tid = threadIdx.x;
    const int bid = blockIdx.x;
    const int bm = bid >> 4;
    const int bn = bid & 15;
    const int m0 = bm * 32;
    const int j0 = bn * 32;

    // ---- one-time weight conversion (full block) ----
    for (int idx = tid; idx < 4096; idx += 256) {
        const int k  = idx >> 3;
        const int c4 = (idx & 7) * 4;
        float4 vz = *(const float4*)&w_hz[(size_t)k * HID_ + j0 + c4];
        float4 vr = *(const float4*)&w_hr[(size_t)k * HID_ + j0 + c4];
        float4 vh = *(const float4*)&w_hh[(size_t)k * HID_ + j0 + c4];
        float az[4] = {vz.x, vz.y, vz.z, vz.w};
        float ar[4] = {vr.x, vr.y, vr.z, vr.w};
        float ah[4] = {vh.x, vh.y, vh.z, vh.w};
        #pragma unroll
        for (int i = 0; i < 4; i++) {
            wZR[(c4 + i) * WPITCH + k]      = f2h(az[i]);
            wZR[(32 + c4 + i) * WPITCH + k] = f2h(ar[i]);
            wH[(c4 + i) * WPITCH + k]       = f2h(ah[i]);
        }
    }

    const int team = tid >> 7;          // 0 or 1
    const int ttid = tid & 127;
    const int twid = ttid >> 5;         // warp in team: 0..3
    const int lane = ttid & 31;
    const int g    = lane >> 2;
    const int tig  = lane & 3;
    const int mt0  = m0 + team * 16;    // team's 16 batch rows

    __shared__ unsigned s_base2[2];
    if (ttid == 0) s_base2[team] = *(volatile unsigned*)&g_flags[(bid * 2 + team) * 32];
    __syncthreads();
    const unsigned base = s_base2[team];
    unsigned nbar = 0;

    char* sAt = sAall + team * 16 * APITCH;
    float* zb  = zball + team * 16 * 33;

    const bool is_z = (twid < 2);
    const int c32b = (twid & 1) * 16;

    // staging mapping within team: 16 rows x 8 threads; 8 rotated 16B slots per thread
    const int srow = ttid >> 3;                     // 0..15
    const int sb0  = ((ttid & 7) - srow) & 7;

    for (int t = 0; t < T_; t++) {
        const int pp = t & 1;
        const float* __restrict__ hprev = g_h[pp];
        float* __restrict__ hnext = g_h[pp ^ 1];
        const u16* __restrict__ hf = g_hf[pp];

        // ---- phase A epilogue prefetch (own cols: valid without barrier) ----
        const int goff = is_z ? 0 : 512;
        float2 pvA[2][2], hvA[2][2];
        #pragma unroll
        for (int i = 0; i < 2; i++) {
            const int rl = g + 8 * i;
            const size_t prow = ((size_t)(mt0 + rl) * T_ + t) * 1536;
            #pragma unroll
            for (int s = 0; s < 2; s++) {
                const int c = c32b + s * 8 + tig * 2;
                pvA[i][s] = *(const float2*)&g_pre[prow + goff + j0 + c];
                if (!is_z)
                    hvA[i][s] = *(const float2*)&hprev[(size_t)(mt0 + rl) * HID_ + j0 + c];
            }
        }

        // ================= phase A GEMM: [16 x 512] @ [512 x 64] =================
        float accA[2][4];
        #pragma unroll
        for (int s = 0; s < 2; s++)
            #pragma unroll
            for (int e = 0; e < 4; e++) accA[s][e] = 0.0f;

        {
            uint4 pf[8];
            #pragma unroll
            for (int i = 0; i < 8; i++)
                pf[i] = *(const uint4*)&hf[(size_t)(mt0 + srow) * HID_ + (sb0 + 8 * i) * 8];
            TBAR(team + 1);
            #pragma unroll
            for (int i = 0; i < 8; i++)
                *(uint4*)(sAt + srow * APITCH + (sb0 + 8 * i) * 16) = pf[i];
            TBAR(team + 1);
        }

        #pragma unroll 8
        for (int kk2 = 0; kk2 < 32; kk2++) {
            const int ab = g * APITCH + kk2 * 32 + tig * 4;
            u32 af[4];
            af[0] = *(const u32*)(sAt + ab);
            af[1] = *(const u32*)(sAt + ab + 8 * APITCH);
            af[2] = *(const u32*)(sAt + ab + 16);
            af[3] = *(const u32*)(sAt + ab + 8 * APITCH + 16);
            #pragma unroll
            for (int s = 0; s < 2; s++) {
                const int col = twid * 16 + s * 8 + g;
                const int bb = col * WPITCH + kk2 * 16 + tig * 2;
                u32 bf[2];
                bf[0] = *(const u32*)&wZR[bb];
                bf[1] = *(const u32*)&wZR[bb + 8];
                MMAF16(accA[s], af, bf);
            }
        }

        // ---- phase A epilogue ----
        if (is_z) {
            #pragma unroll
            for (int i = 0; i < 2; i++) {
                const int rl = g + 8 * i;
                #pragma unroll
                for (int s = 0; s < 2; s++) {
                    const int c = c32b + s * 8 + tig * 2;
                    zb[rl * 33 + c]     = sigmoidf_(pvA[i][s].x + accA[s][2 * i]);
                    zb[rl * 33 + c + 1] = sigmoidf_(pvA[i][s].y + accA[s][2 * i + 1]);
                }
            }
        } else {
            #pragma unroll
            for (int i = 0; i < 2; i++) {
                const int rl = g + 8 * i;
                #pragma unroll
                for (int s = 0; s < 2; s++) {
                    const int c = c32b + s * 8 + tig * 2;
                    const float r0 = sigmoidf_(pvA[i][s].x + accA[s][2 * i]);
                    const float r1 = sigmoidf_(pvA[i][s].y + accA[s][2 * i + 1]);
                    const float rh0 = r0 * hvA[i][s].x;
                    const float rh1 = r1 * hvA[i][s].y;
                    const size_t gi = (size_t)(mt0 + rl) * HID_ + j0 + c;
                    *(u32*)&g_rhf[gi] = (u32)f2h(rh0) | ((u32)f2h(rh1) << 16);
                }
            }
        }

        // ---- phase B epilogue prefetch BEFORE barrier (own cols, static pre) ----
        const int cB = twid * 8 + tig * 2;
        float2 phB[2], hoB[2];
        #pragma unroll
        for (int i = 0; i < 2; i++) {
            const int rl = g + 8 * i;
            const size_t prow = ((size_t)(mt0 + rl) * T_ + t) * 1536;
            phB[i] = *(const float2*)&g_pre[prow + 1024 + j0 + cB];
            hoB[i] = *(const float2*)&hprev[(size_t)(mt0 + rl) * HID_ + j0 + cB];
        }

        gbar_team(base + (++nbar), bm, team, ttid);

        // ================= phase B GEMM: [16 x 512] @ [512 x 32] =================
        float accB[4] = {0.0f, 0.0f, 0.0f, 0.0f};

        {
            uint4 pf[8];
            #pragma unroll
            for (int i = 0; i < 8; i++)
                pf[i] = *(const uint4*)&g_rhf[(size_t)(mt0 + srow) * HID_ + (sb0 + 8 * i) * 8];
            TBAR(team + 1);
            #pragma unroll
            for (int i = 0; i < 8; i++)
                *(uint4*)(sAt + srow * APITCH + (sb0 + 8 * i) * 16) = pf[i];
            TBAR(team + 1);
        }

        #pragma unroll 8
        for (int kk2 = 0; kk2 < 32; kk2++) {
            const int ab = g * APITCH + kk2 * 32 + tig * 4;
            u32 af[4];
            af[0] = *(const u32*)(sAt + ab);
            af[1] = *(const u32*)(sAt + ab + 8 * APITCH);
            af[2] = *(const u32*)(sAt + ab + 16);
            af[3] = *(const u32*)(sAt + ab + 8 * APITCH + 16);
            const int col = twid * 8 + g;
            const int bb = col * WPITCH + kk2 * 16 + tig * 2;
            u32 bf[2];
            bf[0] = *(const u32*)&wH[bb];
            bf[1] = *(const u32*)&wH[bb + 8];
            MMAF16(accB, af, bf);
        }

        // ---- phase B epilogue ----
        #pragma unroll
        for (int i = 0; i < 2; i++) {
            const int rl = g + 8 * i;
            const float ht0 = tanhf(phB[i].x + accB[2 * i]);
            const float ht1 = tanhf(phB[i].y + accB[2 * i + 1]);
            const float z0 = zb[rl * 33 + cB];
            const float z1 = zb[rl * 33 + cB + 1];
            const float hn0 = fmaf(z0, ht0 - hoB[i].x, hoB[i].x);
            const float hn1 = fmaf(z1, ht1 - hoB[i].y, hoB[i].y);
            const size_t gi = (size_t)(mt0 + rl) * HID_ + j0 + cB;
            *(float2*)&hnext[gi] = make_float2(hn0, hn1);
            *(u32*)&g_hf[pp ^ 1][gi] = (u32)f2h(hn0) | ((u32)f2h(hn1) << 16);
            *(float2*)&hs_out[((size_t)(mt0 + rl) * T_ + t) * HID_ + j0 + cB] =
                make_float2(hn0, hn1);
        }
        if (t < T_ - 1) gbar_team(base + (++nbar), bm, team, ttid);
    }
}

// =====================================================================================
// out = relu(h_last @ w_out + b_out)  (unchanged)
// =====================================================================================
__global__ __launch_bounds__(256) void out_kernel(
    const float* __restrict__ w_out, const float* __restrict__ b_out,
    float* __restrict__ out)
{
    __shared__ __align__(16) float As[32][36];
    __shared__ __align__(16) float Bs[32][36];

    const float* __restrict__ hlast = g_h[0];

    const int tid = threadIdx.x;
    const int m0 = blockIdx.y * 32;
    const int n0 = blockIdx.x * 32;

    const int ttr = tid >> 4;
    const int ttc = tid & 15;
    const int arow = tid >> 3;
    const int akq  = tid & 7;
    const int bkr  = tid >> 3;
    const int bnq  = tid & 7;

    u64 acc[2][2];
    #pragma unroll
    for (int i = 0; i < 2; i++)
        #pragma unroll
        for (int p = 0; p < 2; p++) acc[i][p] = 0ull;

    for (int k0 = 0; k0 < HID_; k0 += 32) {
        float4 av = *(const float4*)&hlast[(size_t)(m0 + arow) * HID_ + k0 + akq * 4];
        float4 bv = *(const float4*)&w_out[(size_t)(k0 + bkr) * OUT_ + n0 + bnq * 4];

        __syncthreads();
        *(float4*)&As[arow][akq * 4] = av;
        Bs[bnq * 4 + 0][bkr] = bv.x; Bs[bnq * 4 + 1][bkr] = bv.y;
        Bs[bnq * 4 + 2][bkr] = bv.z; Bs[bnq * 4 + 3][bkr] = bv.w;
        __syncthreads();

        #pragma unroll
        for (int q = 0; q < 8; q++) {
            ulonglong2 a0 = *(const ulonglong2*)&As[ttr * 2 + 0][q * 4];
            ulonglong2 a1 = *(const ulonglong2*)&As[ttr * 2 + 1][q * 4];
            #pragma unroll
            for (int p = 0; p < 2; p++) {
                ulonglong2 bb = *(const ulonglong2*)&Bs[ttc + 16 * p][q * 4];
                f2fma(acc[0][p], a0.x, bb.x); f2fma(acc[0][p], a0.y, bb.y);
                f2fma(acc[1][p], a1.x, bb.x); f2fma(acc[1][p], a1.y, bb.y);
            }
        }
    }

    #pragma unroll
    for (int i = 0; i < 2; i++) {
        const int b = m0 + ttr * 2 + i;
        #pragma unroll
        for (int p = 0; p < 2; p++) {
            const int j = n0 + ttc + 16 * p;
            const float s = f2sum(acc[i][p]) + b_out[j];
            out[(size_t)b * OUT_ + j] = fmaxf(s, 0.0f);
        }
    }
}

// =====================================================================================
extern "C" void kernel_launch(void* const* d_in, const int* in_sizes, int n_in,
                              void* d_out, int out_size)
{
    const float* x     = (const float*)d_in[0];
    const float* c     = (const float*)d_in[1];
    const float* h0    = (const float*)d_in[2];
    const float* w_xr  = (const float*)d_in[3];
    const float* w_hr  = (const float*)d_in[4];
    const float* w_cr  = (const float*)d_in[5];
    const float* w_xz  = (const float*)d_in[6];
    const float* w_hz  = (const float*)d_in[7];
    const float* w_cz  = (const float*)d_in[8];
    const float* w_xh  = (const float*)d_in[9];
    const float* w_hh  = (const float*)d_in[10];
    const float* w_ch  = (const float*)d_in[11];
    const float* b_r   = (const float*)d_in[12];
    const float* b_z   = (const float*)d_in[13];
    const float* b_h   = (const float*)d_in[14];
    const float* w_out = (const float*)d_in[15];
    const float* b_out = (const float*)d_in[16];

    float* out = (float*)d_out;
    float* hs  = out + (size_t)B_ * OUT_;

    static int attr_set = 0;
    if (!attr_set) {
        cudaFuncSetAttribute(scan_mma_kernel, cudaFuncAttributeMaxDynamicSharedMemorySize,
                             SC2_SMEM);
        cudaFuncSetAttribute(pre_mma_kernel, cudaFuncAttributeMaxDynamicSharedMemorySize,
                             PM_SMEM);
        attr_set = 1;
    }

    init_h_kernel<<<512, 256>>>(h0);
    convertA_kernel<<<32768, 256>>>(x, c);
    convertB_kernel<<<768, 256>>>(w_xz, w_xr, w_xh, w_cz, w_cr, w_ch);
    pre_mma_kernel<<<dim3(12, 512), 256, PM_SMEM>>>(b_z, b_r, b_h);

    scan_mma_kernel<<<NBLK, 256, SC2_SMEM>>>(w_hz, w_hr, w_hh, hs);

    out_kernel<<<dim3(8, 8), 256>>>(w_out, b_out, out);
}

// round 17
// speedup vs baseline: 4.3539x; 1.0078x over previous
#include <cuda_runtime.h>
#include <cuda_fp16.h>
#include <math.h>

#define B_   256
#define T_   256
#define IN_  256
#define HID_ 512
#define OUT_ 256
#define NBLK 128

typedef unsigned long long u64;
typedef unsigned int u32;
typedef unsigned short u16;

// ---------- packed f32x2 FMA (out kernel) ----------
__device__ __forceinline__ void f2fma(u64 &d, u64 a, u64 b) {
    asm("fma.rn.f32x2 %0, %1, %2, %0;" : "+l"(d) : "l"(a), "l"(b));
}
__device__ __forceinline__ float f2sum(u64 v) {
    unsigned lo, hi;
    asm("mov.b64 {%0, %1}, %2;" : "=r"(lo), "=r"(hi) : "l"(v));
    return __uint_as_float(lo) + __uint_as_float(hi);
}
__device__ __forceinline__ float sigmoidf_(float x) { return 1.0f / (1.0f + expf(-x)); }

// ---------- warp mma.sync m16n8k16 fp16 ----------
#define MMAF16(d, a, b) \
    asm volatile("mma.sync.aligned.m16n8k16.row.col.f32.f16.f16.f32 " \
        "{%0,%1,%2,%3}, {%4,%5,%6,%7}, {%8,%9}, {%0,%1,%2,%3};" \
        : "+f"((d)[0]), "+f"((d)[1]), "+f"((d)[2]), "+f"((d)[3]) \
        : "r"((a)[0]), "r"((a)[1]), "r"((a)[2]), "r"((a)[3]), \
          "r"((b)[0]), "r"((b)[1]))

__device__ __forceinline__ void ldsm4(u32* r, u32 addr) {
    asm volatile("ldmatrix.sync.aligned.m8n8.x4.shared.b16 {%0,%1,%2,%3}, [%4];"
        : "=r"(r[0]), "=r"(r[1]), "=r"(r[2]), "=r"(r[3]) : "r"(addr));
}
__device__ __forceinline__ void ldsm2(u32* r, u32 addr) {
    asm volatile("ldmatrix.sync.aligned.m8n8.x2.shared.b16 {%0,%1}, [%2];"
        : "=r"(r[0]), "=r"(r[1]) : "r"(addr));
}
__device__ __forceinline__ u32 smem_u32(const void* p) {
    u32 a;
    asm("{ .reg .u64 t; cvta.to.shared.u64 t, %1; cvt.u32.u64 %0, t; }" : "=r"(a) : "l"(p));
    return a;
}

__device__ __forceinline__ u16 f2h(float v) {
    return __half_as_ushort(__float2half(v));
}

#define TBAR(id) asm volatile("bar.sync %0, 128;" :: "r"(id) : "memory")

// ---------- device scratch ----------
__device__ float g_pre[(size_t)B_ * T_ * 3 * HID_];
__device__ float g_h[2][B_ * HID_];
__device__ unsigned g_flags[NBLK * 2 * 32];
__device__ __align__(16) u16 g_hf[2][B_ * HID_];
__device__ __align__(16) u16 g_rhf[B_ * HID_];
__device__ __align__(16) u16 g_Af[(size_t)65536 * 512];
__device__ __align__(16) u16 g_Bf[3 * 512 * 512];

// =====================================================================================
// Convert A  (unchanged)
// =====================================================================================
__global__ __launch_bounds__(256) void convertA_kernel(
    const float* __restrict__ x, const float* __restrict__ c)
{
    const size_t idx = (size_t)blockIdx.x * 256 + threadIdx.x;
    const int m  = (int)(idx >> 7);
    const int kq = ((int)idx & 127) << 2;
    const float* src = (kq < 256) ? &x[(size_t)m * 256 + kq]
                                  : &c[(size_t)m * 256 + (kq - 256)];
    float4 v = *(const float4*)src;
    u32 p0 = (u32)f2h(v.x) | ((u32)f2h(v.y) << 16);
    u32 p1 = (u32)f2h(v.z) | ((u32)f2h(v.w) << 16);
    *(uint2*)&g_Af[(size_t)m * 512 + kq] = make_uint2(p0, p1);
}

// =====================================================================================
// Convert B  (unchanged)
// =====================================================================================
__global__ __launch_bounds__(256) void convertB_kernel(
    const float* __restrict__ wxz, const float* __restrict__ wxr, const float* __restrict__ wxh,
    const float* __restrict__ wcz, const float* __restrict__ wcr, const float* __restrict__ wch)
{
    const int idx = blockIdx.x * 256 + threadIdx.x;
    const int gate = idx >> 16;
    const int rem  = idx & 65535;
    const int k  = rem >> 7;
    const int nq = (rem & 127) << 2;
    const float* wx = (gate == 0) ? wxz : (gate == 1) ? wxr : wxh;
    const float* wc = (gate == 0) ? wcz : (gate == 1) ? wcr : wch;
    const float* src = (k < 256) ? &wx[(size_t)k * 512 + nq]
                                 : &wc[(size_t)(k - 256) * 512 + nq];
    float4 v = *(const float4*)src;
    float vv[4] = {v.x, v.y, v.z, v.w};
    #pragma unroll
    for (int i = 0; i < 4; i++)
        g_Bf[((size_t)(gate * 512 + nq + i)) * 512 + k] = f2h(vv[i]);
}

// =====================================================================================
// init h0  (unchanged)
// =====================================================================================
__global__ __launch_bounds__(256) void init_h_kernel(const float* __restrict__ h0)
{
    const int idx = blockIdx.x * 256 + threadIdx.x;
    float v = h0[idx];
    g_h[0][idx] = v;
    g_hf[0][idx] = f2h(v);
}

// =====================================================================================
// PRE via mma.sync fp16  (unchanged, 384us, passed)
// =====================================================================================
#define PMA_PITCH 144
#define PMA_IMG   (128 * PMA_PITCH)
#define PM_SMEM   (2 * PMA_IMG)

__global__ __launch_bounds__(256) void pre_mma_kernel(
    const float* __restrict__ bz, const float* __restrict__ br, const float* __restrict__ bh)
{
    extern __shared__ __align__(16) char psm[];
    char* sA = psm;
    char* sB = psm + PMA_IMG;

    const int tid = threadIdx.x;
    const int wid = tid >> 5, lane = tid & 31;
    const int g   = lane >> 2;
    const int tig = lane & 3;

    const int ntg   = blockIdx.x;
    const int mtile = blockIdx.y;
    const int gate  = ntg >> 2;
    const int n0    = (ntg & 3) * 128;

    const int wm = wid >> 2;
    const int wn = wid & 3;

    float acc[4][4][4];
    #pragma unroll
    for (int mi = 0; mi < 4; mi++)
        #pragma unroll
        for (int ni = 0; ni < 4; ni++)
            #pragma unroll
            for (int e = 0; e < 4; e++) acc[mi][ni][e] = 0.0f;

    for (int kc = 0; kc < 8; kc++) {
        __syncthreads();
        #pragma unroll
        for (int i = 0; i < 4; i++) {
            const int lin = tid + 256 * i;
            const int row = lin >> 3, q = lin & 7;
            const size_t asrc = ((size_t)(mtile * 128 + row)) * 512 + kc * 64 + q * 8;
            const size_t bsrc = ((size_t)(gate * 512 + n0 + row)) * 512 + kc * 64 + q * 8;
            *(uint4*)(sA + row * PMA_PITCH + q * 16) = *(const uint4*)&g_Af[asrc];
            *(uint4*)(sB + row * PMA_PITCH + q * 16) = *(const uint4*)&g_Bf[bsrc];
        }
        __syncthreads();

        #pragma unroll
        for (int kk = 0; kk < 4; kk++) {
            const int kb = kk * 32 + tig * 4;
            u32 af[4][4], bf[4][2];
            #pragma unroll
            for (int mi = 0; mi < 4; mi++) {
                const int rbase = (wm * 64 + mi * 16 + g) * PMA_PITCH + kb;
                af[mi][0] = *(const u32*)(sA + rbase);
                af[mi][1] = *(const u32*)(sA + rbase + 8 * PMA_PITCH);
                af[mi][2] = *(const u32*)(sA + rbase + 16);
                af[mi][3] = *(const u32*)(sA + rbase + 8 * PMA_PITCH + 16);
            }
            #pragma unroll
            for (int ni = 0; ni < 4; ni++) {
                const int nbase = (wn * 32 + ni * 8 + g) * PMA_PITCH + kb;
                bf[ni][0] = *(const u32*)(sB + nbase);
                bf[ni][1] = *(const u32*)(sB + nbase + 16);
            }
            #pragma unroll
            for (int mi = 0; mi < 4; mi++)
                #pragma unroll
                for (int ni = 0; ni < 4; ni++)
                    MMAF16(acc[mi][ni], af[mi], bf[ni]);
        }
    }

    const float* bias = (gate == 0) ? bz : (gate == 1) ? br : bh;
    #pragma unroll
    for (int mi = 0; mi < 4; mi++) {
        const int r0 = mtile * 128 + wm * 64 + mi * 16 + g;
        #pragma unroll
        for (int ni = 0; ni < 4; ni++) {
            const int cl = n0 + wn * 32 + ni * 8 + tig * 2;
            const float b0 = bias[cl], b1 = bias[cl + 1];
            float* d0 = &g_pre[(size_t)r0 * 1536 + gate * 512 + cl];
            float* d1 = &g_pre[(size_t)(r0 + 8) * 1536 + gate * 512 + cl];
            *(float2*)d0 = make_float2(acc[mi][ni][0] + b0, acc[mi][ni][1] + b1);
            *(float2*)d1 = make_float2(acc[mi][ni][2] + b0, acc[mi][ni][3] + b1);
        }
    }
}

// =====================================================================================
// Per-TEAM group barrier  (unchanged)
// =====================================================================================
__device__ __forceinline__ void gbar_team(unsigned want, int bm, int team, int ttid)
{
    TBAR(team + 1);
    if (ttid == 0) {
        asm volatile("st.release.gpu.global.u32 [%0], %1;"
                     :: "l"(&g_flags[(blockIdx.x * 2 + team) * 32]), "r"(want) : "memory");
    }
    if (ttid < 16) {
        unsigned v;
        do {
            asm volatile("ld.acquire.gpu.global.u32 %0, [%1];"
                         : "=r"(v)
                         : "l"(&g_flags[((bm * 16 + ttid) * 2 + team) * 32]) : "memory");
        } while ((int)(v - want) < 0);
    }
    TBAR(team + 1);
}

// =====================================================================================
// Tensor-core persistent scan, fp16, 2 teams, ldmatrix fragments,
// double-buffered staging (1 TBAR/phase), hs_out deferred past the step barrier.
// =====================================================================================
#define WPITCH 520
#define APITCH 1040
#define TEAMBUF (16 * APITCH)                          // 16640
#define SOFF_WZR  0
#define SOFF_WH   (SOFF_WZR + 64 * WPITCH * 2)         // 66560
#define SOFF_SA   (SOFF_WH + 32 * WPITCH * 2)          // 99840
#define SOFF_ZBUF (SOFF_SA + 4 * TEAMBUF)              // 166400
#define SC2_SMEM  (SOFF_ZBUF + 2 * 16 * 33 * 4)        // 170624

__global__ __launch_bounds__(256, 1) void scan_mma_kernel(
    const float* __restrict__ w_hz, const float* __restrict__ w_hr,
    const float* __restrict__ w_hh, float* __restrict__ hs_out)
{
    extern __shared__ __align__(16) char sm2[];
    u16* wZR = (u16*)(sm2 + SOFF_WZR);
    u16* wH  = (u16*)(sm2 + SOFF_WH);
    float* zball = (float*)(sm2 + SOFF_ZBUF);

    const int tid = threadIdx.x;
    const int bid = blockIdx.x;
    const int bm = bid >> 4;
    const int bn = bid & 15;
    const int m0 = bm * 32;
    const int j0 = bn * 32;

    // ---- one-time weight conversion (full block) ----
    for (int idx = tid; idx < 4096; idx += 256) {
        const int k  = idx >> 3;
        const int c4 = (idx & 7) * 4;
        float4 vz = *(const float4*)&w_hz[(size_t)k * HID_ + j0 + c4];
        float4 vr = *(const float4*)&w_hr[(size_t)k * HID_ + j0 + c4];
        float4 vh = *(const float4*)&w_hh[(size_t)k * HID_ + j0 + c4];
        float az[4] = {vz.x, vz.y, vz.z, vz.w};
        float ar[4] = {vr.x, vr.y, vr.z, vr.w};
        float ah[4] = {vh.x, vh.y, vh.z, vh.w};
        #pragma unroll
        for (int i = 0; i < 4; i++) {
            wZR[(c4 + i) * WPITCH + k]      = f2h(az[i]);
            wZR[(32 + c4 + i) * WPITCH + k] = f2h(ar[i]);
            wH[(c4 + i) * WPITCH + k]       = f2h(ah[i]);
        }
    }

    const int team = tid >> 7;
    const int ttid = tid & 127;
    const int twid = ttid >> 5;
    const int lane = ttid & 31;
    const int g    = lane >> 2;
    const int tig  = lane & 3;
    const int mt0  = m0 + team * 16;

    __shared__ unsigned s_base2[2];
    if (ttid == 0) s_base2[team] = *(volatile unsigned*)&g_flags[(bid * 2 + team) * 32];
    __syncthreads();
    const unsigned base = s_base2[team];
    unsigned nbar = 0;

    char* sAt0 = sm2 + SOFF_SA + (team * 2 + 0) * TEAMBUF;
    char* sAt1 = sm2 + SOFF_SA + (team * 2 + 1) * TEAMBUF;
    float* zb  = zball + team * 16 * 33;

    // ldmatrix address bases
    const u32 smb = smem_u32(sm2);
    const u32 aoff = (u32)((lane & 15) * APITCH + ((lane >> 4) << 4));
    const u32 aBase0 = smb + SOFF_SA + (team * 2 + 0) * TEAMBUF + aoff;
    const u32 aBase1 = smb + SOFF_SA + (team * 2 + 1) * TEAMBUF + aoff;
    const u32 bAaddr = smb + SOFF_WZR +
        (u32)((twid * 16 + ((lane >> 4) & 1) * 8 + (lane & 7)) * 1040 + (((lane >> 3) & 1) << 4));
    const u32 bBaddr = smb + SOFF_WH +
        (u32)((twid * 8 + (lane & 7)) * 1040 + (((lane >> 3) & 1) << 4));

    const bool is_z = (twid < 2);
    const int c32b = (twid & 1) * 16;

    const int srow = ttid >> 3;
    const int sb0  = ((ttid & 7) - srow) & 7;

    for (int t = 0; t < T_; t++) {
        const int pp = t & 1;
        const float* __restrict__ hprev = g_h[pp];
        float* __restrict__ hnext = g_h[pp ^ 1];
        const u16* __restrict__ hf = g_hf[pp];

        // ---- phase A epilogue prefetch ----
        const int goff = is_z ? 0 : 512;
        float2 pvA[2][2], hvA[2][2];
        #pragma unroll
        for (int i = 0; i < 2; i++) {
            const int rl = g + 8 * i;
            const size_t prow = ((size_t)(mt0 + rl) * T_ + t) * 1536;
            #pragma unroll
            for (int s = 0; s < 2; s++) {
                const int c = c32b + s * 8 + tig * 2;
                pvA[i][s] = *(const float2*)&g_pre[prow + goff + j0 + c];
                if (!is_z)
                    hvA[i][s] = *(const float2*)&hprev[(size_t)(mt0 + rl) * HID_ + j0 + c];
            }
        }

        // ================= phase A GEMM (buf0) =================
        float accA[2][4];
        #pragma unroll
        for (int s = 0; s < 2; s++)
            #pragma unroll
            for (int e = 0; e < 4; e++) accA[s][e] = 0.0f;

        {
            uint4 pf[8];
            #pragma unroll
            for (int i = 0; i < 8; i++)
                pf[i] = *(const uint4*)&hf[(size_t)(mt0 + srow) * HID_ + (sb0 + 8 * i) * 8];
            #pragma unroll
            for (int i = 0; i < 8; i++)
                *(uint4*)(sAt0 + srow * APITCH + (sb0 + 8 * i) * 16) = pf[i];
            TBAR(team + 1);
        }

        #pragma unroll 8
        for (int kk2 = 0; kk2 < 32; kk2++) {
            u32 af[4], bf4[4];
            ldsm4(af, aBase0 + kk2 * 32);
            ldsm4(bf4, bAaddr + kk2 * 32);
            MMAF16(accA[0], af, bf4);
            MMAF16(accA[1], af, bf4 + 2);
        }

        // ---- phase A epilogue ----
        if (is_z) {
            #pragma unroll
            for (int i = 0; i < 2; i++) {
                const int rl = g + 8 * i;
                #pragma unroll
                for (int s = 0; s < 2; s++) {
                    const int c = c32b + s * 8 + tig * 2;
                    zb[rl * 33 + c]     = sigmoidf_(pvA[i][s].x + accA[s][2 * i]);
                    zb[rl * 33 + c + 1] = sigmoidf_(pvA[i][s].y + accA[s][2 * i + 1]);
                }
            }
        } else {
            #pragma unroll
            for (int i = 0; i < 2; i++) {
                const int rl = g + 8 * i;
                #pragma unroll
                for (int s = 0; s < 2; s++) {
                    const int c = c32b + s * 8 + tig * 2;
                    const float r0 = sigmoidf_(pvA[i][s].x + accA[s][2 * i]);
                    const float r1 = sigmoidf_(pvA[i][s].y + accA[s][2 * i + 1]);
                    const float rh0 = r0 * hvA[i][s].x;
                    const float rh1 = r1 * hvA[i][s].y;
                    const size_t gi = (size_t)(mt0 + rl) * HID_ + j0 + c;
                    *(u32*)&g_rhf[gi] = (u32)f2h(rh0) | ((u32)f2h(rh1) << 16);
                }
            }
        }

        // ---- phase B epilogue prefetch BEFORE barrier ----
        const int cB = twid * 8 + tig * 2;
        float2 phB[2], hoB[2];
        #pragma unroll
        for (int i = 0; i < 2; i++) {
            const int rl = g + 8 * i;
            const size_t prow = ((size_t)(mt0 + rl) * T_ + t) * 1536;
            phB[i] = *(const float2*)&g_pre[prow + 1024 + j0 + cB];
            hoB[i] = *(const float2*)&hprev[(size_t)(mt0 + rl) * HID_ + j0 + cB];
        }

        gbar_team(base + (++nbar), bm, team, ttid);

        // ================= phase B GEMM (buf1) =================
        float accB[4] = {0.0f, 0.0f, 0.0f, 0.0f};

        {
            uint4 pf[8];
            #pragma unroll
            for (int i = 0; i < 8; i++)
                pf[i] = *(const uint4*)&g_rhf[(size_t)(mt0 + srow) * HID_ + (sb0 + 8 * i) * 8];
            #pragma unroll
            for (int i = 0; i < 8; i++)
                *(uint4*)(sAt1 + srow * APITCH + (sb0 + 8 * i) * 16) = pf[i];
            TBAR(team + 1);
        }

        #pragma unroll 8
        for (int kk2 = 0; kk2 < 32; kk2++) {
            u32 af[4], bf2[2];
            ldsm4(af, aBase1 + kk2 * 32);
            ldsm2(bf2, bBaddr + kk2 * 32);
            MMAF16(accB, af, bf2);
        }

        // ---- phase B epilogue (hs_out deferred past barrier) ----
        float2 hsv[2];
        #pragma unroll
        for (int i = 0; i < 2; i++) {
            const int rl = g + 8 * i;
            const float ht0 = tanhf(phB[i].x + accB[2 * i]);
            const float ht1 = tanhf(phB[i].y + accB[2 * i + 1]);
            const float z0 = zb[rl * 33 + cB];
            const float z1 = zb[rl * 33 + cB + 1];
            const float hn0 = fmaf(z0, ht0 - hoB[i].x, hoB[i].x);
            const float hn1 = fmaf(z1, ht1 - hoB[i].y, hoB[i].y);
            const size_t gi = (size_t)(mt0 + rl) * HID_ + j0 + cB;
            *(float2*)&hnext[gi] = make_float2(hn0, hn1);
            *(u32*)&g_hf[pp ^ 1][gi] = (u32)f2h(hn0) | ((u32)f2h(hn1) << 16);
            hsv[i] = make_float2(hn0, hn1);
        }
        if (t < T_ - 1) gbar_team(base + (++nbar), bm, team, ttid);
        #pragma unroll
        for (int i = 0; i < 2; i++) {
            const int rl = g + 8 * i;
            *(float2*)&hs_out[((size_t)(mt0 + rl) * T_ + t) * HID_ + j0 + cB] = hsv[i];
        }
    }
}

// =====================================================================================
// out = relu(h_last @ w_out + b_out)  (unchanged)
// =====================================================================================
__global__ __launch_bounds__(256) void out_kernel(
    const float* __restrict__ w_out, const float* __restrict__ b_out,
    float* __restrict__ out)
{
    __shared__ __align__(16) float As[32][36];
    __shared__ __align__(16) float Bs[32][36];

    const float* __restrict__ hlast = g_h[0];

    const int tid = threadIdx.x;
    const int m0 = blockIdx.y * 32;
    const int n0 = blockIdx.x * 32;

    const int ttr = tid >> 4;
    const int ttc = tid & 15;
    const int arow = tid >> 3;
    const int akq  = tid & 7;
    const int bkr  = tid >> 3;
    const int bnq  = tid & 7;

    u64 acc[2][2];
    #pragma unroll
    for (int i = 0; i < 2; i++)
        #pragma unroll
        for (int p = 0; p < 2; p++) acc[i][p] = 0ull;

    for (int k0 = 0; k0 < HID_; k0 += 32) {
        float4 av = *(const float4*)&hlast[(size_t)(m0 + arow) * HID_ + k0 + akq * 4];
        float4 bv = *(const float4*)&w_out[(size_t)(k0 + bkr) * OUT_ + n0 + bnq * 4];

        __syncthreads();
        *(float4*)&As[arow][akq * 4] = av;
        Bs[bnq * 4 + 0][bkr] = bv.x; Bs[bnq * 4 + 1][bkr] = bv.y;
        Bs[bnq * 4 + 2][bkr] = bv.z; Bs[bnq * 4 + 3][bkr] = bv.w;
        __syncthreads();

        #pragma unroll
        for (int q = 0; q < 8; q++) {
            ulonglong2 a0 = *(const ulonglong2*)&As[ttr * 2 + 0][q * 4];
            ulonglong2 a1 = *(const ulonglong2*)&As[ttr * 2 + 1][q * 4];
            #pragma unroll
            for (int p = 0; p < 2; p++) {
                ulonglong2 bb = *(const ulonglong2*)&Bs[ttc + 16 * p][q * 4];
                f2fma(acc[0][p], a0.x, bb.x); f2fma(acc[0][p], a0.y, bb.y);
                f2fma(acc[1][p], a1.x, bb.x); f2fma(acc[1][p], a1.y, bb.y);
            }
        }
    }

    #pragma unroll
    for (int i = 0; i < 2; i++) {
        const int b = m0 + ttr * 2 + i;
        #pragma unroll
        for (int p = 0; p < 2; p++) {
            const int j = n0 + ttc + 16 * p;
            const float s = f2sum(acc[i][p]) + b_out[j];
            out[(size_t)b * OUT_ + j] = fmaxf(s, 0.0f);
        }
    }
}

// =====================================================================================
extern "C" void kernel_launch(void* const* d_in, const int* in_sizes, int n_in,
                              void* d_out, int out_size)
{
    const float* x     = (const float*)d_in[0];
    const float* c     = (const float*)d_in[1];
    const float* h0    = (const float*)d_in[2];
    const float* w_xr  = (const float*)d_in[3];
    const float* w_hr  = (const float*)d_in[4];
    const float* w_cr  = (const float*)d_in[5];
    const float* w_xz  = (const float*)d_in[6];
    const float* w_hz  = (const float*)d_in[7];
    const float* w_cz  = (const float*)d_in[8];
    const float* w_xh  = (const float*)d_in[9];
    const float* w_hh  = (const float*)d_in[10];
    const float* w_ch  = (const float*)d_in[11];
    const float* b_r   = (const float*)d_in[12];
    const float* b_z   = (const float*)d_in[13];
    const float* b_h   = (const float*)d_in[14];
    const float* w_out = (const float*)d_in[15];
    const float* b_out = (const float*)d_in[16];

    float* out = (float*)d_out;
    float* hs  = out + (size_t)B_ * OUT_;

    static int attr_set = 0;
    if (!attr_set) {
        cudaFuncSetAttribute(scan_mma_kernel, cudaFuncAttributeMaxDynamicSharedMemorySize,
                             SC2_SMEM);
        cudaFuncSetAttribute(pre_mma_kernel, cudaFuncAttributeMaxDynamicSharedMemorySize,
                             PM_SMEM);
        attr_set = 1;
    }

    init_h_kernel<<<512, 256>>>(h0);
    convertA_kernel<<<32768, 256>>>(x, c);
    convertB_kernel<<<768, 256>>>(w_xz, w_xr, w_xh, w_cz, w_cr, w_ch);
    pre_mma_kernel<<<dim3(12, 512), 256, PM_SMEM>>>(b_z, b_r, b_h);

    scan_mma_kernel<<<NBLK, 256, SC2_SMEM>>>(w_hz, w_hr, w_hh, hs);

    out_kernel<<<dim3(8, 8), 256>>>(w_out, b_out, out);
}